// round 1
// baseline (speedup 1.0000x reference)
#include <cuda_runtime.h>
#include <cuda_bf16.h>
#include <math.h>

// Problem constants
#define BB 4
#define DD 256
#define TT 256
#define FF 64
#define HH 8
#define HD 32
#define NT (BB*TT*FF)          // 65536 tokens
#define THETA 10000.0f

// Scratch (no allocations allowed -> device globals)
__device__ float g_X[(size_t)NT * DD];        // canonical token-major activations
__device__ float g_QKV[(size_t)NT * 3 * DD];  // qkv / reused as proj output

// ---------------------------------------------------------------------------
// Permute input: x[b][d][t][f] -> X[(b*T+t)*F+f][d]
// ---------------------------------------------------------------------------
__global__ __launch_bounds__(256) void permute_in_kernel(const float* __restrict__ x) {
    int idx = blockIdx.x * 256 + threadIdx.x;     // over NT*DD = 16.7M
    int d = idx & 255;
    int tok = idx >> 8;
    int f = tok & 63;
    int t = (tok >> 6) & 255;
    int b = tok >> 14;
    g_X[idx] = x[(((size_t)(b * 256 + d) * 256) + t) * 64 + f];
}

// ---------------------------------------------------------------------------
// Permute output: Y[(b*T+t)*F+f][d] (in g_QKV) -> out[b][d][t][f]
// ---------------------------------------------------------------------------
__global__ __launch_bounds__(256) void permute_out_kernel(float* __restrict__ out) {
    int idx = blockIdx.x * 256 + threadIdx.x;     // over B*D*T*F
    int f = idx & 63;
    int t = (idx >> 6) & 255;
    int d = (idx >> 14) & 255;
    int b = idx >> 22;
    out[idx] = g_QKV[(size_t)((b * 256 + t) * 64 + f) * 256 + d];
}

// ---------------------------------------------------------------------------
// Classic 128x128 register-blocked SGEMM, row-major: C[M,N] = A[M,K] @ B[K,N]
// Requires M%128==0, N%128==0, K%8==0 (all true here).
// ---------------------------------------------------------------------------
__global__ __launch_bounds__(256) void sgemm128_kernel(
    const float* __restrict__ A, const float* __restrict__ B, float* __restrict__ C,
    int M, int N, int K)
{
    __shared__ float As[8][128];
    __shared__ float Bs[8][128];

    int tid = threadIdx.x;
    int bx = blockIdx.x;   // N tile
    int by = blockIdx.y;   // M tile
    int tx = tid & 15;     // n micro
    int ty = tid >> 4;     // m micro

    float acc[8][8];
    #pragma unroll
    for (int i = 0; i < 8; i++)
        #pragma unroll
        for (int j = 0; j < 8; j++) acc[i][j] = 0.0f;

    // A tile load map: thread -> (row, 4 k's)
    int arow  = tid >> 1;           // 0..127
    int acol4 = (tid & 1) * 4;      // 0 or 4
    // B tile load map: thread -> (k row, 4 n's)
    int brow  = tid >> 5;           // 0..7
    int bcol4 = (tid & 31) * 4;     // 0..124

    const float* Ab = A + (size_t)(by * 128 + arow) * K + acol4;
    const float* Bb = B + (size_t)brow * N + bx * 128 + bcol4;

    float4 av = *(const float4*)(Ab);
    float4 bv = *(const float4*)(Bb);

    for (int k0 = 0; k0 < K; k0 += 8) {
        // store current fragments
        As[acol4 + 0][arow] = av.x;
        As[acol4 + 1][arow] = av.y;
        As[acol4 + 2][arow] = av.z;
        As[acol4 + 3][arow] = av.w;
        *(float4*)&Bs[brow][bcol4] = bv;
        __syncthreads();

        // prefetch next tile while computing
        if (k0 + 8 < K) {
            av = *(const float4*)(Ab + k0 + 8);
            bv = *(const float4*)(Bb + (size_t)(k0 + 8) * N);
        }

        #pragma unroll
        for (int kk = 0; kk < 8; kk++) {
            float4 a0 = *(float4*)&As[kk][ty * 4];
            float4 a1 = *(float4*)&As[kk][64 + ty * 4];
            float4 b0 = *(float4*)&Bs[kk][tx * 4];
            float4 b1 = *(float4*)&Bs[kk][64 + tx * 4];
            float ar[8] = {a0.x, a0.y, a0.z, a0.w, a1.x, a1.y, a1.z, a1.w};
            float br[8] = {b0.x, b0.y, b0.z, b0.w, b1.x, b1.y, b1.z, b1.w};
            #pragma unroll
            for (int i = 0; i < 8; i++)
                #pragma unroll
                for (int j = 0; j < 8; j++)
                    acc[i][j] += ar[i] * br[j];
        }
        __syncthreads();
    }

    // epilogue: 8x8 per thread, float4 stores
    #pragma unroll
    for (int i = 0; i < 8; i++) {
        int mrow = by * 128 + ((i < 4) ? (ty * 4 + i) : (64 + ty * 4 + i - 4));
        float* Cp = C + (size_t)mrow * N + bx * 128;
        float4 v0 = make_float4(acc[i][0], acc[i][1], acc[i][2], acc[i][3]);
        float4 v1 = make_float4(acc[i][4], acc[i][5], acc[i][6], acc[i][7]);
        *(float4*)(Cp + tx * 4)      = v0;
        *(float4*)(Cp + 64 + tx * 4) = v1;
    }
}

// ---------------------------------------------------------------------------
// Token index for (group, position) per stage.
// Stage 1: groups = (b,f), seq over t (S=256)
// Stage 2: groups = (b,t), seq over f (S=64)
// Stage 3: groups = (b, t1, f1) windows, seq over (t2, f2) (S=64)
// ---------------------------------------------------------------------------
template <int STAGE>
__device__ __forceinline__ int tok_of(int g, int p) {
    if (STAGE == 1) {
        int b = g >> 6, f = g & 63;
        return (b * 256 + p) * 64 + f;
    } else if (STAGE == 2) {
        return g * 64 + p;
    } else {
        int b = g >> 8, rem = g & 255;
        int i = rem >> 3, jf = rem & 7;
        int t = i * 8 + (p >> 3);
        int f = jf * 8 + (p & 7);
        return (b * 256 + t) * 64 + f;
    }
}

// ---------------------------------------------------------------------------
// Fused attention for one (group, head). QKV layout per token: 768 floats as
// [q(h*32) | k(h*32) | v(h*32)] with head-major 32-dim chunks.
// RoPE (interleaved-pair convention) applied to q and k on the fly.
// Writes attention output into g_X[tok][h*32 + d].
// ---------------------------------------------------------------------------
template <int STAGE, int S>
__global__ __launch_bounds__(256) void attn_kernel(const float* __restrict__ qkv) {
    extern __shared__ float sm[];
    float* Ksm = sm;                 // S x 33 (padded)
    float* Vsm = Ksm + S * 33;       // S x 33
    float* Qb  = Vsm + S * 33;       // 8 x 32
    float* Pb  = Qb + 8 * 32;        // 8 x S

    const int g = blockIdx.x;
    const int h = blockIdx.y;
    const int tid = threadIdx.x;
    const int w = tid >> 5;
    const int lane = tid & 31;

    const float SCALE = 0.17677669529663687f;          // 1/sqrt(32)
    const float CEXP  = 0.830482023721841f;            // log2(10000)/16

    // --- load K with RoPE (pairwise) ---
    for (int idx = tid; idx < S * 16; idx += 256) {
        int k = idx >> 4, j = idx & 15;
        int tk = tok_of<STAGE>(g, k);
        const float* base = qkv + (size_t)tk * 768 + 256 + h * 32;
        float x0 = base[2 * j];
        float x1 = base[2 * j + 1];
        float inv = exp2f(-(float)j * CEXP);
        float ang = (float)k * inv;
        float sn, cs;
        sincosf(ang, &sn, &cs);
        Ksm[k * 33 + 2 * j]     = x0 * cs - x1 * sn;
        Ksm[k * 33 + 2 * j + 1] = x1 * cs + x0 * sn;
    }
    // --- load V ---
    for (int idx = tid; idx < S * 32; idx += 256) {
        int k = idx >> 5, d = idx & 31;
        int tk = tok_of<STAGE>(g, k);
        Vsm[k * 33 + d] = qkv[(size_t)tk * 768 + 512 + h * 32 + d];
    }
    __syncthreads();

    const float inv_l = exp2f(-(float)(lane >> 1) * CEXP);
    constexpr int NC = S / 32;

    for (int r = w; r < S; r += 8) {
        int tr = tok_of<STAGE>(g, r);
        // q with RoPE (lane = dim)
        float q = qkv[(size_t)tr * 768 + h * 32 + lane];
        float partner = __shfl_xor_sync(0xFFFFFFFFu, q, 1);
        float ang = (float)r * inv_l;
        float sn, cs;
        sincosf(ang, &sn, &cs);
        float qr = (lane & 1) ? (q * cs + partner * sn) : (q * cs - partner * sn);
        Qb[w * 32 + lane] = qr * SCALE;
        __syncwarp();

        // scores: lane owns keys lane + 32*jj
        float s[NC];
        #pragma unroll
        for (int jj = 0; jj < NC; jj++) s[jj] = 0.0f;
        #pragma unroll
        for (int d = 0; d < 32; d++) {
            float qd = Qb[w * 32 + d];
            #pragma unroll
            for (int jj = 0; jj < NC; jj++)
                s[jj] += qd * Ksm[(lane + 32 * jj) * 33 + d];
        }

        // softmax
        float m = s[0];
        #pragma unroll
        for (int jj = 1; jj < NC; jj++) m = fmaxf(m, s[jj]);
        #pragma unroll
        for (int off = 16; off > 0; off >>= 1)
            m = fmaxf(m, __shfl_xor_sync(0xFFFFFFFFu, m, off));
        float sum = 0.0f;
        #pragma unroll
        for (int jj = 0; jj < NC; jj++) {
            float p = __expf(s[jj] - m);
            s[jj] = p;
            sum += p;
        }
        #pragma unroll
        for (int off = 16; off > 0; off >>= 1)
            sum += __shfl_xor_sync(0xFFFFFFFFu, sum, off);
        float invs = 1.0f / sum;
        #pragma unroll
        for (int jj = 0; jj < NC; jj++)
            Pb[w * S + lane + 32 * jj] = s[jj] * invs;
        __syncwarp();

        // PV: lane = output dim
        float o = 0.0f;
        #pragma unroll 8
        for (int k = 0; k < S; k++)
            o += Pb[w * S + k] * Vsm[k * 33 + lane];

        g_X[(size_t)tr * 256 + h * 32 + lane] = o;
        __syncwarp();
    }
}

// ---------------------------------------------------------------------------
extern "C" void kernel_launch(void* const* d_in, const int* in_sizes, int n_in,
                              void* d_out, int out_size) {
    const float* x  = (const float*)d_in[0];
    const float* W1 = (const float*)d_in[1];
    const float* W2 = (const float*)d_in[2];
    const float* W3 = (const float*)d_in[3];
    const float* Wp = (const float*)d_in[4];
    float* out = (float*)d_out;

    float* Xp;   cudaGetSymbolAddress((void**)&Xp,   g_X);
    float* QKVp; cudaGetSymbolAddress((void**)&QKVp, g_QKV);

    // dynamic smem sizes: (74*S + 256) * 4 bytes
    const int SMEM1 = (74 * 256 + 256) * 4;   // 76800
    const int SMEM2 = (74 * 64 + 256) * 4;    // 19968

    cudaFuncSetAttribute(attn_kernel<1, 256>,
                         cudaFuncAttributeMaxDynamicSharedMemorySize, SMEM1);

    // 0) permute input to token-major
    permute_in_kernel<<<NT, 256>>>(x);

    // Stage 1: time-axis attention
    sgemm128_kernel<<<dim3(768 / 128, NT / 128), 256>>>(Xp, W1, QKVp, NT, 768, 256);
    attn_kernel<1, 256><<<dim3(BB * FF, HH), 256, SMEM1>>>(QKVp);

    // Stage 2: freq-axis attention
    sgemm128_kernel<<<dim3(768 / 128, NT / 128), 256>>>(Xp, W2, QKVp, NT, 768, 256);
    attn_kernel<2, 64><<<dim3(BB * TT, HH), 256, SMEM2>>>(QKVp);

    // Stage 3: windowed attention
    sgemm128_kernel<<<dim3(768 / 128, NT / 128), 256>>>(Xp, W3, QKVp, NT, 768, 256);
    attn_kernel<3, 64><<<dim3(BB * (TT / 8) * (FF / 8), HH), 256, SMEM2>>>(QKVp);

    // Projection (writes into g_QKV reused as Y)
    sgemm128_kernel<<<dim3(256 / 128, NT / 128), 256>>>(Xp, Wp, QKVp, NT, 256, 256);

    // Output permute to (B, D, T, F)
    permute_out_kernel<<<NT, 256>>>(out);
}

// round 2
// speedup vs baseline: 1.3705x; 1.3705x over previous
#include <cuda_runtime.h>
#include <cuda_bf16.h>
#include <math.h>
#include <stdint.h>

// Problem constants
#define BB 4
#define DD 256
#define TT 256
#define FF 64
#define HH 8
#define HD 32
#define NT (BB*TT*FF)          // 65536 tokens

// Scratch (no allocations allowed -> device globals)
__device__ float g_X[(size_t)NT * DD];        // canonical token-major activations
__device__ float g_QKV[(size_t)NT * 3 * DD];  // qkv / reused as proj output

// ---------------------------------------------------------------------------
// Permute input: x[b][d][t][f] -> X[(b*T+t)*F+f][d]
// ---------------------------------------------------------------------------
__global__ __launch_bounds__(256) void permute_in_kernel(const float* __restrict__ x) {
    int idx = blockIdx.x * 256 + threadIdx.x;
    int d = idx & 255;
    int tok = idx >> 8;
    int f = tok & 63;
    int t = (tok >> 6) & 255;
    int b = tok >> 14;
    g_X[idx] = x[(((size_t)(b * 256 + d) * 256) + t) * 64 + f];
}

// ---------------------------------------------------------------------------
// Permute output: Y[(b*T+t)*F+f][d] (in g_QKV) -> out[b][d][t][f]
// ---------------------------------------------------------------------------
__global__ __launch_bounds__(256) void permute_out_kernel(float* __restrict__ out) {
    int idx = blockIdx.x * 256 + threadIdx.x;
    int f = idx & 63;
    int t = (idx >> 6) & 255;
    int d = (idx >> 14) & 255;
    int b = idx >> 22;
    out[idx] = g_QKV[(size_t)((b * 256 + t) * 64 + f) * 256 + d];
}

// ---------------------------------------------------------------------------
// TF32 tensor-core GEMM: C[M,N] = A[M,K] @ B[K,N], row-major fp32 in/out.
// Block tile 128x128, 8 warps (2x4), warp tile 64x32, K-tile 32.
// mma.sync.aligned.m16n8k8.row.col.f32.tf32.tf32.f32
// Requires M%128==0, N%128==0, K%32==0.
// ---------------------------------------------------------------------------
__device__ __forceinline__ uint32_t f2tf32(float x) {
    uint32_t r;
    asm("cvt.rna.tf32.f32 %0, %1;" : "=r"(r) : "f"(x));
    return r;
}

__device__ __forceinline__ void mma_tf32(float* c, const uint32_t* a, const uint32_t* b) {
    asm volatile(
        "mma.sync.aligned.m16n8k8.row.col.f32.tf32.tf32.f32 "
        "{%0,%1,%2,%3}, {%4,%5,%6,%7}, {%8,%9}, {%0,%1,%2,%3};"
        : "+f"(c[0]), "+f"(c[1]), "+f"(c[2]), "+f"(c[3])
        : "r"(a[0]), "r"(a[1]), "r"(a[2]), "r"(a[3]), "r"(b[0]), "r"(b[1]));
}

__global__ __launch_bounds__(256) void tf32_gemm_kernel(
    const float* __restrict__ A, const float* __restrict__ B, float* __restrict__ C,
    int M, int N, int K)
{
    __shared__ float As[128][36];   // [m][k], pad 36 -> frag bank = 4*tq+tr (conflict-free)
    __shared__ float Bs[32][136];   // [k][n], pad 136 -> frag bank = 8*tr+tq (conflict-free)

    const int tid = threadIdx.x;
    const int wid = tid >> 5;
    const int lane = tid & 31;
    const int tq = lane >> 2;   // t/4
    const int tr = lane & 3;    // t%4
    const int warp_m = (wid & 1) * 64;
    const int warp_n = (wid >> 1) * 32;
    const int bx = blockIdx.x * 128;   // N offset
    const int by = blockIdx.y * 128;   // M offset

    float acc[4][4][4];
    #pragma unroll
    for (int i = 0; i < 4; i++)
        #pragma unroll
        for (int j = 0; j < 4; j++)
            #pragma unroll
            for (int r = 0; r < 4; r++) acc[i][j][r] = 0.0f;

    // global load maps
    const int am = tid >> 3;           // 0..31 (+32*it)
    const int ak = (tid & 7) * 4;      // 0..28
    const int bk = tid >> 5;           // 0..7 (+8*it)
    const int bn = (tid & 31) * 4;     // 0..124

    const float* Ag = A + (size_t)(by + am) * K + ak;
    const float* Bg = B + (size_t)bk * N + bx + bn;

    float4 aP[4], bP[4];
    #pragma unroll
    for (int it = 0; it < 4; it++) {
        aP[it] = *(const float4*)(Ag + (size_t)(32 * it) * K);
        bP[it] = *(const float4*)(Bg + (size_t)(8 * it) * N);
    }

    for (int k0 = 0; k0 < K; k0 += 32) {
        // store current tiles (convert to tf32 bit patterns)
        #pragma unroll
        for (int it = 0; it < 4; it++) {
            float4 a = aP[it];
            float4 av = make_float4(__uint_as_float(f2tf32(a.x)), __uint_as_float(f2tf32(a.y)),
                                    __uint_as_float(f2tf32(a.z)), __uint_as_float(f2tf32(a.w)));
            *(float4*)&As[am + 32 * it][ak] = av;
            float4 b = bP[it];
            float4 bv = make_float4(__uint_as_float(f2tf32(b.x)), __uint_as_float(f2tf32(b.y)),
                                    __uint_as_float(f2tf32(b.z)), __uint_as_float(f2tf32(b.w)));
            *(float4*)&Bs[bk + 8 * it][bn] = bv;
        }
        __syncthreads();

        // prefetch next k-tile
        if (k0 + 32 < K) {
            #pragma unroll
            for (int it = 0; it < 4; it++) {
                aP[it] = *(const float4*)(Ag + (size_t)(32 * it) * K + (k0 + 32));
                bP[it] = *(const float4*)(Bg + (size_t)(k0 + 32 + 8 * it) * N);
            }
        }

        // compute: 4 k-steps of 8
        #pragma unroll
        for (int c = 0; c < 4; c++) {
            const int ks = c * 8;
            uint32_t a[4][4], b[4][2];
            #pragma unroll
            for (int i = 0; i < 4; i++) {
                int row = warp_m + i * 16 + tq;
                a[i][0] = __float_as_uint(As[row][ks + tr]);
                a[i][1] = __float_as_uint(As[row + 8][ks + tr]);
                a[i][2] = __float_as_uint(As[row][ks + tr + 4]);
                a[i][3] = __float_as_uint(As[row + 8][ks + tr + 4]);
            }
            #pragma unroll
            for (int j = 0; j < 4; j++) {
                int col = warp_n + j * 8 + tq;
                b[j][0] = __float_as_uint(Bs[ks + tr][col]);
                b[j][1] = __float_as_uint(Bs[ks + tr + 4][col]);
            }
            #pragma unroll
            for (int i = 0; i < 4; i++)
                #pragma unroll
                for (int j = 0; j < 4; j++)
                    mma_tf32(acc[i][j], a[i], b[j]);
        }
        __syncthreads();
    }

    // epilogue: float2 stores
    #pragma unroll
    for (int i = 0; i < 4; i++) {
        int row0 = by + warp_m + i * 16 + tq;
        #pragma unroll
        for (int j = 0; j < 4; j++) {
            int col0 = bx + warp_n + j * 8 + 2 * tr;
            float2 v0 = make_float2(acc[i][j][0], acc[i][j][1]);
            float2 v1 = make_float2(acc[i][j][2], acc[i][j][3]);
            *(float2*)&C[(size_t)row0 * N + col0] = v0;
            *(float2*)&C[(size_t)(row0 + 8) * N + col0] = v1;
        }
    }
}

// ---------------------------------------------------------------------------
// Token index for (group, position) per stage.
// ---------------------------------------------------------------------------
template <int STAGE>
__device__ __forceinline__ int tok_of(int g, int p) {
    if (STAGE == 1) {
        int b = g >> 6, f = g & 63;
        return (b * 256 + p) * 64 + f;
    } else if (STAGE == 2) {
        return g * 64 + p;
    } else {
        int b = g >> 8, rem = g & 255;
        int i = rem >> 3, jf = rem & 7;
        int t = i * 8 + (p >> 3);
        int f = jf * 8 + (p & 7);
        return (b * 256 + t) * 64 + f;
    }
}

// ---------------------------------------------------------------------------
// Fused attention for one (group, head). QKV per token: [q(256)|k(256)|v(256)],
// head-major 32-dim chunks. RoPE applied on the fly. Output -> g_X.
// ---------------------------------------------------------------------------
template <int STAGE, int S>
__global__ __launch_bounds__(256) void attn_kernel(const float* __restrict__ qkv) {
    extern __shared__ float sm[];
    float* Ksm = sm;                 // S x 33
    float* Vsm = Ksm + S * 33;       // S x 33
    float* Qb  = Vsm + S * 33;       // 8 x 32
    float* Pb  = Qb + 8 * 32;        // 8 x S

    const int g = blockIdx.x;
    const int h = blockIdx.y;
    const int tid = threadIdx.x;
    const int w = tid >> 5;
    const int lane = tid & 31;

    const float SCALE = 0.17677669529663687f;   // 1/sqrt(32)
    const float CEXP  = 0.830482023721841f;     // log2(10000)/16 (natural-log form folded)

    for (int idx = tid; idx < S * 16; idx += 256) {
        int k = idx >> 4, j = idx & 15;
        int tk = tok_of<STAGE>(g, k);
        const float* base = qkv + (size_t)tk * 768 + 256 + h * 32;
        float x0 = base[2 * j];
        float x1 = base[2 * j + 1];
        float inv = exp2f(-(float)j * CEXP);
        float ang = (float)k * inv;
        float sn, cs;
        sincosf(ang, &sn, &cs);
        Ksm[k * 33 + 2 * j]     = x0 * cs - x1 * sn;
        Ksm[k * 33 + 2 * j + 1] = x1 * cs + x0 * sn;
    }
    for (int idx = tid; idx < S * 32; idx += 256) {
        int k = idx >> 5, d = idx & 31;
        int tk = tok_of<STAGE>(g, k);
        Vsm[k * 33 + d] = qkv[(size_t)tk * 768 + 512 + h * 32 + d];
    }
    __syncthreads();

    const float inv_l = exp2f(-(float)(lane >> 1) * CEXP);
    constexpr int NC = S / 32;

    for (int r = w; r < S; r += 8) {
        int tr = tok_of<STAGE>(g, r);
        float q = qkv[(size_t)tr * 768 + h * 32 + lane];
        float partner = __shfl_xor_sync(0xFFFFFFFFu, q, 1);
        float ang = (float)r * inv_l;
        float sn, cs;
        sincosf(ang, &sn, &cs);
        float qr = (lane & 1) ? (q * cs + partner * sn) : (q * cs - partner * sn);
        Qb[w * 32 + lane] = qr * SCALE;
        __syncwarp();

        float s[NC];
        #pragma unroll
        for (int jj = 0; jj < NC; jj++) s[jj] = 0.0f;
        #pragma unroll
        for (int d = 0; d < 32; d++) {
            float qd = Qb[w * 32 + d];
            #pragma unroll
            for (int jj = 0; jj < NC; jj++)
                s[jj] += qd * Ksm[(lane + 32 * jj) * 33 + d];
        }

        float m = s[0];
        #pragma unroll
        for (int jj = 1; jj < NC; jj++) m = fmaxf(m, s[jj]);
        #pragma unroll
        for (int off = 16; off > 0; off >>= 1)
            m = fmaxf(m, __shfl_xor_sync(0xFFFFFFFFu, m, off));
        float sum = 0.0f;
        #pragma unroll
        for (int jj = 0; jj < NC; jj++) {
            float p = __expf(s[jj] - m);
            s[jj] = p;
            sum += p;
        }
        #pragma unroll
        for (int off = 16; off > 0; off >>= 1)
            sum += __shfl_xor_sync(0xFFFFFFFFu, sum, off);
        float invs = 1.0f / sum;
        #pragma unroll
        for (int jj = 0; jj < NC; jj++)
            Pb[w * S + lane + 32 * jj] = s[jj] * invs;
        __syncwarp();

        float o = 0.0f;
        #pragma unroll 8
        for (int k = 0; k < S; k++)
            o += Pb[w * S + k] * Vsm[k * 33 + lane];

        g_X[(size_t)tr * 256 + h * 32 + lane] = o;
        __syncwarp();
    }
}

// ---------------------------------------------------------------------------
extern "C" void kernel_launch(void* const* d_in, const int* in_sizes, int n_in,
                              void* d_out, int out_size) {
    const float* x  = (const float*)d_in[0];
    const float* W1 = (const float*)d_in[1];
    const float* W2 = (const float*)d_in[2];
    const float* W3 = (const float*)d_in[3];
    const float* Wp = (const float*)d_in[4];
    float* out = (float*)d_out;

    float* Xp;   cudaGetSymbolAddress((void**)&Xp,   g_X);
    float* QKVp; cudaGetSymbolAddress((void**)&QKVp, g_QKV);

    const int SMEM1 = (74 * 256 + 256) * 4;   // 76800
    const int SMEM2 = (74 * 64 + 256) * 4;    // 19968

    cudaFuncSetAttribute(attn_kernel<1, 256>,
                         cudaFuncAttributeMaxDynamicSharedMemorySize, SMEM1);

    permute_in_kernel<<<NT, 256>>>(x);

    // Stage 1
    tf32_gemm_kernel<<<dim3(768 / 128, NT / 128), 256>>>(Xp, W1, QKVp, NT, 768, 256);
    attn_kernel<1, 256><<<dim3(BB * FF, HH), 256, SMEM1>>>(QKVp);

    // Stage 2
    tf32_gemm_kernel<<<dim3(768 / 128, NT / 128), 256>>>(Xp, W2, QKVp, NT, 768, 256);
    attn_kernel<2, 64><<<dim3(BB * TT, HH), 256, SMEM2>>>(QKVp);

    // Stage 3
    tf32_gemm_kernel<<<dim3(768 / 128, NT / 128), 256>>>(Xp, W3, QKVp, NT, 768, 256);
    attn_kernel<3, 64><<<dim3(BB * (TT / 8) * (FF / 8), HH), 256, SMEM2>>>(QKVp);

    // Projection
    tf32_gemm_kernel<<<dim3(256 / 128, NT / 128), 256>>>(Xp, Wp, QKVp, NT, 256, 256);

    permute_out_kernel<<<NT, 256>>>(out);
}

// round 3
// speedup vs baseline: 1.6190x; 1.1814x over previous
#include <cuda_runtime.h>
#include <cuda_bf16.h>
#include <math.h>
#include <stdint.h>

// Problem constants
#define BB 4
#define DD 256
#define TT 256
#define FF 64
#define HH 8
#define HD 32
#define NT (BB*TT*FF)          // 65536 tokens

// Scratch (no allocations allowed -> device globals)
__device__ float g_X[(size_t)NT * DD];        // canonical token-major activations
__device__ float g_QKV[(size_t)NT * 3 * DD];  // qkv / reused as proj output

// ---------------------------------------------------------------------------
// TF32 helpers
// ---------------------------------------------------------------------------
__device__ __forceinline__ uint32_t f2tf32(float x) {
    uint32_t r;
    asm("cvt.rna.tf32.f32 %0, %1;" : "=r"(r) : "f"(x));
    return r;
}
__device__ __forceinline__ float tf32r(float x) { return __uint_as_float(f2tf32(x)); }

__device__ __forceinline__ void mma_tf32(float* c, const uint32_t* a, const uint32_t* b) {
    asm volatile(
        "mma.sync.aligned.m16n8k8.row.col.f32.tf32.tf32.f32 "
        "{%0,%1,%2,%3}, {%4,%5,%6,%7}, {%8,%9}, {%0,%1,%2,%3};"
        : "+f"(c[0]), "+f"(c[1]), "+f"(c[2]), "+f"(c[3])
        : "r"(a[0]), "r"(a[1]), "r"(a[2]), "r"(a[3]), "r"(b[0]), "r"(b[1]));
}

// ---------------------------------------------------------------------------
// Tiled transpose permutes (coalesced both sides)
// in:  x[b][d][tf] -> X[(b,tf)][d]     (per b: 256 x 16384 transpose)
// ---------------------------------------------------------------------------
__global__ __launch_bounds__(256) void permute_in_kernel(const float* __restrict__ x) {
    __shared__ float tile[32][33];
    const int b = blockIdx.z;
    const int tf0 = blockIdx.x * 32;
    const int d0 = blockIdx.y * 32;
    const int tx = threadIdx.x, ty = threadIdx.y;
    #pragma unroll
    for (int i = 0; i < 4; i++)
        tile[ty + 8 * i][tx] = x[((size_t)(b * 256 + d0 + ty + 8 * i) * 16384) + tf0 + tx];
    __syncthreads();
    #pragma unroll
    for (int i = 0; i < 4; i++)
        g_X[((size_t)(b * 16384 + tf0 + ty + 8 * i)) * 256 + d0 + tx] = tile[tx][ty + 8 * i];
}

// out[b][d][tf] = Y[(b,tf)][d]   (Y lives in g_QKV)
__global__ __launch_bounds__(256) void permute_out_kernel(float* __restrict__ out) {
    __shared__ float tile[32][33];
    const int b = blockIdx.z;
    const int d0 = blockIdx.x * 32;
    const int tf0 = blockIdx.y * 32;
    const int tx = threadIdx.x, ty = threadIdx.y;
    #pragma unroll
    for (int i = 0; i < 4; i++)
        tile[ty + 8 * i][tx] = g_QKV[((size_t)(b * 16384 + tf0 + ty + 8 * i)) * 256 + d0 + tx];
    __syncthreads();
    #pragma unroll
    for (int i = 0; i < 4; i++)
        out[((size_t)(b * 256 + d0 + ty + 8 * i) * 16384) + tf0 + tx] = tile[tx][ty + 8 * i];
}

// ---------------------------------------------------------------------------
// TF32 tensor-core GEMM: C[M,N] = A[M,K] @ B[K,N] (unchanged from round 2)
// ---------------------------------------------------------------------------
__global__ __launch_bounds__(256) void tf32_gemm_kernel(
    const float* __restrict__ A, const float* __restrict__ B, float* __restrict__ C,
    int M, int N, int K)
{
    __shared__ float As[128][36];
    __shared__ float Bs[32][136];

    const int tid = threadIdx.x;
    const int wid = tid >> 5;
    const int lane = tid & 31;
    const int tq = lane >> 2;
    const int tr = lane & 3;
    const int warp_m = (wid & 1) * 64;
    const int warp_n = (wid >> 1) * 32;
    const int bx = blockIdx.x * 128;
    const int by = blockIdx.y * 128;

    float acc[4][4][4];
    #pragma unroll
    for (int i = 0; i < 4; i++)
        #pragma unroll
        for (int j = 0; j < 4; j++)
            #pragma unroll
            for (int r = 0; r < 4; r++) acc[i][j][r] = 0.0f;

    const int am = tid >> 3;
    const int ak = (tid & 7) * 4;
    const int bk = tid >> 5;
    const int bn = (tid & 31) * 4;

    const float* Ag = A + (size_t)(by + am) * K + ak;
    const float* Bg = B + (size_t)bk * N + bx + bn;

    float4 aP[4], bP[4];
    #pragma unroll
    for (int it = 0; it < 4; it++) {
        aP[it] = *(const float4*)(Ag + (size_t)(32 * it) * K);
        bP[it] = *(const float4*)(Bg + (size_t)(8 * it) * N);
    }

    for (int k0 = 0; k0 < K; k0 += 32) {
        #pragma unroll
        for (int it = 0; it < 4; it++) {
            float4 a = aP[it];
            *(float4*)&As[am + 32 * it][ak] =
                make_float4(tf32r(a.x), tf32r(a.y), tf32r(a.z), tf32r(a.w));
            float4 b = bP[it];
            *(float4*)&Bs[bk + 8 * it][bn] =
                make_float4(tf32r(b.x), tf32r(b.y), tf32r(b.z), tf32r(b.w));
        }
        __syncthreads();

        if (k0 + 32 < K) {
            #pragma unroll
            for (int it = 0; it < 4; it++) {
                aP[it] = *(const float4*)(Ag + (size_t)(32 * it) * K + (k0 + 32));
                bP[it] = *(const float4*)(Bg + (size_t)(k0 + 32 + 8 * it) * N);
            }
        }

        #pragma unroll
        for (int c = 0; c < 4; c++) {
            const int ks = c * 8;
            uint32_t a[4][4], b[4][2];
            #pragma unroll
            for (int i = 0; i < 4; i++) {
                int row = warp_m + i * 16 + tq;
                a[i][0] = __float_as_uint(As[row][ks + tr]);
                a[i][1] = __float_as_uint(As[row + 8][ks + tr]);
                a[i][2] = __float_as_uint(As[row][ks + tr + 4]);
                a[i][3] = __float_as_uint(As[row + 8][ks + tr + 4]);
            }
            #pragma unroll
            for (int j = 0; j < 4; j++) {
                int col = warp_n + j * 8 + tq;
                b[j][0] = __float_as_uint(Bs[ks + tr][col]);
                b[j][1] = __float_as_uint(Bs[ks + tr + 4][col]);
            }
            #pragma unroll
            for (int i = 0; i < 4; i++)
                #pragma unroll
                for (int j = 0; j < 4; j++)
                    mma_tf32(acc[i][j], a[i], b[j]);
        }
        __syncthreads();
    }

    #pragma unroll
    for (int i = 0; i < 4; i++) {
        int row0 = by + warp_m + i * 16 + tq;
        #pragma unroll
        for (int j = 0; j < 4; j++) {
            int col0 = bx + warp_n + j * 8 + 2 * tr;
            *(float2*)&C[(size_t)row0 * N + col0] = make_float2(acc[i][j][0], acc[i][j][1]);
            *(float2*)&C[(size_t)(row0 + 8) * N + col0] = make_float2(acc[i][j][2], acc[i][j][3]);
        }
    }
}

// ---------------------------------------------------------------------------
// Token index for (group, position) per stage.
// ---------------------------------------------------------------------------
template <int STAGE>
__device__ __forceinline__ int tok_of(int g, int p) {
    if (STAGE == 1) {
        int b = g >> 6, f = g & 63;
        return (b * 256 + p) * 64 + f;
    } else if (STAGE == 2) {
        return g * 64 + p;
    } else {
        int b = g >> 8, rem = g & 255;
        int i = rem >> 3, jf = rem & 7;
        int t = i * 8 + (p >> 3);
        int f = jf * 8 + (p & 7);
        return (b * 256 + t) * 64 + f;
    }
}

// ---------------------------------------------------------------------------
// Tensor-core flash attention.
// Warp = 16 Q rows. QK^T in split-TF32 (3 mma, ~fp32 scores); PV plain TF32.
// HPB = heads per block (1 for S=256 slabs, 2 for S=64).
// smem per head: Khi[S][36] Klo[S][36] Vt[32][S+4] Qhi[QR][36] Qlo[QR][36];
// then Pbuf[8][16][68].
// ---------------------------------------------------------------------------
template <int STAGE, int S, int HPB>
__global__ __launch_bounds__(256) void attn_tc_kernel(const float* __restrict__ qkv) {
    constexpr int QR = (HPB == 1) ? 128 : S;
    constexpr int KS = S * 36;
    constexpr int VTS = 32 * (S + 4);
    constexpr int QS = QR * 36;
    constexpr int HSTR = 2 * KS + VTS + 2 * QS;
    extern __shared__ float sm[];
    float* Pbuf = sm + HPB * HSTR;

    const int g = blockIdx.x;
    const int tid = threadIdx.x;
    const int w = tid >> 5;
    const int lane = tid & 31;
    const int tq = lane >> 2;
    const int tr = lane & 3;

    const int hh = (HPB == 1) ? 0 : (w >> 2);
    const int h = blockIdx.y * HPB + hh;
    const int m_base = (HPB == 1) ? (w * 16) : ((w & 3) * 16);
    const int qoff = (HPB == 1) ? ((int)blockIdx.z * 128) : 0;

    const float SCALE = 0.17677669529663687f;   // 1/sqrt(32)
    const float CEXP  = 0.830482023721841f;     // log2(10000)/16

    // ---- K loader (RoPE + split) ----
    for (int idx = tid; idx < HPB * S * 16; idx += 256) {
        int hl = idx / (S * 16);
        int rem = idx - hl * S * 16;
        int k = rem >> 4, j = rem & 15;
        int tk = tok_of<STAGE>(g, k);
        const float* bp = qkv + (size_t)tk * 768 + 256 + (blockIdx.y * HPB + hl) * 32;
        float x0 = bp[2 * j], x1 = bp[2 * j + 1];
        float ang = (float)k * exp2f(-(float)j * CEXP);
        float sn, cs; sincosf(ang, &sn, &cs);
        float k0 = x0 * cs - x1 * sn;
        float k1 = x1 * cs + x0 * sn;
        float* Khi = sm + hl * HSTR;
        float* Klo = Khi + KS;
        float h0 = tf32r(k0); Khi[k * 36 + 2 * j] = h0;     Klo[k * 36 + 2 * j] = tf32r(k0 - h0);
        float h1 = tf32r(k1); Khi[k * 36 + 2 * j + 1] = h1; Klo[k * 36 + 2 * j + 1] = tf32r(k1 - h1);
    }
    // ---- Q loader (RoPE + scale + split) ----
    for (int idx = tid; idx < HPB * QR * 16; idx += 256) {
        int hl = idx / (QR * 16);
        int rem = idx - hl * QR * 16;
        int r = rem >> 4, j = rem & 15;
        int p = qoff + r;
        int tk = tok_of<STAGE>(g, p);
        const float* bp = qkv + (size_t)tk * 768 + (blockIdx.y * HPB + hl) * 32;
        float x0 = bp[2 * j], x1 = bp[2 * j + 1];
        float ang = (float)p * exp2f(-(float)j * CEXP);
        float sn, cs; sincosf(ang, &sn, &cs);
        float q0 = (x0 * cs - x1 * sn) * SCALE;
        float q1 = (x1 * cs + x0 * sn) * SCALE;
        float* Qhi = sm + hl * HSTR + 2 * KS + VTS;
        float* Qlo = Qhi + QS;
        float h0 = tf32r(q0); Qhi[r * 36 + 2 * j] = h0;     Qlo[r * 36 + 2 * j] = tf32r(q0 - h0);
        float h1 = tf32r(q1); Qhi[r * 36 + 2 * j + 1] = h1; Qlo[r * 36 + 2 * j + 1] = tf32r(q1 - h1);
    }
    // ---- V loader (transposed) ----
    for (int idx = tid; idx < HPB * S * 32; idx += 256) {
        int hl = idx / (S * 32);
        int rem = idx - hl * S * 32;
        int k = rem >> 5, d = rem & 31;
        float v = qkv[(size_t)tok_of<STAGE>(g, k) * 768 + 512 + (blockIdx.y * HPB + hl) * 32 + d];
        (sm + hl * HSTR + 2 * KS)[d * (S + 4) + k] = tf32r(v);
    }
    __syncthreads();

    const float* Khi = sm + hh * HSTR;
    const float* Klo = Khi + KS;
    const float* Vt = Khi + 2 * KS;
    const float* Qhi = Vt + VTS;
    const float* Qlo = Qhi + QS;
    float* Pw = Pbuf + w * 16 * 68;

    // Q a-fragments (held in regs for the whole kernel)
    uint32_t qh[4][4], ql[4][4];
    #pragma unroll
    for (int kt = 0; kt < 4; kt++) {
        int c = kt * 8 + tr;
        qh[kt][0] = __float_as_uint(Qhi[(m_base + tq) * 36 + c]);
        qh[kt][1] = __float_as_uint(Qhi[(m_base + tq + 8) * 36 + c]);
        qh[kt][2] = __float_as_uint(Qhi[(m_base + tq) * 36 + c + 4]);
        qh[kt][3] = __float_as_uint(Qhi[(m_base + tq + 8) * 36 + c + 4]);
        ql[kt][0] = __float_as_uint(Qlo[(m_base + tq) * 36 + c]);
        ql[kt][1] = __float_as_uint(Qlo[(m_base + tq + 8) * 36 + c]);
        ql[kt][2] = __float_as_uint(Qlo[(m_base + tq) * 36 + c + 4]);
        ql[kt][3] = __float_as_uint(Qlo[(m_base + tq + 8) * 36 + c + 4]);
    }

    float co[4][4];
    #pragma unroll
    for (int i = 0; i < 4; i++)
        #pragma unroll
        for (int j = 0; j < 4; j++) co[i][j] = 0.0f;
    float mrun0 = -1e30f, mrun1 = -1e30f, lrun0 = 0.0f, lrun1 = 0.0f;

    for (int j0 = 0; j0 < S; j0 += 64) {
        // --- scores: 16 x 64, split-TF32 ---
        float sc[8][4];
        #pragma unroll
        for (int nt = 0; nt < 8; nt++) {
            float c4[4] = {0.0f, 0.0f, 0.0f, 0.0f};
            #pragma unroll
            for (int kt = 0; kt < 4; kt++) {
                int krow = (j0 + nt * 8 + tq) * 36 + kt * 8 + tr;
                uint32_t bh[2] = {__float_as_uint(Khi[krow]), __float_as_uint(Khi[krow + 4])};
                uint32_t bl[2] = {__float_as_uint(Klo[krow]), __float_as_uint(Klo[krow + 4])};
                mma_tf32(c4, qh[kt], bh);
                mma_tf32(c4, ql[kt], bh);
                mma_tf32(c4, qh[kt], bl);
            }
            #pragma unroll
            for (int r = 0; r < 4; r++) sc[nt][r] = c4[r];
        }

        // --- online softmax (rows tq and tq+8) ---
        float mx0 = -1e30f, mx1 = -1e30f;
        #pragma unroll
        for (int nt = 0; nt < 8; nt++) {
            mx0 = fmaxf(mx0, fmaxf(sc[nt][0], sc[nt][1]));
            mx1 = fmaxf(mx1, fmaxf(sc[nt][2], sc[nt][3]));
        }
        mx0 = fmaxf(mx0, __shfl_xor_sync(0xFFFFFFFFu, mx0, 1));
        mx0 = fmaxf(mx0, __shfl_xor_sync(0xFFFFFFFFu, mx0, 2));
        mx1 = fmaxf(mx1, __shfl_xor_sync(0xFFFFFFFFu, mx1, 1));
        mx1 = fmaxf(mx1, __shfl_xor_sync(0xFFFFFFFFu, mx1, 2));
        float mn0 = fmaxf(mrun0, mx0), mn1 = fmaxf(mrun1, mx1);
        float esc0 = __expf(mrun0 - mn0), esc1 = __expf(mrun1 - mn1);
        float s0 = 0.0f, s1 = 0.0f;
        #pragma unroll
        for (int nt = 0; nt < 8; nt++) {
            float p0 = __expf(sc[nt][0] - mn0);
            float p1 = __expf(sc[nt][1] - mn0);
            float p2 = __expf(sc[nt][2] - mn1);
            float p3 = __expf(sc[nt][3] - mn1);
            s0 += p0 + p1;
            s1 += p2 + p3;
            *(float2*)&Pw[tq * 68 + nt * 8 + 2 * tr] = make_float2(tf32r(p0), tf32r(p1));
            *(float2*)&Pw[(tq + 8) * 68 + nt * 8 + 2 * tr] = make_float2(tf32r(p2), tf32r(p3));
        }
        s0 += __shfl_xor_sync(0xFFFFFFFFu, s0, 1);
        s0 += __shfl_xor_sync(0xFFFFFFFFu, s0, 2);
        s1 += __shfl_xor_sync(0xFFFFFFFFu, s1, 1);
        s1 += __shfl_xor_sync(0xFFFFFFFFu, s1, 2);
        lrun0 = lrun0 * esc0 + s0;
        lrun1 = lrun1 * esc1 + s1;
        mrun0 = mn0; mrun1 = mn1;
        #pragma unroll
        for (int nt2 = 0; nt2 < 4; nt2++) {
            co[nt2][0] *= esc0; co[nt2][1] *= esc0;
            co[nt2][2] *= esc1; co[nt2][3] *= esc1;
        }
        __syncwarp();

        // --- PV: O += P(16x64) @ V(64x32) ---
        #pragma unroll
        for (int kt2 = 0; kt2 < 8; kt2++) {
            int kc = kt2 * 8 + tr;
            uint32_t a[4];
            a[0] = __float_as_uint(Pw[tq * 68 + kc]);
            a[1] = __float_as_uint(Pw[(tq + 8) * 68 + kc]);
            a[2] = __float_as_uint(Pw[tq * 68 + kc + 4]);
            a[3] = __float_as_uint(Pw[(tq + 8) * 68 + kc + 4]);
            #pragma unroll
            for (int nt2 = 0; nt2 < 4; nt2++) {
                const float* vrow = Vt + (nt2 * 8 + tq) * (S + 4) + j0 + kc;
                uint32_t b[2] = {__float_as_uint(vrow[0]), __float_as_uint(vrow[4])};
                mma_tf32(co[nt2], a, b);
            }
        }
        __syncwarp();
    }

    float inv0 = 1.0f / lrun0, inv1 = 1.0f / lrun1;
    int p0r = qoff + m_base + tq;
    size_t o0 = (size_t)tok_of<STAGE>(g, p0r) * 256 + h * 32;
    size_t o1 = (size_t)tok_of<STAGE>(g, p0r + 8) * 256 + h * 32;
    #pragma unroll
    for (int nt2 = 0; nt2 < 4; nt2++) {
        int cc = nt2 * 8 + 2 * tr;
        *(float2*)&g_X[o0 + cc] = make_float2(co[nt2][0] * inv0, co[nt2][1] * inv0);
        *(float2*)&g_X[o1 + cc] = make_float2(co[nt2][2] * inv1, co[nt2][3] * inv1);
    }
}

// ---------------------------------------------------------------------------
extern "C" void kernel_launch(void* const* d_in, const int* in_sizes, int n_in,
                              void* d_out, int out_size) {
    const float* x  = (const float*)d_in[0];
    const float* W1 = (const float*)d_in[1];
    const float* W2 = (const float*)d_in[2];
    const float* W3 = (const float*)d_in[3];
    const float* Wp = (const float*)d_in[4];
    float* out = (float*)d_out;

    float* Xp;   cudaGetSymbolAddress((void**)&Xp,   g_X);
    float* QKVp; cudaGetSymbolAddress((void**)&QKVp, g_QKV);

    // smem bytes: stage1: (2*256*36 + 32*260 + 2*128*36 + 8704)*4 = 178688
    //             stage2/3: (2*(2*64*36 + 32*68 + 2*64*36) + 8704)*4 = 125952
    const int SMEM1 = 178688;
    const int SMEM2 = 125952;
    cudaFuncSetAttribute(attn_tc_kernel<1, 256, 1>,
                         cudaFuncAttributeMaxDynamicSharedMemorySize, SMEM1);
    cudaFuncSetAttribute(attn_tc_kernel<2, 64, 2>,
                         cudaFuncAttributeMaxDynamicSharedMemorySize, SMEM2);
    cudaFuncSetAttribute(attn_tc_kernel<3, 64, 2>,
                         cudaFuncAttributeMaxDynamicSharedMemorySize, SMEM2);

    // input permute (tiled transpose per batch)
    permute_in_kernel<<<dim3(512, 8, 4), dim3(32, 8)>>>(x);

    // Stage 1: time-axis attention (S=256)
    tf32_gemm_kernel<<<dim3(6, 512), 256>>>(Xp, W1, QKVp, NT, 768, 256);
    attn_tc_kernel<1, 256, 1><<<dim3(256, 8, 2), 256, SMEM1>>>(QKVp);

    // Stage 2: freq-axis attention (S=64)
    tf32_gemm_kernel<<<dim3(6, 512), 256>>>(Xp, W2, QKVp, NT, 768, 256);
    attn_tc_kernel<2, 64, 2><<<dim3(1024, 4, 1), 256, SMEM2>>>(QKVp);

    // Stage 3: windowed attention (S=64)
    tf32_gemm_kernel<<<dim3(6, 512), 256>>>(Xp, W3, QKVp, NT, 768, 256);
    attn_tc_kernel<3, 64, 2><<<dim3(1024, 4, 1), 256, SMEM2>>>(QKVp);

    // Projection
    tf32_gemm_kernel<<<dim3(2, 512), 256>>>(Xp, Wp, QKVp, NT, 256, 256);

    // output permute
    permute_out_kernel<<<dim3(8, 512, 4), dim3(32, 8)>>>(out);
}

// round 4
// speedup vs baseline: 2.0240x; 1.2501x over previous
#include <cuda_runtime.h>
#include <cuda_bf16.h>
#include <math.h>
#include <stdint.h>

// Problem constants
#define BB 4
#define DD 256
#define TT 256
#define FF 64
#define HH 8
#define HD 32
#define NT (BB*TT*FF)          // 65536 tokens

// Scratch (no allocations allowed -> device globals)
__device__ float g_X[(size_t)NT * DD];        // canonical token-major activations
__device__ float g_QKV[(size_t)NT * 3 * DD];  // qkv / reused as proj output
__device__ float2 g_rope[256 * 16];           // cos/sin table [pos][j]

// ---------------------------------------------------------------------------
// TF32 helpers
// ---------------------------------------------------------------------------
__device__ __forceinline__ uint32_t f2tf32(float x) {
    uint32_t r;
    asm("cvt.rna.tf32.f32 %0, %1;" : "=r"(r) : "f"(x));
    return r;
}
__device__ __forceinline__ float tf32r(float x) { return __uint_as_float(f2tf32(x)); }

__device__ __forceinline__ void mma_tf32(float* c, const uint32_t* a, const uint32_t* b) {
    asm volatile(
        "mma.sync.aligned.m16n8k8.row.col.f32.tf32.tf32.f32 "
        "{%0,%1,%2,%3}, {%4,%5,%6,%7}, {%8,%9}, {%0,%1,%2,%3};"
        : "+f"(c[0]), "+f"(c[1]), "+f"(c[2]), "+f"(c[3])
        : "r"(a[0]), "r"(a[1]), "r"(a[2]), "r"(a[3]), "r"(b[0]), "r"(b[1]));
}

// ---------------------------------------------------------------------------
// RoPE table: cos/sin for pos in [0,256), j in [0,16)
// ---------------------------------------------------------------------------
__global__ __launch_bounds__(256) void rope_table_kernel() {
    int i = blockIdx.x * 256 + threadIdx.x;   // 4096
    int p = i >> 4, j = i & 15;
    const float CEXP = 0.830482023721841f;    // log2(10000)/16
    float inv = exp2f(-(float)j * CEXP);
    float sn, cs;
    sincosf((float)p * inv, &sn, &cs);
    g_rope[i] = make_float2(cs, sn);
}

// ---------------------------------------------------------------------------
// Tiled transpose permutes (coalesced both sides)
// ---------------------------------------------------------------------------
__global__ __launch_bounds__(256) void permute_in_kernel(const float* __restrict__ x) {
    __shared__ float tile[32][33];
    const int b = blockIdx.z;
    const int tf0 = blockIdx.x * 32;
    const int d0 = blockIdx.y * 32;
    const int tx = threadIdx.x, ty = threadIdx.y;
    #pragma unroll
    for (int i = 0; i < 4; i++)
        tile[ty + 8 * i][tx] = x[((size_t)(b * 256 + d0 + ty + 8 * i) * 16384) + tf0 + tx];
    __syncthreads();
    #pragma unroll
    for (int i = 0; i < 4; i++)
        g_X[((size_t)(b * 16384 + tf0 + ty + 8 * i)) * 256 + d0 + tx] = tile[tx][ty + 8 * i];
}

__global__ __launch_bounds__(256) void permute_out_kernel(float* __restrict__ out) {
    __shared__ float tile[32][33];
    const int b = blockIdx.z;
    const int d0 = blockIdx.x * 32;
    const int tf0 = blockIdx.y * 32;
    const int tx = threadIdx.x, ty = threadIdx.y;
    #pragma unroll
    for (int i = 0; i < 4; i++)
        tile[ty + 8 * i][tx] = g_QKV[((size_t)(b * 16384 + tf0 + ty + 8 * i)) * 256 + d0 + tx];
    __syncthreads();
    #pragma unroll
    for (int i = 0; i < 4; i++)
        out[((size_t)(b * 256 + d0 + ty + 8 * i) * 16384) + tf0 + tx] = tile[tx][ty + 8 * i];
}

// ---------------------------------------------------------------------------
// TF32 GEMM with 2-stage smem double buffering.
// C[M,N] = A[M,K] @ B[K,N]; tiles 128x128x32; 8 warps (2x4) of 64x32.
// ---------------------------------------------------------------------------
__global__ __launch_bounds__(256) void tf32_gemm_kernel(
    const float* __restrict__ A, const float* __restrict__ B, float* __restrict__ C,
    int M, int N, int K)
{
    extern __shared__ float smg[];
    float* Asm = smg;                       // [2][128][36]
    float* Bsm = smg + 2 * 128 * 36;        // [2][32][136]

    const int tid = threadIdx.x;
    const int wid = tid >> 5;
    const int lane = tid & 31;
    const int tq = lane >> 2;
    const int tr = lane & 3;
    const int warp_m = (wid & 1) * 64;
    const int warp_n = (wid >> 1) * 32;
    const int bx = blockIdx.x * 128;
    const int by = blockIdx.y * 128;

    float acc[4][4][4];
    #pragma unroll
    for (int i = 0; i < 4; i++)
        #pragma unroll
        for (int j = 0; j < 4; j++)
            #pragma unroll
            for (int r = 0; r < 4; r++) acc[i][j][r] = 0.0f;

    const int am = tid >> 3;
    const int ak = (tid & 7) * 4;
    const int bk = tid >> 5;
    const int bn = (tid & 31) * 4;

    const float* Ag = A + (size_t)(by + am) * K + ak;
    const float* Bg = B + (size_t)bk * N + bx + bn;

    float4 aP[4], bP[4];
    #pragma unroll
    for (int it = 0; it < 4; it++) {
        aP[it] = *(const float4*)(Ag + (size_t)(32 * it) * K);
        bP[it] = *(const float4*)(Bg + (size_t)(8 * it) * N);
    }
    // store tile 0
    #pragma unroll
    for (int it = 0; it < 4; it++) {
        float4 a = aP[it];
        *(float4*)&Asm[(am + 32 * it) * 36 + ak] =
            make_float4(tf32r(a.x), tf32r(a.y), tf32r(a.z), tf32r(a.w));
        float4 b = bP[it];
        *(float4*)&Bsm[(bk + 8 * it) * 136 + bn] =
            make_float4(tf32r(b.x), tf32r(b.y), tf32r(b.z), tf32r(b.w));
    }
    __syncthreads();

    const int ntiles = K >> 5;
    for (int kt = 0; kt < ntiles; kt++) {
        const int cur = kt & 1;
        const float* As = Asm + cur * 128 * 36;
        const float* Bs = Bsm + cur * 32 * 136;

        if (kt + 1 < ntiles) {
            const int ko = (kt + 1) * 32;
            #pragma unroll
            for (int it = 0; it < 4; it++) {
                aP[it] = *(const float4*)(Ag + (size_t)(32 * it) * K + ko);
                bP[it] = *(const float4*)(Bg + (size_t)(ko + 8 * it) * N);
            }
        }

        #pragma unroll
        for (int c = 0; c < 4; c++) {
            const int ks = c * 8;
            uint32_t a[4][4], b[4][2];
            #pragma unroll
            for (int i = 0; i < 4; i++) {
                int row = warp_m + i * 16 + tq;
                a[i][0] = __float_as_uint(As[row * 36 + ks + tr]);
                a[i][1] = __float_as_uint(As[(row + 8) * 36 + ks + tr]);
                a[i][2] = __float_as_uint(As[row * 36 + ks + tr + 4]);
                a[i][3] = __float_as_uint(As[(row + 8) * 36 + ks + tr + 4]);
            }
            #pragma unroll
            for (int j = 0; j < 4; j++) {
                int col = warp_n + j * 8 + tq;
                b[j][0] = __float_as_uint(Bs[(ks + tr) * 136 + col]);
                b[j][1] = __float_as_uint(Bs[(ks + tr + 4) * 136 + col]);
            }
            #pragma unroll
            for (int i = 0; i < 4; i++)
                #pragma unroll
                for (int j = 0; j < 4; j++)
                    mma_tf32(acc[i][j], a[i], b[j]);
        }

        if (kt + 1 < ntiles) {
            float* An = Asm + (cur ^ 1) * 128 * 36;
            float* Bn = Bsm + (cur ^ 1) * 32 * 136;
            #pragma unroll
            for (int it = 0; it < 4; it++) {
                float4 a = aP[it];
                *(float4*)&An[(am + 32 * it) * 36 + ak] =
                    make_float4(tf32r(a.x), tf32r(a.y), tf32r(a.z), tf32r(a.w));
                float4 b = bP[it];
                *(float4*)&Bn[(bk + 8 * it) * 136 + bn] =
                    make_float4(tf32r(b.x), tf32r(b.y), tf32r(b.z), tf32r(b.w));
            }
        }
        __syncthreads();
    }

    #pragma unroll
    for (int i = 0; i < 4; i++) {
        int row0 = by + warp_m + i * 16 + tq;
        #pragma unroll
        for (int j = 0; j < 4; j++) {
            int col0 = bx + warp_n + j * 8 + 2 * tr;
            *(float2*)&C[(size_t)row0 * N + col0] = make_float2(acc[i][j][0], acc[i][j][1]);
            *(float2*)&C[(size_t)(row0 + 8) * N + col0] = make_float2(acc[i][j][2], acc[i][j][3]);
        }
    }
}

// ---------------------------------------------------------------------------
// Token index for (group, position) per stage.
// ---------------------------------------------------------------------------
template <int STAGE>
__device__ __forceinline__ int tok_of(int g, int p) {
    if (STAGE == 1) {
        int b = g >> 6, f = g & 63;
        return (b * 256 + p) * 64 + f;
    } else if (STAGE == 2) {
        return g * 64 + p;
    } else {
        int b = g >> 8, rem = g & 255;
        int i = rem >> 3, jf = rem & 7;
        int t = i * 8 + (p >> 3);
        int f = jf * 8 + (p & 7);
        return (b * 256 + t) * 64 + f;
    }
}

// ---------------------------------------------------------------------------
// Tensor-core flash attention. K/Q stored fp32 in smem, split to TF32 hi/lo
// on the fly (3-MMA split product for scores); PV plain TF32.
// KV chunked at 32 cols. smem per head: K[S][36] Vt[32][S+4] Q[QR][36];
// then Pbuf[8][16][36].
// ---------------------------------------------------------------------------
template <int STAGE, int S, int HPB>
__global__ __launch_bounds__(256) void attn_tc_kernel(const float* __restrict__ qkv) {
    constexpr int QR = (HPB == 1) ? 128 : S;
    constexpr int HS = S * 36 + 32 * (S + 4) + QR * 36;
    extern __shared__ float sm[];
    float* Pbuf = sm + HPB * HS;

    const int g = blockIdx.x;
    const int tid = threadIdx.x;
    const int w = tid >> 5;
    const int lane = tid & 31;
    const int tq = lane >> 2;
    const int tr = lane & 3;

    const int hh = (HPB == 1) ? 0 : (w >> 2);
    const int h = blockIdx.y * HPB + hh;
    const int m_base = (HPB == 1) ? (w * 16) : ((w & 3) * 16);
    const int qoff = (HPB == 1) ? ((int)blockIdx.z * 128) : 0;

    const float SCALE = 0.17677669529663687f;   // 1/sqrt(32)

    // ---- K loader (RoPE via table) ----
    for (int idx = tid; idx < HPB * S * 16; idx += 256) {
        int hl = idx / (S * 16);
        int rem = idx - hl * S * 16;
        int k = rem >> 4, j = rem & 15;
        int tk = tok_of<STAGE>(g, k);
        const float* bp = qkv + (size_t)tk * 768 + 256 + (blockIdx.y * HPB + hl) * 32;
        float x0 = bp[2 * j], x1 = bp[2 * j + 1];
        float2 cssn = g_rope[k * 16 + j];
        float* Ksm = sm + hl * HS;
        Ksm[k * 36 + 2 * j]     = x0 * cssn.x - x1 * cssn.y;
        Ksm[k * 36 + 2 * j + 1] = x1 * cssn.x + x0 * cssn.y;
    }
    // ---- Q loader (RoPE + scale) ----
    for (int idx = tid; idx < HPB * QR * 16; idx += 256) {
        int hl = idx / (QR * 16);
        int rem = idx - hl * QR * 16;
        int r = rem >> 4, j = rem & 15;
        int p = qoff + r;
        int tk = tok_of<STAGE>(g, p);
        const float* bp = qkv + (size_t)tk * 768 + (blockIdx.y * HPB + hl) * 32;
        float x0 = bp[2 * j], x1 = bp[2 * j + 1];
        float2 cssn = g_rope[p * 16 + j];
        float* Qsm = sm + hl * HS + S * 36 + 32 * (S + 4);
        Qsm[r * 36 + 2 * j]     = (x0 * cssn.x - x1 * cssn.y) * SCALE;
        Qsm[r * 36 + 2 * j + 1] = (x1 * cssn.x + x0 * cssn.y) * SCALE;
    }
    // ---- V loader (transposed, tf32-rounded) ----
    for (int idx = tid; idx < HPB * S * 32; idx += 256) {
        int hl = idx / (S * 32);
        int rem = idx - hl * S * 32;
        int k = rem >> 5, d = rem & 31;
        float v = qkv[(size_t)tok_of<STAGE>(g, k) * 768 + 512 + (blockIdx.y * HPB + hl) * 32 + d];
        (sm + hl * HS + S * 36)[d * (S + 4) + k] = tf32r(v);
    }
    __syncthreads();

    const float* Ksm = sm + hh * HS;
    const float* Vt = Ksm + S * 36;
    const float* Qsm = Vt + 32 * (S + 4);
    float* Pw = Pbuf + w * 16 * 36;

    // Q fragments split hi/lo into regs (held for whole kernel)
    uint32_t qh[4][4], ql[4][4];
    #pragma unroll
    for (int kt = 0; kt < 4; kt++) {
        int c = kt * 8 + tr;
        float f0 = Qsm[(m_base + tq) * 36 + c];
        float f1 = Qsm[(m_base + tq + 8) * 36 + c];
        float f2 = Qsm[(m_base + tq) * 36 + c + 4];
        float f3 = Qsm[(m_base + tq + 8) * 36 + c + 4];
        qh[kt][0] = f2tf32(f0); ql[kt][0] = f2tf32(f0 - __uint_as_float(qh[kt][0]));
        qh[kt][1] = f2tf32(f1); ql[kt][1] = f2tf32(f1 - __uint_as_float(qh[kt][1]));
        qh[kt][2] = f2tf32(f2); ql[kt][2] = f2tf32(f2 - __uint_as_float(qh[kt][2]));
        qh[kt][3] = f2tf32(f3); ql[kt][3] = f2tf32(f3 - __uint_as_float(qh[kt][3]));
    }

    float co[4][4];
    #pragma unroll
    for (int i = 0; i < 4; i++)
        #pragma unroll
        for (int j = 0; j < 4; j++) co[i][j] = 0.0f;
    float mrun0 = -1e30f, mrun1 = -1e30f, lrun0 = 0.0f, lrun1 = 0.0f;

    for (int j0 = 0; j0 < S; j0 += 32) {
        // --- scores: 16 x 32, split-TF32 ---
        float sc[4][4];
        #pragma unroll
        for (int nt = 0; nt < 4; nt++) {
            float c4[4] = {0.0f, 0.0f, 0.0f, 0.0f};
            #pragma unroll
            for (int kt = 0; kt < 4; kt++) {
                int krow = (j0 + nt * 8 + tq) * 36 + kt * 8 + tr;
                float k0 = Ksm[krow], k4 = Ksm[krow + 4];
                uint32_t bh[2], bl[2];
                bh[0] = f2tf32(k0); bl[0] = f2tf32(k0 - __uint_as_float(bh[0]));
                bh[1] = f2tf32(k4); bl[1] = f2tf32(k4 - __uint_as_float(bh[1]));
                mma_tf32(c4, qh[kt], bh);
                mma_tf32(c4, ql[kt], bh);
                mma_tf32(c4, qh[kt], bl);
            }
            #pragma unroll
            for (int r = 0; r < 4; r++) sc[nt][r] = c4[r];
        }

        // --- online softmax (rows tq and tq+8) ---
        float mx0 = -1e30f, mx1 = -1e30f;
        #pragma unroll
        for (int nt = 0; nt < 4; nt++) {
            mx0 = fmaxf(mx0, fmaxf(sc[nt][0], sc[nt][1]));
            mx1 = fmaxf(mx1, fmaxf(sc[nt][2], sc[nt][3]));
        }
        mx0 = fmaxf(mx0, __shfl_xor_sync(0xFFFFFFFFu, mx0, 1));
        mx0 = fmaxf(mx0, __shfl_xor_sync(0xFFFFFFFFu, mx0, 2));
        mx1 = fmaxf(mx1, __shfl_xor_sync(0xFFFFFFFFu, mx1, 1));
        mx1 = fmaxf(mx1, __shfl_xor_sync(0xFFFFFFFFu, mx1, 2));
        float mn0 = fmaxf(mrun0, mx0), mn1 = fmaxf(mrun1, mx1);
        float esc0 = __expf(mrun0 - mn0), esc1 = __expf(mrun1 - mn1);
        float s0 = 0.0f, s1 = 0.0f;
        #pragma unroll
        for (int nt = 0; nt < 4; nt++) {
            float p0 = __expf(sc[nt][0] - mn0);
            float p1 = __expf(sc[nt][1] - mn0);
            float p2 = __expf(sc[nt][2] - mn1);
            float p3 = __expf(sc[nt][3] - mn1);
            s0 += p0 + p1;
            s1 += p2 + p3;
            *(float2*)&Pw[tq * 36 + nt * 8 + 2 * tr] = make_float2(tf32r(p0), tf32r(p1));
            *(float2*)&Pw[(tq + 8) * 36 + nt * 8 + 2 * tr] = make_float2(tf32r(p2), tf32r(p3));
        }
        s0 += __shfl_xor_sync(0xFFFFFFFFu, s0, 1);
        s0 += __shfl_xor_sync(0xFFFFFFFFu, s0, 2);
        s1 += __shfl_xor_sync(0xFFFFFFFFu, s1, 1);
        s1 += __shfl_xor_sync(0xFFFFFFFFu, s1, 2);
        lrun0 = lrun0 * esc0 + s0;
        lrun1 = lrun1 * esc1 + s1;
        mrun0 = mn0; mrun1 = mn1;
        #pragma unroll
        for (int nt2 = 0; nt2 < 4; nt2++) {
            co[nt2][0] *= esc0; co[nt2][1] *= esc0;
            co[nt2][2] *= esc1; co[nt2][3] *= esc1;
        }
        __syncwarp();

        // --- PV: O += P(16x32) @ V(32x32) ---
        #pragma unroll
        for (int kt2 = 0; kt2 < 4; kt2++) {
            int kc = kt2 * 8 + tr;
            uint32_t a[4];
            a[0] = __float_as_uint(Pw[tq * 36 + kc]);
            a[1] = __float_as_uint(Pw[(tq + 8) * 36 + kc]);
            a[2] = __float_as_uint(Pw[tq * 36 + kc + 4]);
            a[3] = __float_as_uint(Pw[(tq + 8) * 36 + kc + 4]);
            #pragma unroll
            for (int nt2 = 0; nt2 < 4; nt2++) {
                const float* vrow = Vt + (nt2 * 8 + tq) * (S + 4) + j0 + kc;
                uint32_t b[2] = {__float_as_uint(vrow[0]), __float_as_uint(vrow[4])};
                mma_tf32(co[nt2], a, b);
            }
        }
        __syncwarp();
    }

    float inv0 = 1.0f / lrun0, inv1 = 1.0f / lrun1;
    int p0r = qoff + m_base + tq;
    size_t o0 = (size_t)tok_of<STAGE>(g, p0r) * 256 + h * 32;
    size_t o1 = (size_t)tok_of<STAGE>(g, p0r + 8) * 256 + h * 32;
    #pragma unroll
    for (int nt2 = 0; nt2 < 4; nt2++) {
        int cc = nt2 * 8 + 2 * tr;
        *(float2*)&g_X[o0 + cc] = make_float2(co[nt2][0] * inv0, co[nt2][1] * inv0);
        *(float2*)&g_X[o1 + cc] = make_float2(co[nt2][2] * inv1, co[nt2][3] * inv1);
    }
}

// ---------------------------------------------------------------------------
extern "C" void kernel_launch(void* const* d_in, const int* in_sizes, int n_in,
                              void* d_out, int out_size) {
    const float* x  = (const float*)d_in[0];
    const float* W1 = (const float*)d_in[1];
    const float* W2 = (const float*)d_in[2];
    const float* W3 = (const float*)d_in[3];
    const float* Wp = (const float*)d_in[4];
    float* out = (float*)d_out;

    float* Xp;   cudaGetSymbolAddress((void**)&Xp,   g_X);
    float* QKVp; cudaGetSymbolAddress((void**)&QKVp, g_QKV);

    const int SMEMG = (2 * 128 * 36 + 2 * 32 * 136) * 4;   // 71680
    // attn smem: stage1: (256*36 + 32*260 + 128*36 + 8*16*36)*4 = 107008
    //            stage2/3: (2*(64*36 + 32*68 + 64*36) + 8*16*36)*4 = 72704
    const int SMEM1 = 107008;
    const int SMEM2 = 72704;

    cudaFuncSetAttribute(tf32_gemm_kernel,
                         cudaFuncAttributeMaxDynamicSharedMemorySize, SMEMG);
    cudaFuncSetAttribute(attn_tc_kernel<1, 256, 1>,
                         cudaFuncAttributeMaxDynamicSharedMemorySize, SMEM1);
    cudaFuncSetAttribute(attn_tc_kernel<2, 64, 2>,
                         cudaFuncAttributeMaxDynamicSharedMemorySize, SMEM2);
    cudaFuncSetAttribute(attn_tc_kernel<3, 64, 2>,
                         cudaFuncAttributeMaxDynamicSharedMemorySize, SMEM2);

    rope_table_kernel<<<16, 256>>>();
    permute_in_kernel<<<dim3(512, 8, 4), dim3(32, 8)>>>(x);

    // Stage 1: time-axis attention (S=256)
    tf32_gemm_kernel<<<dim3(6, 512), 256, SMEMG>>>(Xp, W1, QKVp, NT, 768, 256);
    attn_tc_kernel<1, 256, 1><<<dim3(256, 8, 2), 256, SMEM1>>>(QKVp);

    // Stage 2: freq-axis attention (S=64)
    tf32_gemm_kernel<<<dim3(6, 512), 256, SMEMG>>>(Xp, W2, QKVp, NT, 768, 256);
    attn_tc_kernel<2, 64, 2><<<dim3(1024, 4, 1), 256, SMEM2>>>(QKVp);

    // Stage 3: windowed attention (S=64)
    tf32_gemm_kernel<<<dim3(6, 512), 256, SMEMG>>>(Xp, W3, QKVp, NT, 768, 256);
    attn_tc_kernel<3, 64, 2><<<dim3(1024, 4, 1), 256, SMEM2>>>(QKVp);

    // Projection
    tf32_gemm_kernel<<<dim3(2, 512), 256, SMEMG>>>(Xp, Wp, QKVp, NT, 256, 256);

    permute_out_kernel<<<dim3(8, 512, 4), dim3(32, 8)>>>(out);
}

// round 6
// speedup vs baseline: 2.2668x; 1.1200x over previous
#include <cuda_runtime.h>
#include <cuda_bf16.h>
#include <math.h>
#include <stdint.h>

// Problem constants
#define BB 4
#define DD 256
#define TT 256
#define FF 64
#define HH 8
#define HD 32
#define NT (BB*TT*FF)          // 65536 tokens

// Scratch (no allocations allowed -> device globals)
__device__ float g_X[(size_t)NT * DD];        // canonical token-major activations
__device__ float g_QKV[(size_t)NT * 3 * DD];  // qkv / reused as proj output
__device__ float2 g_rope[256 * 16];           // cos/sin table [pos][j]

// ---------------------------------------------------------------------------
// TF32 / bf16 helpers
// ---------------------------------------------------------------------------
__device__ __forceinline__ uint32_t f2tf32(float x) {
    uint32_t r;
    asm("cvt.rna.tf32.f32 %0, %1;" : "=r"(r) : "f"(x));
    return r;
}
__device__ __forceinline__ float tf32r(float x) { return __uint_as_float(f2tf32(x)); }

__device__ __forceinline__ void mma_tf32(float* c, const uint32_t* a, const uint32_t* b) {
    asm volatile(
        "mma.sync.aligned.m16n8k8.row.col.f32.tf32.tf32.f32 "
        "{%0,%1,%2,%3}, {%4,%5,%6,%7}, {%8,%9}, {%0,%1,%2,%3};"
        : "+f"(c[0]), "+f"(c[1]), "+f"(c[2]), "+f"(c[3])
        : "r"(a[0]), "r"(a[1]), "r"(a[2]), "r"(a[3]), "r"(b[0]), "r"(b[1]));
}

__device__ __forceinline__ void mma_bf16(float* c, const uint32_t* a, const uint32_t* b) {
    asm volatile(
        "mma.sync.aligned.m16n8k16.row.col.f32.bf16.bf16.f32 "
        "{%0,%1,%2,%3}, {%4,%5,%6,%7}, {%8,%9}, {%0,%1,%2,%3};"
        : "+f"(c[0]), "+f"(c[1]), "+f"(c[2]), "+f"(c[3])
        : "r"(a[0]), "r"(a[1]), "r"(a[2]), "r"(a[3]), "r"(b[0]), "r"(b[1]));
}

// pack two floats' bf16 hi parts / lo residuals
__device__ __forceinline__ uint32_t pack_bf16_hi(float x0, float x1, float& r0, float& r1) {
    __nv_bfloat16 h0 = __float2bfloat16(x0);
    __nv_bfloat16 h1 = __float2bfloat16(x1);
    r0 = x0 - __bfloat162float(h0);
    r1 = x1 - __bfloat162float(h1);
    __nv_bfloat162 p = {h0, h1};
    return *(uint32_t*)&p;
}
__device__ __forceinline__ uint32_t pack_bf16(float x0, float x1) {
    __nv_bfloat162 p = {__float2bfloat16(x0), __float2bfloat16(x1)};
    return *(uint32_t*)&p;
}

// ---------------------------------------------------------------------------
// RoPE table
// ---------------------------------------------------------------------------
__global__ __launch_bounds__(256) void rope_table_kernel() {
    int i = blockIdx.x * 256 + threadIdx.x;   // 4096
    int p = i >> 4, j = i & 15;
    const float CEXP = 0.830482023721841f;    // log2(10000)/16
    float inv = exp2f(-(float)j * CEXP);
    float sn, cs;
    sincosf((float)p * inv, &sn, &cs);
    g_rope[i] = make_float2(cs, sn);
}

// ---------------------------------------------------------------------------
// Tiled transpose permutes
// ---------------------------------------------------------------------------
__global__ __launch_bounds__(256) void permute_in_kernel(const float* __restrict__ x) {
    __shared__ float tile[32][33];
    const int b = blockIdx.z;
    const int tf0 = blockIdx.x * 32;
    const int d0 = blockIdx.y * 32;
    const int tx = threadIdx.x, ty = threadIdx.y;
    #pragma unroll
    for (int i = 0; i < 4; i++)
        tile[ty + 8 * i][tx] = x[((size_t)(b * 256 + d0 + ty + 8 * i) * 16384) + tf0 + tx];
    __syncthreads();
    #pragma unroll
    for (int i = 0; i < 4; i++)
        g_X[((size_t)(b * 16384 + tf0 + ty + 8 * i)) * 256 + d0 + tx] = tile[tx][ty + 8 * i];
}

__global__ __launch_bounds__(256) void permute_out_kernel(float* __restrict__ out) {
    __shared__ float tile[32][33];
    const int b = blockIdx.z;
    const int d0 = blockIdx.x * 32;
    const int tf0 = blockIdx.y * 32;
    const int tx = threadIdx.x, ty = threadIdx.y;
    #pragma unroll
    for (int i = 0; i < 4; i++)
        tile[ty + 8 * i][tx] = g_QKV[((size_t)(b * 16384 + tf0 + ty + 8 * i)) * 256 + d0 + tx];
    __syncthreads();
    #pragma unroll
    for (int i = 0; i < 4; i++)
        out[((size_t)(b * 256 + d0 + ty + 8 * i) * 16384) + tf0 + tx] = tile[tx][ty + 8 * i];
}

// ---------------------------------------------------------------------------
// TF32 GEMM with 2-stage smem double buffering.
// ---------------------------------------------------------------------------
__global__ __launch_bounds__(256) void tf32_gemm_kernel(
    const float* __restrict__ A, const float* __restrict__ B, float* __restrict__ C,
    int M, int N, int K)
{
    extern __shared__ float smg[];
    float* Asm = smg;
    float* Bsm = smg + 2 * 128 * 36;

    const int tid = threadIdx.x;
    const int wid = tid >> 5;
    const int lane = tid & 31;
    const int tq = lane >> 2;
    const int tr = lane & 3;
    const int warp_m = (wid & 1) * 64;
    const int warp_n = (wid >> 1) * 32;
    const int bx = blockIdx.x * 128;
    const int by = blockIdx.y * 128;

    float acc[4][4][4];
    #pragma unroll
    for (int i = 0; i < 4; i++)
        #pragma unroll
        for (int j = 0; j < 4; j++)
            #pragma unroll
            for (int r = 0; r < 4; r++) acc[i][j][r] = 0.0f;

    const int am = tid >> 3;
    const int ak = (tid & 7) * 4;
    const int bk = tid >> 5;
    const int bn = (tid & 31) * 4;

    const float* Ag = A + (size_t)(by + am) * K + ak;
    const float* Bg = B + (size_t)bk * N + bx + bn;

    float4 aP[4], bP[4];
    #pragma unroll
    for (int it = 0; it < 4; it++) {
        aP[it] = *(const float4*)(Ag + (size_t)(32 * it) * K);
        bP[it] = *(const float4*)(Bg + (size_t)(8 * it) * N);
    }
    #pragma unroll
    for (int it = 0; it < 4; it++) {
        float4 a = aP[it];
        *(float4*)&Asm[(am + 32 * it) * 36 + ak] =
            make_float4(tf32r(a.x), tf32r(a.y), tf32r(a.z), tf32r(a.w));
        float4 b = bP[it];
        *(float4*)&Bsm[(bk + 8 * it) * 136 + bn] =
            make_float4(tf32r(b.x), tf32r(b.y), tf32r(b.z), tf32r(b.w));
    }
    __syncthreads();

    const int ntiles = K >> 5;
    for (int kt = 0; kt < ntiles; kt++) {
        const int cur = kt & 1;
        const float* As = Asm + cur * 128 * 36;
        const float* Bs = Bsm + cur * 32 * 136;

        if (kt + 1 < ntiles) {
            const int ko = (kt + 1) * 32;
            #pragma unroll
            for (int it = 0; it < 4; it++) {
                aP[it] = *(const float4*)(Ag + (size_t)(32 * it) * K + ko);
                bP[it] = *(const float4*)(Bg + (size_t)(ko + 8 * it) * N);
            }
        }

        #pragma unroll
        for (int c = 0; c < 4; c++) {
            const int ks = c * 8;
            uint32_t a[4][4], b[4][2];
            #pragma unroll
            for (int i = 0; i < 4; i++) {
                int row = warp_m + i * 16 + tq;
                a[i][0] = __float_as_uint(As[row * 36 + ks + tr]);
                a[i][1] = __float_as_uint(As[(row + 8) * 36 + ks + tr]);
                a[i][2] = __float_as_uint(As[row * 36 + ks + tr + 4]);
                a[i][3] = __float_as_uint(As[(row + 8) * 36 + ks + tr + 4]);
            }
            #pragma unroll
            for (int j = 0; j < 4; j++) {
                int col = warp_n + j * 8 + tq;
                b[j][0] = __float_as_uint(Bs[(ks + tr) * 136 + col]);
                b[j][1] = __float_as_uint(Bs[(ks + tr + 4) * 136 + col]);
            }
            #pragma unroll
            for (int i = 0; i < 4; i++)
                #pragma unroll
                for (int j = 0; j < 4; j++)
                    mma_tf32(acc[i][j], a[i], b[j]);
        }

        if (kt + 1 < ntiles) {
            float* An = Asm + (cur ^ 1) * 128 * 36;
            float* Bn = Bsm + (cur ^ 1) * 32 * 136;
            #pragma unroll
            for (int it = 0; it < 4; it++) {
                float4 a = aP[it];
                *(float4*)&An[(am + 32 * it) * 36 + ak] =
                    make_float4(tf32r(a.x), tf32r(a.y), tf32r(a.z), tf32r(a.w));
                float4 b = bP[it];
                *(float4*)&Bn[(bk + 8 * it) * 136 + bn] =
                    make_float4(tf32r(b.x), tf32r(b.y), tf32r(b.z), tf32r(b.w));
            }
        }
        __syncthreads();
    }

    #pragma unroll
    for (int i = 0; i < 4; i++) {
        int row0 = by + warp_m + i * 16 + tq;
        #pragma unroll
        for (int j = 0; j < 4; j++) {
            int col0 = bx + warp_n + j * 8 + 2 * tr;
            *(float2*)&C[(size_t)row0 * N + col0] = make_float2(acc[i][j][0], acc[i][j][1]);
            *(float2*)&C[(size_t)(row0 + 8) * N + col0] = make_float2(acc[i][j][2], acc[i][j][3]);
        }
    }
}

// ---------------------------------------------------------------------------
// Token index per stage.
// ---------------------------------------------------------------------------
template <int STAGE>
__device__ __forceinline__ int tok_of(int g, int p) {
    if (STAGE == 1) {
        int b = g >> 6, f = g & 63;
        return (b * 256 + p) * 64 + f;
    } else if (STAGE == 2) {
        return g * 64 + p;
    } else {
        int b = g >> 8, rem = g & 255;
        int i = rem >> 3, jf = rem & 7;
        int t = i * 8 + (p >> 3);
        int f = jf * 8 + (p & 7);
        return (b * 256 + t) * 64 + f;
    }
}

// ---------------------------------------------------------------------------
// Flash attention: scores via packed bf16-split m16n8k16 (3-term), PV tf32.
// smem per head (uint32 units): Khi[S][20] Klo[S][20] Vt[32][S+4]
//                               Qhi[QR][20] Qlo[QR][20]; then Pbuf[8][16][36].
// Pad 20 half2/row -> fragment banks (tq*20+tr) mod 32 all distinct.
// ---------------------------------------------------------------------------
template <int STAGE, int S, int HPB>
__global__ __launch_bounds__(256) void attn_tc_kernel(const float* __restrict__ qkv) {
    constexpr int QR = (HPB == 1) ? 128 : S;
    constexpr int OFF_KLO = S * 20;
    constexpr int OFF_V   = 2 * S * 20;
    constexpr int OFF_QHI = OFF_V + 32 * (S + 4);
    constexpr int OFF_QLO = OFF_QHI + QR * 20;
    constexpr int HS = OFF_QLO + QR * 20;
    extern __shared__ float sm[];
    uint32_t* smu = (uint32_t*)sm;
    float* Pbuf = sm + HPB * HS;

    const int g = blockIdx.x;
    const int tid = threadIdx.x;
    const int w = tid >> 5;
    const int lane = tid & 31;
    const int tq = lane >> 2;
    const int tr = lane & 3;

    const int hh = (HPB == 1) ? 0 : (w >> 2);
    const int h = blockIdx.y * HPB + hh;
    const int m_base = (HPB == 1) ? (w * 16) : ((w & 3) * 16);
    const int qoff = (HPB == 1) ? ((int)blockIdx.z * 128) : 0;

    const float SCALE = 0.17677669529663687f;   // 1/sqrt(32)

    // ---- K loader: RoPE -> bf16 hi/lo packed pairs ----
    for (int idx = tid; idx < HPB * S * 16; idx += 256) {
        int hl = idx / (S * 16);
        int rem = idx - hl * S * 16;
        int k = rem >> 4, j = rem & 15;
        int tk = tok_of<STAGE>(g, k);
        const float* bp = qkv + (size_t)tk * 768 + 256 + (blockIdx.y * HPB + hl) * 32;
        float x0 = bp[2 * j], x1 = bp[2 * j + 1];
        float2 cssn = g_rope[k * 16 + j];
        float k0 = x0 * cssn.x - x1 * cssn.y;
        float k1 = x1 * cssn.x + x0 * cssn.y;
        float r0, r1;
        uint32_t* Khi = smu + hl * HS;
        Khi[k * 20 + j] = pack_bf16_hi(k0, k1, r0, r1);
        Khi[OFF_KLO + k * 20 + j] = pack_bf16(r0, r1);
    }
    // ---- Q loader: RoPE + scale -> bf16 hi/lo ----
    for (int idx = tid; idx < HPB * QR * 16; idx += 256) {
        int hl = idx / (QR * 16);
        int rem = idx - hl * QR * 16;
        int r = rem >> 4, j = rem & 15;
        int p = qoff + r;
        int tk = tok_of<STAGE>(g, p);
        const float* bp = qkv + (size_t)tk * 768 + (blockIdx.y * HPB + hl) * 32;
        float x0 = bp[2 * j], x1 = bp[2 * j + 1];
        float2 cssn = g_rope[p * 16 + j];
        float q0 = (x0 * cssn.x - x1 * cssn.y) * SCALE;
        float q1 = (x1 * cssn.x + x0 * cssn.y) * SCALE;
        float r0, r1;
        uint32_t* base = smu + hl * HS;
        base[OFF_QHI + r * 20 + j] = pack_bf16_hi(q0, q1, r0, r1);
        base[OFF_QLO + r * 20 + j] = pack_bf16(r0, r1);
    }
    // ---- V loader (transposed, tf32-rounded fp32) ----
    for (int idx = tid; idx < HPB * S * 32; idx += 256) {
        int hl = idx / (S * 32);
        int rem = idx - hl * S * 32;
        int k = rem >> 5, d = rem & 31;
        float v = qkv[(size_t)tok_of<STAGE>(g, k) * 768 + 512 + (blockIdx.y * HPB + hl) * 32 + d];
        (sm + hl * HS + OFF_V)[d * (S + 4) + k] = tf32r(v);
    }
    __syncthreads();

    const uint32_t* Khi = smu + hh * HS;
    const uint32_t* Klo = Khi + OFF_KLO;
    const float* Vt = (const float*)(Khi + OFF_V);
    const uint32_t* Qhi = Khi + OFF_QHI;
    const uint32_t* Qlo = Khi + OFF_QLO;
    float* Pw = Pbuf + w * 16 * 36;

    // Q fragments (2 k16 groups), held in regs
    uint32_t qh[2][4], ql[2][4];
    #pragma unroll
    for (int kt = 0; kt < 2; kt++) {
        int r0 = (m_base + tq) * 20 + kt * 8 + tr;
        int r1 = (m_base + tq + 8) * 20 + kt * 8 + tr;
        qh[kt][0] = Qhi[r0];     qh[kt][1] = Qhi[r1];
        qh[kt][2] = Qhi[r0 + 4]; qh[kt][3] = Qhi[r1 + 4];
        ql[kt][0] = Qlo[r0];     ql[kt][1] = Qlo[r1];
        ql[kt][2] = Qlo[r0 + 4]; ql[kt][3] = Qlo[r1 + 4];
    }

    float co[4][4];
    #pragma unroll
    for (int i = 0; i < 4; i++)
        #pragma unroll
        for (int j = 0; j < 4; j++) co[i][j] = 0.0f;
    float mrun0 = -1e30f, mrun1 = -1e30f, lrun0 = 0.0f, lrun1 = 0.0f;

    for (int j0 = 0; j0 < S; j0 += 32) {
        // --- scores: 16 x 32, bf16 3-term split, independent accumulators ---
        float sc[4][4];
        #pragma unroll
        for (int nt = 0; nt < 4; nt++) {
            const uint32_t* Krh = Khi + (j0 + nt * 8 + tq) * 20;
            const uint32_t* Krl = Klo + (j0 + nt * 8 + tq) * 20;
            float c0[4] = {0, 0, 0, 0}, c1[4] = {0, 0, 0, 0}, c2[4] = {0, 0, 0, 0};
            #pragma unroll
            for (int kt = 0; kt < 2; kt++) {
                uint32_t bh[2] = {Krh[kt * 8 + tr], Krh[kt * 8 + tr + 4]};
                uint32_t bl[2] = {Krl[kt * 8 + tr], Krl[kt * 8 + tr + 4]};
                mma_bf16(c0, qh[kt], bh);
                mma_bf16(c1, ql[kt], bh);
                mma_bf16(c2, qh[kt], bl);
            }
            #pragma unroll
            for (int r = 0; r < 4; r++) sc[nt][r] = c0[r] + c1[r] + c2[r];
        }

        // --- online softmax ---
        float mx0 = -1e30f, mx1 = -1e30f;
        #pragma unroll
        for (int nt = 0; nt < 4; nt++) {
            mx0 = fmaxf(mx0, fmaxf(sc[nt][0], sc[nt][1]));
            mx1 = fmaxf(mx1, fmaxf(sc[nt][2], sc[nt][3]));
        }
        mx0 = fmaxf(mx0, __shfl_xor_sync(0xFFFFFFFFu, mx0, 1));
        mx0 = fmaxf(mx0, __shfl_xor_sync(0xFFFFFFFFu, mx0, 2));
        mx1 = fmaxf(mx1, __shfl_xor_sync(0xFFFFFFFFu, mx1, 1));
        mx1 = fmaxf(mx1, __shfl_xor_sync(0xFFFFFFFFu, mx1, 2));
        float mn0 = fmaxf(mrun0, mx0), mn1 = fmaxf(mrun1, mx1);
        float esc0 = __expf(mrun0 - mn0), esc1 = __expf(mrun1 - mn1);
        float s0 = 0.0f, s1 = 0.0f;
        #pragma unroll
        for (int nt = 0; nt < 4; nt++) {
            float p0 = __expf(sc[nt][0] - mn0);
            float p1 = __expf(sc[nt][1] - mn0);
            float p2 = __expf(sc[nt][2] - mn1);
            float p3 = __expf(sc[nt][3] - mn1);
            s0 += p0 + p1;
            s1 += p2 + p3;
            *(float2*)&Pw[tq * 36 + nt * 8 + 2 * tr] = make_float2(tf32r(p0), tf32r(p1));
            *(float2*)&Pw[(tq + 8) * 36 + nt * 8 + 2 * tr] = make_float2(tf32r(p2), tf32r(p3));
        }
        s0 += __shfl_xor_sync(0xFFFFFFFFu, s0, 1);
        s0 += __shfl_xor_sync(0xFFFFFFFFu, s0, 2);
        s1 += __shfl_xor_sync(0xFFFFFFFFu, s1, 1);
        s1 += __shfl_xor_sync(0xFFFFFFFFu, s1, 2);
        lrun0 = lrun0 * esc0 + s0;
        lrun1 = lrun1 * esc1 + s1;
        mrun0 = mn0; mrun1 = mn1;
        #pragma unroll
        for (int nt2 = 0; nt2 < 4; nt2++) {
            co[nt2][0] *= esc0; co[nt2][1] *= esc0;
            co[nt2][2] *= esc1; co[nt2][3] *= esc1;
        }
        __syncwarp();

        // --- PV: O += P(16x32) @ V(32x32), tf32 ---
        #pragma unroll
        for (int kt2 = 0; kt2 < 4; kt2++) {
            int kc = kt2 * 8 + tr;
            uint32_t a[4];
            a[0] = __float_as_uint(Pw[tq * 36 + kc]);
            a[1] = __float_as_uint(Pw[(tq + 8) * 36 + kc]);
            a[2] = __float_as_uint(Pw[tq * 36 + kc + 4]);
            a[3] = __float_as_uint(Pw[(tq + 8) * 36 + kc + 4]);
            #pragma unroll
            for (int nt2 = 0; nt2 < 4; nt2++) {
                const float* vrow = Vt + (nt2 * 8 + tq) * (S + 4) + j0 + kc;
                uint32_t b[2] = {__float_as_uint(vrow[0]), __float_as_uint(vrow[4])};
                mma_tf32(co[nt2], a, b);
            }
        }
        __syncwarp();
    }

    float inv0 = 1.0f / lrun0, inv1 = 1.0f / lrun1;
    int p0r = qoff + m_base + tq;
    size_t o0 = (size_t)tok_of<STAGE>(g, p0r) * 256 + h * 32;
    size_t o1 = (size_t)tok_of<STAGE>(g, p0r + 8) * 256 + h * 32;
    #pragma unroll
    for (int nt2 = 0; nt2 < 4; nt2++) {
        int cc = nt2 * 8 + 2 * tr;
        *(float2*)&g_X[o0 + cc] = make_float2(co[nt2][0] * inv0, co[nt2][1] * inv0);
        *(float2*)&g_X[o1 + cc] = make_float2(co[nt2][2] * inv1, co[nt2][3] * inv1);
    }
}

// ---------------------------------------------------------------------------
extern "C" void kernel_launch(void* const* d_in, const int* in_sizes, int n_in,
                              void* d_out, int out_size) {
    const float* x  = (const float*)d_in[0];
    const float* W1 = (const float*)d_in[1];
    const float* W2 = (const float*)d_in[2];
    const float* W3 = (const float*)d_in[3];
    const float* Wp = (const float*)d_in[4];
    float* out = (float*)d_out;

    float* Xp;   cudaGetSymbolAddress((void**)&Xp,   g_X);
    float* QKVp; cudaGetSymbolAddress((void**)&QKVp, g_QKV);

    const int SMEMG = (2 * 128 * 36 + 2 * 32 * 136) * 4;   // 71680
    // stage1: (2*256*20 + 32*260 + 2*128*20 + 8*16*36)*4 = 113152
    // stage2/3: (2*(2*64*20 + 32*68 + 2*64*20) + 8*16*36)*4 = 76800
    const int SMEM1 = 113152;
    const int SMEM2 = 76800;

    cudaFuncSetAttribute(tf32_gemm_kernel,
                         cudaFuncAttributeMaxDynamicSharedMemorySize, SMEMG);
    cudaFuncSetAttribute(attn_tc_kernel<1, 256, 1>,
                         cudaFuncAttributeMaxDynamicSharedMemorySize, SMEM1);
    cudaFuncSetAttribute(attn_tc_kernel<2, 64, 2>,
                         cudaFuncAttributeMaxDynamicSharedMemorySize, SMEM2);
    cudaFuncSetAttribute(attn_tc_kernel<3, 64, 2>,
                         cudaFuncAttributeMaxDynamicSharedMemorySize, SMEM2);

    rope_table_kernel<<<16, 256>>>();
    permute_in_kernel<<<dim3(512, 8, 4), dim3(32, 8)>>>(x);

    // Stage 1: time-axis attention (S=256)
    tf32_gemm_kernel<<<dim3(6, 512), 256, SMEMG>>>(Xp, W1, QKVp, NT, 768, 256);
    attn_tc_kernel<1, 256, 1><<<dim3(256, 8, 2), 256, SMEM1>>>(QKVp);

    // Stage 2: freq-axis attention (S=64)
    tf32_gemm_kernel<<<dim3(6, 512), 256, SMEMG>>>(Xp, W2, QKVp, NT, 768, 256);
    attn_tc_kernel<2, 64, 2><<<dim3(1024, 4, 1), 256, SMEM2>>>(QKVp);

    // Stage 3: windowed attention (S=64)
    tf32_gemm_kernel<<<dim3(6, 512), 256, SMEMG>>>(Xp, W3, QKVp, NT, 768, 256);
    attn_tc_kernel<3, 64, 2><<<dim3(1024, 4, 1), 256, SMEM2>>>(QKVp);

    // Projection
    tf32_gemm_kernel<<<dim3(2, 512), 256, SMEMG>>>(Xp, Wp, QKVp, NT, 256, 256);

    permute_out_kernel<<<dim3(8, 512, 4), dim3(32, 8)>>>(out);
}

// round 7
// speedup vs baseline: 2.6862x; 1.1850x over previous
#include <cuda_runtime.h>
#include <cuda_bf16.h>
#include <math.h>
#include <stdint.h>

// Problem constants
#define BB 4
#define DD 256
#define TT 256
#define FF 64
#define HH 8
#define HD 32
#define NT (BB*TT*FF)          // 65536 tokens

// Scratch (no allocations allowed -> device globals)
__device__ float g_X[(size_t)NT * DD];        // canonical token-major activations
__device__ float g_QKV[(size_t)NT * 3 * DD];  // qkv / reused as proj output
__device__ float2 g_rope[256 * 16];           // cos/sin table [pos][j]

// ---------------------------------------------------------------------------
// TF32 / bf16 helpers
// ---------------------------------------------------------------------------
__device__ __forceinline__ uint32_t f2tf32(float x) {
    uint32_t r;
    asm("cvt.rna.tf32.f32 %0, %1;" : "=r"(r) : "f"(x));
    return r;
}
__device__ __forceinline__ float tf32r(float x) { return __uint_as_float(f2tf32(x)); }

__device__ __forceinline__ void mma_tf32(float* c, const uint32_t* a, const uint32_t* b) {
    asm volatile(
        "mma.sync.aligned.m16n8k8.row.col.f32.tf32.tf32.f32 "
        "{%0,%1,%2,%3}, {%4,%5,%6,%7}, {%8,%9}, {%0,%1,%2,%3};"
        : "+f"(c[0]), "+f"(c[1]), "+f"(c[2]), "+f"(c[3])
        : "r"(a[0]), "r"(a[1]), "r"(a[2]), "r"(a[3]), "r"(b[0]), "r"(b[1]));
}

__device__ __forceinline__ void mma_bf16(float* c, const uint32_t* a, const uint32_t* b) {
    asm volatile(
        "mma.sync.aligned.m16n8k16.row.col.f32.bf16.bf16.f32 "
        "{%0,%1,%2,%3}, {%4,%5,%6,%7}, {%8,%9}, {%0,%1,%2,%3};"
        : "+f"(c[0]), "+f"(c[1]), "+f"(c[2]), "+f"(c[3])
        : "r"(a[0]), "r"(a[1]), "r"(a[2]), "r"(a[3]), "r"(b[0]), "r"(b[1]));
}

__device__ __forceinline__ uint32_t pack_bf16_hi(float x0, float x1, float& r0, float& r1) {
    __nv_bfloat16 h0 = __float2bfloat16(x0);
    __nv_bfloat16 h1 = __float2bfloat16(x1);
    r0 = x0 - __bfloat162float(h0);
    r1 = x1 - __bfloat162float(h1);
    __nv_bfloat162 p = {h0, h1};
    return *(uint32_t*)&p;
}
__device__ __forceinline__ uint32_t pack_bf16(float x0, float x1) {
    __nv_bfloat162 p = {__float2bfloat16(x0), __float2bfloat16(x1)};
    return *(uint32_t*)&p;
}

// ---------------------------------------------------------------------------
// RoPE table
// ---------------------------------------------------------------------------
__global__ __launch_bounds__(256) void rope_table_kernel() {
    int i = blockIdx.x * 256 + threadIdx.x;   // 4096
    int p = i >> 4, j = i & 15;
    const float CEXP = 0.830482023721841f;    // log2(10000)/16
    float inv = exp2f(-(float)j * CEXP);
    float sn, cs;
    sincosf((float)p * inv, &sn, &cs);
    g_rope[i] = make_float2(cs, sn);
}

// ---------------------------------------------------------------------------
// Tiled transpose permutes
// ---------------------------------------------------------------------------
__global__ __launch_bounds__(256) void permute_in_kernel(const float* __restrict__ x) {
    __shared__ float tile[32][33];
    const int b = blockIdx.z;
    const int tf0 = blockIdx.x * 32;
    const int d0 = blockIdx.y * 32;
    const int tx = threadIdx.x, ty = threadIdx.y;
    #pragma unroll
    for (int i = 0; i < 4; i++)
        tile[ty + 8 * i][tx] = x[((size_t)(b * 256 + d0 + ty + 8 * i) * 16384) + tf0 + tx];
    __syncthreads();
    #pragma unroll
    for (int i = 0; i < 4; i++)
        g_X[((size_t)(b * 16384 + tf0 + ty + 8 * i)) * 256 + d0 + tx] = tile[tx][ty + 8 * i];
}

__global__ __launch_bounds__(256) void permute_out_kernel(float* __restrict__ out) {
    __shared__ float tile[32][33];
    const int b = blockIdx.z;
    const int d0 = blockIdx.x * 32;
    const int tf0 = blockIdx.y * 32;
    const int tx = threadIdx.x, ty = threadIdx.y;
    #pragma unroll
    for (int i = 0; i < 4; i++)
        tile[ty + 8 * i][tx] = g_QKV[((size_t)(b * 16384 + tf0 + ty + 8 * i)) * 256 + d0 + tx];
    __syncthreads();
    #pragma unroll
    for (int i = 0; i < 4; i++)
        out[((size_t)(b * 256 + d0 + ty + 8 * i) * 16384) + tf0 + tx] = tile[tx][ty + 8 * i];
}

// ---------------------------------------------------------------------------
// TF32 GEMM with 2-stage smem double buffering (unchanged).
// ---------------------------------------------------------------------------
__global__ __launch_bounds__(256) void tf32_gemm_kernel(
    const float* __restrict__ A, const float* __restrict__ B, float* __restrict__ C,
    int M, int N, int K)
{
    extern __shared__ float smg[];
    float* Asm = smg;
    float* Bsm = smg + 2 * 128 * 36;

    const int tid = threadIdx.x;
    const int wid = tid >> 5;
    const int lane = tid & 31;
    const int tq = lane >> 2;
    const int tr = lane & 3;
    const int warp_m = (wid & 1) * 64;
    const int warp_n = (wid >> 1) * 32;
    const int bx = blockIdx.x * 128;
    const int by = blockIdx.y * 128;

    float acc[4][4][4];
    #pragma unroll
    for (int i = 0; i < 4; i++)
        #pragma unroll
        for (int j = 0; j < 4; j++)
            #pragma unroll
            for (int r = 0; r < 4; r++) acc[i][j][r] = 0.0f;

    const int am = tid >> 3;
    const int ak = (tid & 7) * 4;
    const int bk = tid >> 5;
    const int bn = (tid & 31) * 4;

    const float* Ag = A + (size_t)(by + am) * K + ak;
    const float* Bg = B + (size_t)bk * N + bx + bn;

    float4 aP[4], bP[4];
    #pragma unroll
    for (int it = 0; it < 4; it++) {
        aP[it] = *(const float4*)(Ag + (size_t)(32 * it) * K);
        bP[it] = *(const float4*)(Bg + (size_t)(8 * it) * N);
    }
    #pragma unroll
    for (int it = 0; it < 4; it++) {
        float4 a = aP[it];
        *(float4*)&Asm[(am + 32 * it) * 36 + ak] =
            make_float4(tf32r(a.x), tf32r(a.y), tf32r(a.z), tf32r(a.w));
        float4 b = bP[it];
        *(float4*)&Bsm[(bk + 8 * it) * 136 + bn] =
            make_float4(tf32r(b.x), tf32r(b.y), tf32r(b.z), tf32r(b.w));
    }
    __syncthreads();

    const int ntiles = K >> 5;
    for (int kt = 0; kt < ntiles; kt++) {
        const int cur = kt & 1;
        const float* As = Asm + cur * 128 * 36;
        const float* Bs = Bsm + cur * 32 * 136;

        if (kt + 1 < ntiles) {
            const int ko = (kt + 1) * 32;
            #pragma unroll
            for (int it = 0; it < 4; it++) {
                aP[it] = *(const float4*)(Ag + (size_t)(32 * it) * K + ko);
                bP[it] = *(const float4*)(Bg + (size_t)(ko + 8 * it) * N);
            }
        }

        #pragma unroll
        for (int c = 0; c < 4; c++) {
            const int ks = c * 8;
            uint32_t a[4][4], b[4][2];
            #pragma unroll
            for (int i = 0; i < 4; i++) {
                int row = warp_m + i * 16 + tq;
                a[i][0] = __float_as_uint(As[row * 36 + ks + tr]);
                a[i][1] = __float_as_uint(As[(row + 8) * 36 + ks + tr]);
                a[i][2] = __float_as_uint(As[row * 36 + ks + tr + 4]);
                a[i][3] = __float_as_uint(As[(row + 8) * 36 + ks + tr + 4]);
            }
            #pragma unroll
            for (int j = 0; j < 4; j++) {
                int col = warp_n + j * 8 + tq;
                b[j][0] = __float_as_uint(Bs[(ks + tr) * 136 + col]);
                b[j][1] = __float_as_uint(Bs[(ks + tr + 4) * 136 + col]);
            }
            #pragma unroll
            for (int i = 0; i < 4; i++)
                #pragma unroll
                for (int j = 0; j < 4; j++)
                    mma_tf32(acc[i][j], a[i], b[j]);
        }

        if (kt + 1 < ntiles) {
            float* An = Asm + (cur ^ 1) * 128 * 36;
            float* Bn = Bsm + (cur ^ 1) * 32 * 136;
            #pragma unroll
            for (int it = 0; it < 4; it++) {
                float4 a = aP[it];
                *(float4*)&An[(am + 32 * it) * 36 + ak] =
                    make_float4(tf32r(a.x), tf32r(a.y), tf32r(a.z), tf32r(a.w));
                float4 b = bP[it];
                *(float4*)&Bn[(bk + 8 * it) * 136 + bn] =
                    make_float4(tf32r(b.x), tf32r(b.y), tf32r(b.z), tf32r(b.w));
            }
        }
        __syncthreads();
    }

    #pragma unroll
    for (int i = 0; i < 4; i++) {
        int row0 = by + warp_m + i * 16 + tq;
        #pragma unroll
        for (int j = 0; j < 4; j++) {
            int col0 = bx + warp_n + j * 8 + 2 * tr;
            *(float2*)&C[(size_t)row0 * N + col0] = make_float2(acc[i][j][0], acc[i][j][1]);
            *(float2*)&C[(size_t)(row0 + 8) * N + col0] = make_float2(acc[i][j][2], acc[i][j][3]);
        }
    }
}

// ---------------------------------------------------------------------------
// Token index per stage.
// ---------------------------------------------------------------------------
template <int STAGE>
__device__ __forceinline__ int tok_of(int g, int p) {
    if (STAGE == 1) {
        int b = g >> 6, f = g & 63;
        return (b * 256 + p) * 64 + f;
    } else if (STAGE == 2) {
        return g * 64 + p;
    } else {
        int b = g >> 8, rem = g & 255;
        int i = rem >> 3, jf = rem & 7;
        int t = i * 8 + (p >> 3);
        int f = jf * 8 + (p & 7);
        return (b * 256 + t) * 64 + f;
    }
}

// ---------------------------------------------------------------------------
// Q fragments: bf16-split, built directly from gmem (no smem staging).
// Frag regs: a[0]=row0/pairA a[1]=row1/pairA a[2]=row0/pairB a[3]=row1/pairB.
// ---------------------------------------------------------------------------
template <int STAGE>
__device__ __forceinline__ void load_q_frags(
    const float* __restrict__ qkv, int g, int h, int p0,
    int tr, uint32_t qh[2][4], uint32_t ql[2][4])
{
    const float SCALE = 0.17677669529663687f;   // 1/sqrt(32)
    #pragma unroll
    for (int kt = 0; kt < 2; kt++)
        #pragma unroll
        for (int hv = 0; hv < 2; hv++) {
            int j = kt * 8 + tr + 4 * hv;
            #pragma unroll
            for (int rr = 0; rr < 2; rr++) {
                int p = p0 + rr * 8;
                int tok = tok_of<STAGE>(g, p);
                float2 q = *(const float2*)(qkv + (size_t)tok * 768 + h * 32 + 2 * j);
                float2 cs = g_rope[p * 16 + j];
                float q0 = (q.x * cs.x - q.y * cs.y) * SCALE;
                float q1 = (q.y * cs.x + q.x * cs.y) * SCALE;
                float r0, r1;
                qh[kt][hv * 2 + rr] = pack_bf16_hi(q0, q1, r0, r1);
                ql[kt][hv * 2 + rr] = pack_bf16(r0, r1);
            }
        }
}

// ---------------------------------------------------------------------------
// Stage-1 attention: S=256, streamed KV (32-key double-buffered chunks).
// Block: (g, h, q-slab of 128). 8 warps x 16 q rows. Static smem 37.9KB.
// ---------------------------------------------------------------------------
__global__ __launch_bounds__(256, 3) void attn1_kernel(const float* __restrict__ qkv) {
    constexpr int BUF = 2432;              // u32 per KV buffer
    __shared__ uint32_t smu[2 * BUF + 8 * 576];
    float* smf = (float*)smu;

    const int g = blockIdx.x;              // b*64+f
    const int h = blockIdx.y;
    const int qoff = blockIdx.z * 128;
    const int tid = threadIdx.x;
    const int w = tid >> 5, lane = tid & 31, tq = lane >> 2, tr = lane & 3;
    const int m_base = w * 16;

    // Q fragments in regs
    uint32_t qh[2][4], ql[2][4];
    load_q_frags<1>(qkv, g, h, qoff + m_base + tq, tr, qh, ql);

    // K/V chunk prefetch state
    const int kj = tid & 15;               // K pair index for this thread
    const int kk0 = tid >> 4;              // K row base (r*16 + kk0)
    const int vd = tid & 31;               // V dim
    const int vk0 = tid >> 5;              // V row base (r*8 + vk0)
    float2 kx[2];
    float vx[4];

    auto load_chunk = [&](int c) {
        int kb = c * 32;
        #pragma unroll
        for (int r = 0; r < 2; r++) {
            int tok = tok_of<1>(g, kb + r * 16 + kk0);
            kx[r] = *(const float2*)(qkv + (size_t)tok * 768 + 256 + h * 32 + 2 * kj);
        }
        #pragma unroll
        for (int r = 0; r < 4; r++) {
            int tok = tok_of<1>(g, kb + r * 8 + vk0);
            vx[r] = qkv[(size_t)tok * 768 + 512 + h * 32 + vd];
        }
    };
    auto store_chunk = [&](int c, int base) {
        int kb = c * 32;
        #pragma unroll
        for (int r = 0; r < 2; r++) {
            int k = r * 16 + kk0;
            float2 cs = g_rope[(kb + k) * 16 + kj];
            float k0 = kx[r].x * cs.x - kx[r].y * cs.y;
            float k1 = kx[r].y * cs.x + kx[r].x * cs.y;
            float r0, r1;
            smu[base + k * 20 + kj] = pack_bf16_hi(k0, k1, r0, r1);
            smu[base + 640 + k * 20 + kj] = pack_bf16(r0, r1);
        }
        #pragma unroll
        for (int r = 0; r < 4; r++)
            smf[base + 1280 + vd * 36 + (r * 8 + vk0)] = tf32r(vx[r]);
    };

    load_chunk(0);
    store_chunk(0, 0);
    __syncthreads();

    float* Pw = smf + 2 * BUF + w * 576;
    float co[4][4];
    #pragma unroll
    for (int i = 0; i < 4; i++)
        #pragma unroll
        for (int j = 0; j < 4; j++) co[i][j] = 0.0f;
    float mrun0 = -1e30f, mrun1 = -1e30f, lrun0 = 0.0f, lrun1 = 0.0f;

    for (int c = 0; c < 8; c++) {
        const uint32_t* Khi = smu + (c & 1) * BUF;
        const uint32_t* Klo = Khi + 640;
        const float* Vt = (const float*)(Khi + 1280);

        if (c < 7) load_chunk(c + 1);

        // scores 16x32
        float sc[4][4];
        #pragma unroll
        for (int nt = 0; nt < 4; nt++) {
            const uint32_t* Krh = Khi + (nt * 8 + tq) * 20;
            const uint32_t* Krl = Klo + (nt * 8 + tq) * 20;
            float c0[4] = {0, 0, 0, 0}, c1[4] = {0, 0, 0, 0}, c2[4] = {0, 0, 0, 0};
            #pragma unroll
            for (int kt = 0; kt < 2; kt++) {
                uint32_t bh[2] = {Krh[kt * 8 + tr], Krh[kt * 8 + tr + 4]};
                uint32_t bl[2] = {Krl[kt * 8 + tr], Krl[kt * 8 + tr + 4]};
                mma_bf16(c0, qh[kt], bh);
                mma_bf16(c1, ql[kt], bh);
                mma_bf16(c2, qh[kt], bl);
            }
            #pragma unroll
            for (int r = 0; r < 4; r++) sc[nt][r] = c0[r] + c1[r] + c2[r];
        }

        // online softmax
        float mx0 = -1e30f, mx1 = -1e30f;
        #pragma unroll
        for (int nt = 0; nt < 4; nt++) {
            mx0 = fmaxf(mx0, fmaxf(sc[nt][0], sc[nt][1]));
            mx1 = fmaxf(mx1, fmaxf(sc[nt][2], sc[nt][3]));
        }
        mx0 = fmaxf(mx0, __shfl_xor_sync(0xFFFFFFFFu, mx0, 1));
        mx0 = fmaxf(mx0, __shfl_xor_sync(0xFFFFFFFFu, mx0, 2));
        mx1 = fmaxf(mx1, __shfl_xor_sync(0xFFFFFFFFu, mx1, 1));
        mx1 = fmaxf(mx1, __shfl_xor_sync(0xFFFFFFFFu, mx1, 2));
        float mn0 = fmaxf(mrun0, mx0), mn1 = fmaxf(mrun1, mx1);
        float esc0 = __expf(mrun0 - mn0), esc1 = __expf(mrun1 - mn1);
        float s0 = 0.0f, s1 = 0.0f;
        #pragma unroll
        for (int nt = 0; nt < 4; nt++) {
            float p0 = __expf(sc[nt][0] - mn0);
            float p1 = __expf(sc[nt][1] - mn0);
            float p2 = __expf(sc[nt][2] - mn1);
            float p3 = __expf(sc[nt][3] - mn1);
            s0 += p0 + p1;
            s1 += p2 + p3;
            *(float2*)&Pw[tq * 36 + nt * 8 + 2 * tr] = make_float2(tf32r(p0), tf32r(p1));
            *(float2*)&Pw[(tq + 8) * 36 + nt * 8 + 2 * tr] = make_float2(tf32r(p2), tf32r(p3));
        }
        s0 += __shfl_xor_sync(0xFFFFFFFFu, s0, 1);
        s0 += __shfl_xor_sync(0xFFFFFFFFu, s0, 2);
        s1 += __shfl_xor_sync(0xFFFFFFFFu, s1, 1);
        s1 += __shfl_xor_sync(0xFFFFFFFFu, s1, 2);
        lrun0 = lrun0 * esc0 + s0;
        lrun1 = lrun1 * esc1 + s1;
        mrun0 = mn0; mrun1 = mn1;
        #pragma unroll
        for (int nt2 = 0; nt2 < 4; nt2++) {
            co[nt2][0] *= esc0; co[nt2][1] *= esc0;
            co[nt2][2] *= esc1; co[nt2][3] *= esc1;
        }
        __syncwarp();

        // PV
        #pragma unroll
        for (int kt2 = 0; kt2 < 4; kt2++) {
            int kc = kt2 * 8 + tr;
            uint32_t a[4];
            a[0] = __float_as_uint(Pw[tq * 36 + kc]);
            a[1] = __float_as_uint(Pw[(tq + 8) * 36 + kc]);
            a[2] = __float_as_uint(Pw[tq * 36 + kc + 4]);
            a[3] = __float_as_uint(Pw[(tq + 8) * 36 + kc + 4]);
            #pragma unroll
            for (int nt2 = 0; nt2 < 4; nt2++) {
                const float* vrow = Vt + (nt2 * 8 + tq) * 36 + kc;
                uint32_t b[2] = {__float_as_uint(vrow[0]), __float_as_uint(vrow[4])};
                mma_tf32(co[nt2], a, b);
            }
        }
        __syncwarp();

        if (c < 7) store_chunk(c + 1, ((c + 1) & 1) * BUF);
        __syncthreads();
    }

    float inv0 = 1.0f / lrun0, inv1 = 1.0f / lrun1;
    int p0r = qoff + m_base + tq;
    size_t o0 = (size_t)tok_of<1>(g, p0r) * 256 + h * 32;
    size_t o1 = (size_t)tok_of<1>(g, p0r + 8) * 256 + h * 32;
    #pragma unroll
    for (int nt2 = 0; nt2 < 4; nt2++) {
        int cc = nt2 * 8 + 2 * tr;
        *(float2*)&g_X[o0 + cc] = make_float2(co[nt2][0] * inv0, co[nt2][1] * inv0);
        *(float2*)&g_X[o1 + cc] = make_float2(co[nt2][2] * inv1, co[nt2][3] * inv1);
    }
}

// ---------------------------------------------------------------------------
// Stage-2/3 attention: S=64, 2 heads per block, Q frags from gmem.
// smem per head: Khi[64][20] Klo[64][20] V[32][68]; then Pbuf 8x16x36.
// ---------------------------------------------------------------------------
template <int STAGE>
__global__ __launch_bounds__(256, 3) void attn64_kernel(const float* __restrict__ qkv) {
    constexpr int HS = 4736;               // u32 per head block
    extern __shared__ uint32_t smu2[];
    float* smf = (float*)smu2;

    const int g = blockIdx.x;
    const int tid = threadIdx.x;
    const int w = tid >> 5, lane = tid & 31, tq = lane >> 2, tr = lane & 3;
    const int hh = w >> 2;
    const int h = blockIdx.y * 2 + hh;
    const int m_base = (w & 3) * 16;

    // K loader: 2 heads x 64 rows x 16 pairs
    for (int idx = tid; idx < 2048; idx += 256) {
        int hl = idx >> 10, rem = idx & 1023;
        int k = rem >> 4, j = rem & 15;
        int tok = tok_of<STAGE>(g, k);
        const float* bp = qkv + (size_t)tok * 768 + 256 + (blockIdx.y * 2 + hl) * 32;
        float x0 = bp[2 * j], x1 = bp[2 * j + 1];
        float2 cs = g_rope[k * 16 + j];
        float k0 = x0 * cs.x - x1 * cs.y;
        float k1 = x1 * cs.x + x0 * cs.y;
        float r0, r1;
        int base = hl * HS;
        smu2[base + k * 20 + j] = pack_bf16_hi(k0, k1, r0, r1);
        smu2[base + 1280 + k * 20 + j] = pack_bf16(r0, r1);
    }
    // V loader: 2 heads x 64 rows x 32 dims (transposed)
    for (int idx = tid; idx < 4096; idx += 256) {
        int hl = idx >> 11, rem = idx & 2047;
        int k = rem >> 5, d = rem & 31;
        float v = qkv[(size_t)tok_of<STAGE>(g, k) * 768 + 512 + (blockIdx.y * 2 + hl) * 32 + d];
        smf[hl * HS + 2560 + d * 68 + k] = tf32r(v);
    }

    // Q fragments (no smem)
    uint32_t qh[2][4], ql[2][4];
    load_q_frags<STAGE>(qkv, g, h, m_base + tq, tr, qh, ql);
    __syncthreads();

    const uint32_t* KhiB = smu2 + hh * HS;
    const uint32_t* KloB = KhiB + 1280;
    const float* VtB = (const float*)(KhiB + 2560);
    float* Pw = smf + 2 * HS + w * 576;

    float co[4][4];
    #pragma unroll
    for (int i = 0; i < 4; i++)
        #pragma unroll
        for (int j = 0; j < 4; j++) co[i][j] = 0.0f;
    float mrun0 = -1e30f, mrun1 = -1e30f, lrun0 = 0.0f, lrun1 = 0.0f;

    #pragma unroll
    for (int j0 = 0; j0 < 64; j0 += 32) {
        float sc[4][4];
        #pragma unroll
        for (int nt = 0; nt < 4; nt++) {
            const uint32_t* Krh = KhiB + (j0 + nt * 8 + tq) * 20;
            const uint32_t* Krl = KloB + (j0 + nt * 8 + tq) * 20;
            float c0[4] = {0, 0, 0, 0}, c1[4] = {0, 0, 0, 0}, c2[4] = {0, 0, 0, 0};
            #pragma unroll
            for (int kt = 0; kt < 2; kt++) {
                uint32_t bh[2] = {Krh[kt * 8 + tr], Krh[kt * 8 + tr + 4]};
                uint32_t bl[2] = {Krl[kt * 8 + tr], Krl[kt * 8 + tr + 4]};
                mma_bf16(c0, qh[kt], bh);
                mma_bf16(c1, ql[kt], bh);
                mma_bf16(c2, qh[kt], bl);
            }
            #pragma unroll
            for (int r = 0; r < 4; r++) sc[nt][r] = c0[r] + c1[r] + c2[r];
        }

        float mx0 = -1e30f, mx1 = -1e30f;
        #pragma unroll
        for (int nt = 0; nt < 4; nt++) {
            mx0 = fmaxf(mx0, fmaxf(sc[nt][0], sc[nt][1]));
            mx1 = fmaxf(mx1, fmaxf(sc[nt][2], sc[nt][3]));
        }
        mx0 = fmaxf(mx0, __shfl_xor_sync(0xFFFFFFFFu, mx0, 1));
        mx0 = fmaxf(mx0, __shfl_xor_sync(0xFFFFFFFFu, mx0, 2));
        mx1 = fmaxf(mx1, __shfl_xor_sync(0xFFFFFFFFu, mx1, 1));
        mx1 = fmaxf(mx1, __shfl_xor_sync(0xFFFFFFFFu, mx1, 2));
        float mn0 = fmaxf(mrun0, mx0), mn1 = fmaxf(mrun1, mx1);
        float esc0 = __expf(mrun0 - mn0), esc1 = __expf(mrun1 - mn1);
        float s0 = 0.0f, s1 = 0.0f;
        #pragma unroll
        for (int nt = 0; nt < 4; nt++) {
            float p0 = __expf(sc[nt][0] - mn0);
            float p1 = __expf(sc[nt][1] - mn0);
            float p2 = __expf(sc[nt][2] - mn1);
            float p3 = __expf(sc[nt][3] - mn1);
            s0 += p0 + p1;
            s1 += p2 + p3;
            *(float2*)&Pw[tq * 36 + nt * 8 + 2 * tr] = make_float2(tf32r(p0), tf32r(p1));
            *(float2*)&Pw[(tq + 8) * 36 + nt * 8 + 2 * tr] = make_float2(tf32r(p2), tf32r(p3));
        }
        s0 += __shfl_xor_sync(0xFFFFFFFFu, s0, 1);
        s0 += __shfl_xor_sync(0xFFFFFFFFu, s0, 2);
        s1 += __shfl_xor_sync(0xFFFFFFFFu, s1, 1);
        s1 += __shfl_xor_sync(0xFFFFFFFFu, s1, 2);
        lrun0 = lrun0 * esc0 + s0;
        lrun1 = lrun1 * esc1 + s1;
        mrun0 = mn0; mrun1 = mn1;
        #pragma unroll
        for (int nt2 = 0; nt2 < 4; nt2++) {
            co[nt2][0] *= esc0; co[nt2][1] *= esc0;
            co[nt2][2] *= esc1; co[nt2][3] *= esc1;
        }
        __syncwarp();

        #pragma unroll
        for (int kt2 = 0; kt2 < 4; kt2++) {
            int kc = kt2 * 8 + tr;
            uint32_t a[4];
            a[0] = __float_as_uint(Pw[tq * 36 + kc]);
            a[1] = __float_as_uint(Pw[(tq + 8) * 36 + kc]);
            a[2] = __float_as_uint(Pw[tq * 36 + kc + 4]);
            a[3] = __float_as_uint(Pw[(tq + 8) * 36 + kc + 4]);
            #pragma unroll
            for (int nt2 = 0; nt2 < 4; nt2++) {
                const float* vrow = VtB + (nt2 * 8 + tq) * 68 + j0 + kc;
                uint32_t b[2] = {__float_as_uint(vrow[0]), __float_as_uint(vrow[4])};
                mma_tf32(co[nt2], a, b);
            }
        }
        __syncwarp();
    }

    float inv0 = 1.0f / lrun0, inv1 = 1.0f / lrun1;
    int p0r = m_base + tq;
    size_t o0 = (size_t)tok_of<STAGE>(g, p0r) * 256 + h * 32;
    size_t o1 = (size_t)tok_of<STAGE>(g, p0r + 8) * 256 + h * 32;
    #pragma unroll
    for (int nt2 = 0; nt2 < 4; nt2++) {
        int cc = nt2 * 8 + 2 * tr;
        *(float2*)&g_X[o0 + cc] = make_float2(co[nt2][0] * inv0, co[nt2][1] * inv0);
        *(float2*)&g_X[o1 + cc] = make_float2(co[nt2][2] * inv1, co[nt2][3] * inv1);
    }
}

// ---------------------------------------------------------------------------
extern "C" void kernel_launch(void* const* d_in, const int* in_sizes, int n_in,
                              void* d_out, int out_size) {
    const float* x  = (const float*)d_in[0];
    const float* W1 = (const float*)d_in[1];
    const float* W2 = (const float*)d_in[2];
    const float* W3 = (const float*)d_in[3];
    const float* Wp = (const float*)d_in[4];
    float* out = (float*)d_out;

    float* Xp;   cudaGetSymbolAddress((void**)&Xp,   g_X);
    float* QKVp; cudaGetSymbolAddress((void**)&QKVp, g_QKV);

    const int SMEMG = (2 * 128 * 36 + 2 * 32 * 136) * 4;   // 71680
    const int SMEM64 = (2 * 4736 + 8 * 576) * 4;           // 56320

    cudaFuncSetAttribute(tf32_gemm_kernel,
                         cudaFuncAttributeMaxDynamicSharedMemorySize, SMEMG);
    cudaFuncSetAttribute(attn64_kernel<2>,
                         cudaFuncAttributeMaxDynamicSharedMemorySize, SMEM64);
    cudaFuncSetAttribute(attn64_kernel<3>,
                         cudaFuncAttributeMaxDynamicSharedMemorySize, SMEM64);

    rope_table_kernel<<<16, 256>>>();
    permute_in_kernel<<<dim3(512, 8, 4), dim3(32, 8)>>>(x);

    // Stage 1: time-axis attention (S=256), streamed KV
    tf32_gemm_kernel<<<dim3(6, 512), 256, SMEMG>>>(Xp, W1, QKVp, NT, 768, 256);
    attn1_kernel<<<dim3(256, 8, 2), 256>>>(QKVp);

    // Stage 2: freq-axis attention (S=64)
    tf32_gemm_kernel<<<dim3(6, 512), 256, SMEMG>>>(Xp, W2, QKVp, NT, 768, 256);
    attn64_kernel<2><<<dim3(1024, 4), 256, SMEM64>>>(QKVp);

    // Stage 3: windowed attention (S=64)
    tf32_gemm_kernel<<<dim3(6, 512), 256, SMEMG>>>(Xp, W3, QKVp, NT, 768, 256);
    attn64_kernel<3><<<dim3(1024, 4), 256, SMEM64>>>(QKVp);

    // Projection
    tf32_gemm_kernel<<<dim3(2, 512), 256, SMEMG>>>(Xp, Wp, QKVp, NT, 256, 256);

    permute_out_kernel<<<dim3(8, 512, 4), dim3(32, 8)>>>(out);
}

// round 8
// speedup vs baseline: 3.0987x; 1.1536x over previous
#include <cuda_runtime.h>
#include <cuda_bf16.h>
#include <math.h>
#include <stdint.h>

// Problem constants
#define BB 4
#define DD 256
#define TT 256
#define FF 64
#define HH 8
#define HD 32
#define NT (BB*TT*FF)          // 65536 tokens

// Scratch (no allocations allowed -> device globals)
__device__ float g_X[(size_t)NT * DD];        // canonical token-major activations (tf32-rounded)
__device__ float g_QKV[(size_t)NT * 3 * DD];  // qkv / reused as proj output
__device__ float g_W[655360];                 // tf32-rounded weights: W1|W2|W3|Wp
__device__ float2 g_rope[256 * 16];           // cos/sin table [pos][j]

// ---------------------------------------------------------------------------
// TF32 / bf16 helpers
// ---------------------------------------------------------------------------
__device__ __forceinline__ uint32_t f2tf32(float x) {
    uint32_t r;
    asm("cvt.rna.tf32.f32 %0, %1;" : "=r"(r) : "f"(x));
    return r;
}
__device__ __forceinline__ float tf32r(float x) { return __uint_as_float(f2tf32(x)); }

__device__ __forceinline__ void mma_tf32(float* c, const uint32_t* a, const uint32_t* b) {
    asm volatile(
        "mma.sync.aligned.m16n8k8.row.col.f32.tf32.tf32.f32 "
        "{%0,%1,%2,%3}, {%4,%5,%6,%7}, {%8,%9}, {%0,%1,%2,%3};"
        : "+f"(c[0]), "+f"(c[1]), "+f"(c[2]), "+f"(c[3])
        : "r"(a[0]), "r"(a[1]), "r"(a[2]), "r"(a[3]), "r"(b[0]), "r"(b[1]));
}

__device__ __forceinline__ void mma_bf16(float* c, const uint32_t* a, const uint32_t* b) {
    asm volatile(
        "mma.sync.aligned.m16n8k16.row.col.f32.bf16.bf16.f32 "
        "{%0,%1,%2,%3}, {%4,%5,%6,%7}, {%8,%9}, {%0,%1,%2,%3};"
        : "+f"(c[0]), "+f"(c[1]), "+f"(c[2]), "+f"(c[3])
        : "r"(a[0]), "r"(a[1]), "r"(a[2]), "r"(a[3]), "r"(b[0]), "r"(b[1]));
}

__device__ __forceinline__ uint32_t pack_bf16_hi(float x0, float x1, float& r0, float& r1) {
    __nv_bfloat16 h0 = __float2bfloat16(x0);
    __nv_bfloat16 h1 = __float2bfloat16(x1);
    r0 = x0 - __bfloat162float(h0);
    r1 = x1 - __bfloat162float(h1);
    __nv_bfloat162 p = {h0, h1};
    return *(uint32_t*)&p;
}
__device__ __forceinline__ uint32_t pack_bf16(float x0, float x1) {
    __nv_bfloat162 p = {__float2bfloat16(x0), __float2bfloat16(x1)};
    return *(uint32_t*)&p;
}

// cp.async helpers
__device__ __forceinline__ void cp_async16(uint32_t saddr, const void* g) {
    asm volatile("cp.async.cg.shared.global [%0], [%1], 16;" :: "r"(saddr), "l"(g));
}
__device__ __forceinline__ void cp_commit() {
    asm volatile("cp.async.commit_group;");
}
template <int N> __device__ __forceinline__ void cp_wait() {
    asm volatile("cp.async.wait_group %0;" :: "n"(N));
}

// ---------------------------------------------------------------------------
// RoPE table + weight pre-rounding
// ---------------------------------------------------------------------------
__global__ __launch_bounds__(256) void rope_table_kernel() {
    int i = blockIdx.x * 256 + threadIdx.x;   // 4096
    int p = i >> 4, j = i & 15;
    const float CEXP = 0.830482023721841f;    // log2(10000)/16
    float inv = exp2f(-(float)j * CEXP);
    float sn, cs;
    sincosf((float)p * inv, &sn, &cs);
    g_rope[i] = make_float2(cs, sn);
}

__global__ __launch_bounds__(256) void round_w_kernel(const float* __restrict__ src,
                                                      int dst_off, int n) {
    int i = blockIdx.x * 256 + threadIdx.x;
    if (i < n) g_W[dst_off + i] = tf32r(src[i]);
}

// ---------------------------------------------------------------------------
// Tiled transpose permutes
// ---------------------------------------------------------------------------
__global__ __launch_bounds__(256) void permute_in_kernel(const float* __restrict__ x) {
    __shared__ float tile[32][33];
    const int b = blockIdx.z;
    const int tf0 = blockIdx.x * 32;
    const int d0 = blockIdx.y * 32;
    const int tx = threadIdx.x, ty = threadIdx.y;
    #pragma unroll
    for (int i = 0; i < 4; i++)
        tile[ty + 8 * i][tx] = x[((size_t)(b * 256 + d0 + ty + 8 * i) * 16384) + tf0 + tx];
    __syncthreads();
    #pragma unroll
    for (int i = 0; i < 4; i++)
        g_X[((size_t)(b * 16384 + tf0 + ty + 8 * i)) * 256 + d0 + tx] = tf32r(tile[tx][ty + 8 * i]);
}

__global__ __launch_bounds__(256) void permute_out_kernel(float* __restrict__ out) {
    __shared__ float tile[32][33];
    const int b = blockIdx.z;
    const int d0 = blockIdx.x * 32;
    const int tf0 = blockIdx.y * 32;
    const int tx = threadIdx.x, ty = threadIdx.y;
    #pragma unroll
    for (int i = 0; i < 4; i++)
        tile[ty + 8 * i][tx] = g_QKV[((size_t)(b * 16384 + tf0 + ty + 8 * i)) * 256 + d0 + tx];
    __syncthreads();
    #pragma unroll
    for (int i = 0; i < 4; i++)
        out[((size_t)(b * 256 + d0 + ty + 8 * i) * 16384) + tf0 + tx] = tile[tx][ty + 8 * i];
}

// ---------------------------------------------------------------------------
// TF32 GEMM, cp.async 3-stage pipeline. Operands pre-rounded to tf32.
// C[M,N] = A[M,K] @ B[K,N]; tile 128x128x32; 8 warps of 64x32.
// Stage: As[128][36] | Bs[32][136] = 8960 floats.
// ---------------------------------------------------------------------------
__global__ __launch_bounds__(256, 2) void tf32_gemm_kernel(
    const float* __restrict__ A, const float* __restrict__ B, float* __restrict__ C,
    int M, int N, int K)
{
    extern __shared__ float smg[];

    const int tid = threadIdx.x;
    const int wid = tid >> 5;
    const int lane = tid & 31;
    const int tq = lane >> 2;
    const int tr = lane & 3;
    const int warp_m = (wid & 1) * 64;
    const int warp_n = (wid >> 1) * 32;
    const int bx = blockIdx.x * 128;
    const int by = blockIdx.y * 128;

    float acc[4][4][4];
    #pragma unroll
    for (int i = 0; i < 4; i++)
        #pragma unroll
        for (int j = 0; j < 4; j++)
            #pragma unroll
            for (int r = 0; r < 4; r++) acc[i][j][r] = 0.0f;

    const int am = tid >> 3;           // 0..31 (+32*it)
    const int ak = (tid & 7) * 4;      // 0..28
    const int bk = tid >> 5;           // 0..7 (+8*it)
    const int bn = (tid & 31) * 4;     // 0..124

    const float* Ag = A + (size_t)(by + am) * K + ak;
    const float* Bg = B + (size_t)bk * N + bx + bn;

    uint32_t sA[3], sB[3];
    #pragma unroll
    for (int s = 0; s < 3; s++) {
        sA[s] = (uint32_t)__cvta_generic_to_shared(&smg[s * 8960]);
        sB[s] = sA[s] + 4608 * 4;
    }

    auto issue = [&](int kt, int s) {
        const int ko = kt * 32;
        #pragma unroll
        for (int it = 0; it < 4; it++) {
            cp_async16(sA[s] + ((am + 32 * it) * 36 + ak) * 4, Ag + (size_t)(32 * it) * K + ko);
            cp_async16(sB[s] + ((bk + 8 * it) * 136 + bn) * 4, Bg + (size_t)(ko + 8 * it) * N);
        }
        cp_commit();
    };

    const int nt = K >> 5;
    issue(0, 0);
    issue(1, 1);
    cp_wait<1>();
    __syncthreads();

    for (int kt = 0; kt < nt; kt++) {
        const float* As = smg + (kt % 3) * 8960;
        const float* Bs = As + 4608;

        #pragma unroll
        for (int c = 0; c < 4; c++) {
            const int ks = c * 8;
            uint32_t a[4][4], b[4][2];
            #pragma unroll
            for (int i = 0; i < 4; i++) {
                int row = warp_m + i * 16 + tq;
                a[i][0] = __float_as_uint(As[row * 36 + ks + tr]);
                a[i][1] = __float_as_uint(As[(row + 8) * 36 + ks + tr]);
                a[i][2] = __float_as_uint(As[row * 36 + ks + tr + 4]);
                a[i][3] = __float_as_uint(As[(row + 8) * 36 + ks + tr + 4]);
            }
            #pragma unroll
            for (int j = 0; j < 4; j++) {
                int col = warp_n + j * 8 + tq;
                b[j][0] = __float_as_uint(Bs[(ks + tr) * 136 + col]);
                b[j][1] = __float_as_uint(Bs[(ks + tr + 4) * 136 + col]);
            }
            #pragma unroll
            for (int i = 0; i < 4; i++)
                #pragma unroll
                for (int j = 0; j < 4; j++)
                    mma_tf32(acc[i][j], a[i], b[j]);
        }

        if (kt + 1 < nt) {
            if (kt + 2 < nt) {
                issue(kt + 2, (kt + 2) % 3);
                cp_wait<1>();
            } else {
                cp_wait<0>();
            }
            __syncthreads();
        }
    }

    #pragma unroll
    for (int i = 0; i < 4; i++) {
        int row0 = by + warp_m + i * 16 + tq;
        #pragma unroll
        for (int j = 0; j < 4; j++) {
            int col0 = bx + warp_n + j * 8 + 2 * tr;
            *(float2*)&C[(size_t)row0 * N + col0] = make_float2(acc[i][j][0], acc[i][j][1]);
            *(float2*)&C[(size_t)(row0 + 8) * N + col0] = make_float2(acc[i][j][2], acc[i][j][3]);
        }
    }
}

// ---------------------------------------------------------------------------
// Token index per stage.
// ---------------------------------------------------------------------------
template <int STAGE>
__device__ __forceinline__ int tok_of(int g, int p) {
    if (STAGE == 1) {
        int b = g >> 6, f = g & 63;
        return (b * 256 + p) * 64 + f;
    } else if (STAGE == 2) {
        return g * 64 + p;
    } else {
        int b = g >> 8, rem = g & 255;
        int i = rem >> 3, jf = rem & 7;
        int t = i * 8 + (p >> 3);
        int f = jf * 8 + (p & 7);
        return (b * 256 + t) * 64 + f;
    }
}

// ---------------------------------------------------------------------------
// Q fragments: bf16-split, built directly from gmem.
// ---------------------------------------------------------------------------
template <int STAGE>
__device__ __forceinline__ void load_q_frags(
    const float* __restrict__ qkv, int g, int h, int p0,
    int tr, uint32_t qh[2][4], uint32_t ql[2][4])
{
    const float SCALE = 0.17677669529663687f;   // 1/sqrt(32)
    #pragma unroll
    for (int kt = 0; kt < 2; kt++)
        #pragma unroll
        for (int hv = 0; hv < 2; hv++) {
            int j = kt * 8 + tr + 4 * hv;
            #pragma unroll
            for (int rr = 0; rr < 2; rr++) {
                int p = p0 + rr * 8;
                int tok = tok_of<STAGE>(g, p);
                float2 q = *(const float2*)(qkv + (size_t)tok * 768 + h * 32 + 2 * j);
                float2 cs = g_rope[p * 16 + j];
                float q0 = (q.x * cs.x - q.y * cs.y) * SCALE;
                float q1 = (q.y * cs.x + q.x * cs.y) * SCALE;
                float r0, r1;
                qh[kt][hv * 2 + rr] = pack_bf16_hi(q0, q1, r0, r1);
                ql[kt][hv * 2 + rr] = pack_bf16(r0, r1);
            }
        }
}

// ---------------------------------------------------------------------------
// Stage-1 attention: S=256, streamed KV (32-key double-buffered chunks).
// ---------------------------------------------------------------------------
__global__ __launch_bounds__(256, 3) void attn1_kernel(const float* __restrict__ qkv) {
    constexpr int BUF = 2432;              // u32 per KV buffer
    __shared__ uint32_t smu[2 * BUF + 8 * 576];
    float* smf = (float*)smu;

    const int g = blockIdx.x;              // b*64+f
    const int h = blockIdx.y;
    const int qoff = blockIdx.z * 128;
    const int tid = threadIdx.x;
    const int w = tid >> 5, lane = tid & 31, tq = lane >> 2, tr = lane & 3;
    const int m_base = w * 16;

    uint32_t qh[2][4], ql[2][4];
    load_q_frags<1>(qkv, g, h, qoff + m_base + tq, tr, qh, ql);

    const int kj = tid & 15;
    const int kk0 = tid >> 4;
    const int vd = tid & 31;
    const int vk0 = tid >> 5;
    float2 kx[2];
    float vx[4];

    auto load_chunk = [&](int c) {
        int kb = c * 32;
        #pragma unroll
        for (int r = 0; r < 2; r++) {
            int tok = tok_of<1>(g, kb + r * 16 + kk0);
            kx[r] = *(const float2*)(qkv + (size_t)tok * 768 + 256 + h * 32 + 2 * kj);
        }
        #pragma unroll
        for (int r = 0; r < 4; r++) {
            int tok = tok_of<1>(g, kb + r * 8 + vk0);
            vx[r] = qkv[(size_t)tok * 768 + 512 + h * 32 + vd];
        }
    };
    auto store_chunk = [&](int c, int base) {
        int kb = c * 32;
        #pragma unroll
        for (int r = 0; r < 2; r++) {
            int k = r * 16 + kk0;
            float2 cs = g_rope[(kb + k) * 16 + kj];
            float k0 = kx[r].x * cs.x - kx[r].y * cs.y;
            float k1 = kx[r].y * cs.x + kx[r].x * cs.y;
            float r0, r1;
            smu[base + k * 20 + kj] = pack_bf16_hi(k0, k1, r0, r1);
            smu[base + 640 + k * 20 + kj] = pack_bf16(r0, r1);
        }
        #pragma unroll
        for (int r = 0; r < 4; r++)
            smf[base + 1280 + vd * 36 + (r * 8 + vk0)] = tf32r(vx[r]);
    };

    load_chunk(0);
    store_chunk(0, 0);
    __syncthreads();

    float* Pw = smf + 2 * BUF + w * 576;
    float co[4][4];
    #pragma unroll
    for (int i = 0; i < 4; i++)
        #pragma unroll
        for (int j = 0; j < 4; j++) co[i][j] = 0.0f;
    float mrun0 = -1e30f, mrun1 = -1e30f, lrun0 = 0.0f, lrun1 = 0.0f;

    for (int c = 0; c < 8; c++) {
        const uint32_t* Khi = smu + (c & 1) * BUF;
        const uint32_t* Klo = Khi + 640;
        const float* Vt = (const float*)(Khi + 1280);

        if (c < 7) load_chunk(c + 1);

        float sc[4][4];
        #pragma unroll
        for (int nt = 0; nt < 4; nt++) {
            const uint32_t* Krh = Khi + (nt * 8 + tq) * 20;
            const uint32_t* Krl = Klo + (nt * 8 + tq) * 20;
            float c0[4] = {0, 0, 0, 0}, c1[4] = {0, 0, 0, 0}, c2[4] = {0, 0, 0, 0};
            #pragma unroll
            for (int kt = 0; kt < 2; kt++) {
                uint32_t bh[2] = {Krh[kt * 8 + tr], Krh[kt * 8 + tr + 4]};
                uint32_t bl[2] = {Krl[kt * 8 + tr], Krl[kt * 8 + tr + 4]};
                mma_bf16(c0, qh[kt], bh);
                mma_bf16(c1, ql[kt], bh);
                mma_bf16(c2, qh[kt], bl);
            }
            #pragma unroll
            for (int r = 0; r < 4; r++) sc[nt][r] = c0[r] + c1[r] + c2[r];
        }

        float mx0 = -1e30f, mx1 = -1e30f;
        #pragma unroll
        for (int nt = 0; nt < 4; nt++) {
            mx0 = fmaxf(mx0, fmaxf(sc[nt][0], sc[nt][1]));
            mx1 = fmaxf(mx1, fmaxf(sc[nt][2], sc[nt][3]));
        }
        mx0 = fmaxf(mx0, __shfl_xor_sync(0xFFFFFFFFu, mx0, 1));
        mx0 = fmaxf(mx0, __shfl_xor_sync(0xFFFFFFFFu, mx0, 2));
        mx1 = fmaxf(mx1, __shfl_xor_sync(0xFFFFFFFFu, mx1, 1));
        mx1 = fmaxf(mx1, __shfl_xor_sync(0xFFFFFFFFu, mx1, 2));
        float mn0 = fmaxf(mrun0, mx0), mn1 = fmaxf(mrun1, mx1);
        float esc0 = __expf(mrun0 - mn0), esc1 = __expf(mrun1 - mn1);
        float s0 = 0.0f, s1 = 0.0f;
        #pragma unroll
        for (int nt = 0; nt < 4; nt++) {
            float p0 = __expf(sc[nt][0] - mn0);
            float p1 = __expf(sc[nt][1] - mn0);
            float p2 = __expf(sc[nt][2] - mn1);
            float p3 = __expf(sc[nt][3] - mn1);
            s0 += p0 + p1;
            s1 += p2 + p3;
            *(float2*)&Pw[tq * 36 + nt * 8 + 2 * tr] = make_float2(tf32r(p0), tf32r(p1));
            *(float2*)&Pw[(tq + 8) * 36 + nt * 8 + 2 * tr] = make_float2(tf32r(p2), tf32r(p3));
        }
        s0 += __shfl_xor_sync(0xFFFFFFFFu, s0, 1);
        s0 += __shfl_xor_sync(0xFFFFFFFFu, s0, 2);
        s1 += __shfl_xor_sync(0xFFFFFFFFu, s1, 1);
        s1 += __shfl_xor_sync(0xFFFFFFFFu, s1, 2);
        lrun0 = lrun0 * esc0 + s0;
        lrun1 = lrun1 * esc1 + s1;
        mrun0 = mn0; mrun1 = mn1;
        #pragma unroll
        for (int nt2 = 0; nt2 < 4; nt2++) {
            co[nt2][0] *= esc0; co[nt2][1] *= esc0;
            co[nt2][2] *= esc1; co[nt2][3] *= esc1;
        }
        __syncwarp();

        #pragma unroll
        for (int kt2 = 0; kt2 < 4; kt2++) {
            int kc = kt2 * 8 + tr;
            uint32_t a[4];
            a[0] = __float_as_uint(Pw[tq * 36 + kc]);
            a[1] = __float_as_uint(Pw[(tq + 8) * 36 + kc]);
            a[2] = __float_as_uint(Pw[tq * 36 + kc + 4]);
            a[3] = __float_as_uint(Pw[(tq + 8) * 36 + kc + 4]);
            #pragma unroll
            for (int nt2 = 0; nt2 < 4; nt2++) {
                const float* vrow = Vt + (nt2 * 8 + tq) * 36 + kc;
                uint32_t b[2] = {__float_as_uint(vrow[0]), __float_as_uint(vrow[4])};
                mma_tf32(co[nt2], a, b);
            }
        }
        __syncwarp();

        if (c < 7) store_chunk(c + 1, ((c + 1) & 1) * BUF);
        __syncthreads();
    }

    float inv0 = 1.0f / lrun0, inv1 = 1.0f / lrun1;
    int p0r = qoff + m_base + tq;
    size_t o0 = (size_t)tok_of<1>(g, p0r) * 256 + h * 32;
    size_t o1 = (size_t)tok_of<1>(g, p0r + 8) * 256 + h * 32;
    #pragma unroll
    for (int nt2 = 0; nt2 < 4; nt2++) {
        int cc = nt2 * 8 + 2 * tr;
        *(float2*)&g_X[o0 + cc] = make_float2(tf32r(co[nt2][0] * inv0), tf32r(co[nt2][1] * inv0));
        *(float2*)&g_X[o1 + cc] = make_float2(tf32r(co[nt2][2] * inv1), tf32r(co[nt2][3] * inv1));
    }
}

// ---------------------------------------------------------------------------
// Stage-2/3 attention: S=64, 2 heads per block.
// ---------------------------------------------------------------------------
template <int STAGE>
__global__ __launch_bounds__(256, 3) void attn64_kernel(const float* __restrict__ qkv) {
    constexpr int HS = 4736;               // u32 per head block
    extern __shared__ uint32_t smu2[];
    float* smf = (float*)smu2;

    const int g = blockIdx.x;
    const int tid = threadIdx.x;
    const int w = tid >> 5, lane = tid & 31, tq = lane >> 2, tr = lane & 3;
    const int hh = w >> 2;
    const int h = blockIdx.y * 2 + hh;
    const int m_base = (w & 3) * 16;

    for (int idx = tid; idx < 2048; idx += 256) {
        int hl = idx >> 10, rem = idx & 1023;
        int k = rem >> 4, j = rem & 15;
        int tok = tok_of<STAGE>(g, k);
        const float* bp = qkv + (size_t)tok * 768 + 256 + (blockIdx.y * 2 + hl) * 32;
        float x0 = bp[2 * j], x1 = bp[2 * j + 1];
        float2 cs = g_rope[k * 16 + j];
        float k0 = x0 * cs.x - x1 * cs.y;
        float k1 = x1 * cs.x + x0 * cs.y;
        float r0, r1;
        int base = hl * HS;
        smu2[base + k * 20 + j] = pack_bf16_hi(k0, k1, r0, r1);
        smu2[base + 1280 + k * 20 + j] = pack_bf16(r0, r1);
    }
    for (int idx = tid; idx < 4096; idx += 256) {
        int hl = idx >> 11, rem = idx & 2047;
        int k = rem >> 5, d = rem & 31;
        float v = qkv[(size_t)tok_of<STAGE>(g, k) * 768 + 512 + (blockIdx.y * 2 + hl) * 32 + d];
        smf[hl * HS + 2560 + d * 68 + k] = tf32r(v);
    }

    uint32_t qh[2][4], ql[2][4];
    load_q_frags<STAGE>(qkv, g, h, m_base + tq, tr, qh, ql);
    __syncthreads();

    const uint32_t* KhiB = smu2 + hh * HS;
    const uint32_t* KloB = KhiB + 1280;
    const float* VtB = (const float*)(KhiB + 2560);
    float* Pw = smf + 2 * HS + w * 576;

    float co[4][4];
    #pragma unroll
    for (int i = 0; i < 4; i++)
        #pragma unroll
        for (int j = 0; j < 4; j++) co[i][j] = 0.0f;
    float mrun0 = -1e30f, mrun1 = -1e30f, lrun0 = 0.0f, lrun1 = 0.0f;

    #pragma unroll
    for (int j0 = 0; j0 < 64; j0 += 32) {
        float sc[4][4];
        #pragma unroll
        for (int nt = 0; nt < 4; nt++) {
            const uint32_t* Krh = KhiB + (j0 + nt * 8 + tq) * 20;
            const uint32_t* Krl = KloB + (j0 + nt * 8 + tq) * 20;
            float c0[4] = {0, 0, 0, 0}, c1[4] = {0, 0, 0, 0}, c2[4] = {0, 0, 0, 0};
            #pragma unroll
            for (int kt = 0; kt < 2; kt++) {
                uint32_t bh[2] = {Krh[kt * 8 + tr], Krh[kt * 8 + tr + 4]};
                uint32_t bl[2] = {Krl[kt * 8 + tr], Krl[kt * 8 + tr + 4]};
                mma_bf16(c0, qh[kt], bh);
                mma_bf16(c1, ql[kt], bh);
                mma_bf16(c2, qh[kt], bl);
            }
            #pragma unroll
            for (int r = 0; r < 4; r++) sc[nt][r] = c0[r] + c1[r] + c2[r];
        }

        float mx0 = -1e30f, mx1 = -1e30f;
        #pragma unroll
        for (int nt = 0; nt < 4; nt++) {
            mx0 = fmaxf(mx0, fmaxf(sc[nt][0], sc[nt][1]));
            mx1 = fmaxf(mx1, fmaxf(sc[nt][2], sc[nt][3]));
        }
        mx0 = fmaxf(mx0, __shfl_xor_sync(0xFFFFFFFFu, mx0, 1));
        mx0 = fmaxf(mx0, __shfl_xor_sync(0xFFFFFFFFu, mx0, 2));
        mx1 = fmaxf(mx1, __shfl_xor_sync(0xFFFFFFFFu, mx1, 1));
        mx1 = fmaxf(mx1, __shfl_xor_sync(0xFFFFFFFFu, mx1, 2));
        float mn0 = fmaxf(mrun0, mx0), mn1 = fmaxf(mrun1, mx1);
        float esc0 = __expf(mrun0 - mn0), esc1 = __expf(mrun1 - mn1);
        float s0 = 0.0f, s1 = 0.0f;
        #pragma unroll
        for (int nt = 0; nt < 4; nt++) {
            float p0 = __expf(sc[nt][0] - mn0);
            float p1 = __expf(sc[nt][1] - mn0);
            float p2 = __expf(sc[nt][2] - mn1);
            float p3 = __expf(sc[nt][3] - mn1);
            s0 += p0 + p1;
            s1 += p2 + p3;
            *(float2*)&Pw[tq * 36 + nt * 8 + 2 * tr] = make_float2(tf32r(p0), tf32r(p1));
            *(float2*)&Pw[(tq + 8) * 36 + nt * 8 + 2 * tr] = make_float2(tf32r(p2), tf32r(p3));
        }
        s0 += __shfl_xor_sync(0xFFFFFFFFu, s0, 1);
        s0 += __shfl_xor_sync(0xFFFFFFFFu, s0, 2);
        s1 += __shfl_xor_sync(0xFFFFFFFFu, s1, 1);
        s1 += __shfl_xor_sync(0xFFFFFFFFu, s1, 2);
        lrun0 = lrun0 * esc0 + s0;
        lrun1 = lrun1 * esc1 + s1;
        mrun0 = mn0; mrun1 = mn1;
        #pragma unroll
        for (int nt2 = 0; nt2 < 4; nt2++) {
            co[nt2][0] *= esc0; co[nt2][1] *= esc0;
            co[nt2][2] *= esc1; co[nt2][3] *= esc1;
        }
        __syncwarp();

        #pragma unroll
        for (int kt2 = 0; kt2 < 4; kt2++) {
            int kc = kt2 * 8 + tr;
            uint32_t a[4];
            a[0] = __float_as_uint(Pw[tq * 36 + kc]);
            a[1] = __float_as_uint(Pw[(tq + 8) * 36 + kc]);
            a[2] = __float_as_uint(Pw[tq * 36 + kc + 4]);
            a[3] = __float_as_uint(Pw[(tq + 8) * 36 + kc + 4]);
            #pragma unroll
            for (int nt2 = 0; nt2 < 4; nt2++) {
                const float* vrow = VtB + (nt2 * 8 + tq) * 68 + j0 + kc;
                uint32_t b[2] = {__float_as_uint(vrow[0]), __float_as_uint(vrow[4])};
                mma_tf32(co[nt2], a, b);
            }
        }
        __syncwarp();
    }

    float inv0 = 1.0f / lrun0, inv1 = 1.0f / lrun1;
    int p0r = m_base + tq;
    size_t o0 = (size_t)tok_of<STAGE>(g, p0r) * 256 + h * 32;
    size_t o1 = (size_t)tok_of<STAGE>(g, p0r + 8) * 256 + h * 32;
    #pragma unroll
    for (int nt2 = 0; nt2 < 4; nt2++) {
        int cc = nt2 * 8 + 2 * tr;
        *(float2*)&g_X[o0 + cc] = make_float2(tf32r(co[nt2][0] * inv0), tf32r(co[nt2][1] * inv0));
        *(float2*)&g_X[o1 + cc] = make_float2(tf32r(co[nt2][2] * inv1), tf32r(co[nt2][3] * inv1));
    }
}

// ---------------------------------------------------------------------------
extern "C" void kernel_launch(void* const* d_in, const int* in_sizes, int n_in,
                              void* d_out, int out_size) {
    const float* x  = (const float*)d_in[0];
    const float* W1 = (const float*)d_in[1];
    const float* W2 = (const float*)d_in[2];
    const float* W3 = (const float*)d_in[3];
    const float* Wp = (const float*)d_in[4];
    float* out = (float*)d_out;

    float* Xp;   cudaGetSymbolAddress((void**)&Xp,   g_X);
    float* QKVp; cudaGetSymbolAddress((void**)&QKVp, g_QKV);
    float* Wr;   cudaGetSymbolAddress((void**)&Wr,   g_W);

    const int SMEMG = 3 * 8960 * 4;                        // 107520
    const int SMEM64 = (2 * 4736 + 8 * 576) * 4;           // 56320

    cudaFuncSetAttribute(tf32_gemm_kernel,
                         cudaFuncAttributeMaxDynamicSharedMemorySize, SMEMG);
    cudaFuncSetAttribute(attn64_kernel<2>,
                         cudaFuncAttributeMaxDynamicSharedMemorySize, SMEM64);
    cudaFuncSetAttribute(attn64_kernel<3>,
                         cudaFuncAttributeMaxDynamicSharedMemorySize, SMEM64);

    rope_table_kernel<<<16, 256>>>();
    round_w_kernel<<<768, 256>>>(W1, 0, 196608);
    round_w_kernel<<<768, 256>>>(W2, 196608, 196608);
    round_w_kernel<<<768, 256>>>(W3, 393216, 196608);
    round_w_kernel<<<256, 256>>>(Wp, 589824, 65536);
    permute_in_kernel<<<dim3(512, 8, 4), dim3(32, 8)>>>(x);

    // Stage 1: time-axis attention (S=256), streamed KV
    tf32_gemm_kernel<<<dim3(6, 512), 256, SMEMG>>>(Xp, Wr, QKVp, NT, 768, 256);
    attn1_kernel<<<dim3(256, 8, 2), 256>>>(QKVp);

    // Stage 2: freq-axis attention (S=64)
    tf32_gemm_kernel<<<dim3(6, 512), 256, SMEMG>>>(Xp, Wr + 196608, QKVp, NT, 768, 256);
    attn64_kernel<2><<<dim3(1024, 4), 256, SMEM64>>>(QKVp);

    // Stage 3: windowed attention (S=64)
    tf32_gemm_kernel<<<dim3(6, 512), 256, SMEMG>>>(Xp, Wr + 393216, QKVp, NT, 768, 256);
    attn64_kernel<3><<<dim3(1024, 4), 256, SMEM64>>>(QKVp);

    // Projection
    tf32_gemm_kernel<<<dim3(2, 512), 256, SMEMG>>>(Xp, Wr + 589824, QKVp, NT, 256, 256);

    permute_out_kernel<<<dim3(8, 512, 4), dim3(32, 8)>>>(out);
}

// round 9
// speedup vs baseline: 3.1112x; 1.0040x over previous
#include <cuda_runtime.h>
#include <cuda_bf16.h>
#include <math.h>
#include <stdint.h>

// Problem constants
#define BB 4
#define DD 256
#define TT 256
#define FF 64
#define HH 8
#define HD 32
#define NT (BB*TT*FF)          // 65536 tokens

// Scratch (no allocations allowed -> device globals)
__device__ float g_X[(size_t)NT * DD];        // canonical token-major activations (tf32-rounded)
__device__ float g_QKV[(size_t)NT * 3 * DD];  // qkv / reused as proj output
__device__ float g_W[655360];                 // tf32-rounded weights: W1|W2|W3|Wp
__device__ float2 g_rope[256 * 16];           // cos/sin table [pos][j]

// ---------------------------------------------------------------------------
// TF32 / bf16 helpers
// ---------------------------------------------------------------------------
__device__ __forceinline__ uint32_t f2tf32(float x) {
    uint32_t r;
    asm("cvt.rna.tf32.f32 %0, %1;" : "=r"(r) : "f"(x));
    return r;
}
__device__ __forceinline__ float tf32r(float x) { return __uint_as_float(f2tf32(x)); }

__device__ __forceinline__ void mma_tf32(float* c, const uint32_t* a, const uint32_t* b) {
    asm volatile(
        "mma.sync.aligned.m16n8k8.row.col.f32.tf32.tf32.f32 "
        "{%0,%1,%2,%3}, {%4,%5,%6,%7}, {%8,%9}, {%0,%1,%2,%3};"
        : "+f"(c[0]), "+f"(c[1]), "+f"(c[2]), "+f"(c[3])
        : "r"(a[0]), "r"(a[1]), "r"(a[2]), "r"(a[3]), "r"(b[0]), "r"(b[1]));
}

__device__ __forceinline__ void mma_bf16(float* c, const uint32_t* a, const uint32_t* b) {
    asm volatile(
        "mma.sync.aligned.m16n8k16.row.col.f32.bf16.bf16.f32 "
        "{%0,%1,%2,%3}, {%4,%5,%6,%7}, {%8,%9}, {%0,%1,%2,%3};"
        : "+f"(c[0]), "+f"(c[1]), "+f"(c[2]), "+f"(c[3])
        : "r"(a[0]), "r"(a[1]), "r"(a[2]), "r"(a[3]), "r"(b[0]), "r"(b[1]));
}

__device__ __forceinline__ uint32_t pack_bf16_hi(float x0, float x1, float& r0, float& r1) {
    __nv_bfloat16 h0 = __float2bfloat16(x0);
    __nv_bfloat16 h1 = __float2bfloat16(x1);
    r0 = x0 - __bfloat162float(h0);
    r1 = x1 - __bfloat162float(h1);
    __nv_bfloat162 p = {h0, h1};
    return *(uint32_t*)&p;
}
__device__ __forceinline__ uint32_t pack_bf16(float x0, float x1) {
    __nv_bfloat162 p = {__float2bfloat16(x0), __float2bfloat16(x1)};
    return *(uint32_t*)&p;
}

// cp.async helpers
__device__ __forceinline__ void cp_async16(uint32_t saddr, const void* g) {
    asm volatile("cp.async.cg.shared.global [%0], [%1], 16;" :: "r"(saddr), "l"(g));
}
__device__ __forceinline__ void cp_commit() {
    asm volatile("cp.async.commit_group;");
}
template <int N> __device__ __forceinline__ void cp_wait() {
    asm volatile("cp.async.wait_group %0;" :: "n"(N));
}

// ---------------------------------------------------------------------------
// RoPE table + merged weight pre-rounding
// ---------------------------------------------------------------------------
__global__ __launch_bounds__(256) void rope_table_kernel() {
    int i = blockIdx.x * 256 + threadIdx.x;   // 4096
    int p = i >> 4, j = i & 15;
    const float CEXP = 0.830482023721841f;    // log2(10000)/16
    float inv = exp2f(-(float)j * CEXP);
    float sn, cs;
    sincosf((float)p * inv, &sn, &cs);
    g_rope[i] = make_float2(cs, sn);
}

__global__ __launch_bounds__(256) void round_w_kernel(
    const float* __restrict__ W1, const float* __restrict__ W2,
    const float* __restrict__ W3, const float* __restrict__ Wp) {
    int i = blockIdx.x * 256 + threadIdx.x;   // 655360
    float v;
    if (i < 196608)      v = W1[i];
    else if (i < 393216) v = W2[i - 196608];
    else if (i < 589824) v = W3[i - 393216];
    else                 v = Wp[i - 589824];
    g_W[i] = tf32r(v);
}

// ---------------------------------------------------------------------------
// Tiled transpose permutes
// ---------------------------------------------------------------------------
__global__ __launch_bounds__(256) void permute_in_kernel(const float* __restrict__ x) {
    __shared__ float tile[32][33];
    const int b = blockIdx.z;
    const int tf0 = blockIdx.x * 32;
    const int d0 = blockIdx.y * 32;
    const int tx = threadIdx.x, ty = threadIdx.y;
    #pragma unroll
    for (int i = 0; i < 4; i++)
        tile[ty + 8 * i][tx] = x[((size_t)(b * 256 + d0 + ty + 8 * i) * 16384) + tf0 + tx];
    __syncthreads();
    #pragma unroll
    for (int i = 0; i < 4; i++)
        g_X[((size_t)(b * 16384 + tf0 + ty + 8 * i)) * 256 + d0 + tx] = tf32r(tile[tx][ty + 8 * i]);
}

__global__ __launch_bounds__(256) void permute_out_kernel(float* __restrict__ out) {
    __shared__ float tile[32][33];
    const int b = blockIdx.z;
    const int d0 = blockIdx.x * 32;
    const int tf0 = blockIdx.y * 32;
    const int tx = threadIdx.x, ty = threadIdx.y;
    #pragma unroll
    for (int i = 0; i < 4; i++)
        tile[ty + 8 * i][tx] = g_QKV[((size_t)(b * 16384 + tf0 + ty + 8 * i)) * 256 + d0 + tx];
    __syncthreads();
    #pragma unroll
    for (int i = 0; i < 4; i++)
        out[((size_t)(b * 256 + d0 + ty + 8 * i) * 16384) + tf0 + tx] = tile[tx][ty + 8 * i];
}

// ---------------------------------------------------------------------------
// TF32 GEMM, cp.async 3-stage pipeline (unchanged from round 8).
// ---------------------------------------------------------------------------
__global__ __launch_bounds__(256, 2) void tf32_gemm_kernel(
    const float* __restrict__ A, const float* __restrict__ B, float* __restrict__ C,
    int M, int N, int K)
{
    extern __shared__ float smg[];

    const int tid = threadIdx.x;
    const int wid = tid >> 5;
    const int lane = tid & 31;
    const int tq = lane >> 2;
    const int tr = lane & 3;
    const int warp_m = (wid & 1) * 64;
    const int warp_n = (wid >> 1) * 32;
    const int bx = blockIdx.x * 128;
    const int by = blockIdx.y * 128;

    float acc[4][4][4];
    #pragma unroll
    for (int i = 0; i < 4; i++)
        #pragma unroll
        for (int j = 0; j < 4; j++)
            #pragma unroll
            for (int r = 0; r < 4; r++) acc[i][j][r] = 0.0f;

    const int am = tid >> 3;
    const int ak = (tid & 7) * 4;
    const int bk = tid >> 5;
    const int bn = (tid & 31) * 4;

    const float* Ag = A + (size_t)(by + am) * K + ak;
    const float* Bg = B + (size_t)bk * N + bx + bn;

    uint32_t sA[3], sB[3];
    #pragma unroll
    for (int s = 0; s < 3; s++) {
        sA[s] = (uint32_t)__cvta_generic_to_shared(&smg[s * 8960]);
        sB[s] = sA[s] + 4608 * 4;
    }

    auto issue = [&](int kt, int s) {
        const int ko = kt * 32;
        #pragma unroll
        for (int it = 0; it < 4; it++) {
            cp_async16(sA[s] + ((am + 32 * it) * 36 + ak) * 4, Ag + (size_t)(32 * it) * K + ko);
            cp_async16(sB[s] + ((bk + 8 * it) * 136 + bn) * 4, Bg + (size_t)(ko + 8 * it) * N);
        }
        cp_commit();
    };

    const int nt = K >> 5;
    issue(0, 0);
    issue(1, 1);
    cp_wait<1>();
    __syncthreads();

    for (int kt = 0; kt < nt; kt++) {
        const float* As = smg + (kt % 3) * 8960;
        const float* Bs = As + 4608;

        #pragma unroll
        for (int c = 0; c < 4; c++) {
            const int ks = c * 8;
            uint32_t a[4][4], b[4][2];
            #pragma unroll
            for (int i = 0; i < 4; i++) {
                int row = warp_m + i * 16 + tq;
                a[i][0] = __float_as_uint(As[row * 36 + ks + tr]);
                a[i][1] = __float_as_uint(As[(row + 8) * 36 + ks + tr]);
                a[i][2] = __float_as_uint(As[row * 36 + ks + tr + 4]);
                a[i][3] = __float_as_uint(As[(row + 8) * 36 + ks + tr + 4]);
            }
            #pragma unroll
            for (int j = 0; j < 4; j++) {
                int col = warp_n + j * 8 + tq;
                b[j][0] = __float_as_uint(Bs[(ks + tr) * 136 + col]);
                b[j][1] = __float_as_uint(Bs[(ks + tr + 4) * 136 + col]);
            }
            #pragma unroll
            for (int i = 0; i < 4; i++)
                #pragma unroll
                for (int j = 0; j < 4; j++)
                    mma_tf32(acc[i][j], a[i], b[j]);
        }

        if (kt + 1 < nt) {
            if (kt + 2 < nt) {
                issue(kt + 2, (kt + 2) % 3);
                cp_wait<1>();
            } else {
                cp_wait<0>();
            }
            __syncthreads();
        }
    }

    #pragma unroll
    for (int i = 0; i < 4; i++) {
        int row0 = by + warp_m + i * 16 + tq;
        #pragma unroll
        for (int j = 0; j < 4; j++) {
            int col0 = bx + warp_n + j * 8 + 2 * tr;
            *(float2*)&C[(size_t)row0 * N + col0] = make_float2(acc[i][j][0], acc[i][j][1]);
            *(float2*)&C[(size_t)(row0 + 8) * N + col0] = make_float2(acc[i][j][2], acc[i][j][3]);
        }
    }
}

// ---------------------------------------------------------------------------
// Token index per stage.
// ---------------------------------------------------------------------------
template <int STAGE>
__device__ __forceinline__ int tok_of(int g, int p) {
    if (STAGE == 1) {
        int b = g >> 6, f = g & 63;
        return (b * 256 + p) * 64 + f;
    } else if (STAGE == 2) {
        return g * 64 + p;
    } else {
        int b = g >> 8, rem = g & 255;
        int i = rem >> 3, jf = rem & 7;
        int t = i * 8 + (p >> 3);
        int f = jf * 8 + (p & 7);
        return (b * 256 + t) * 64 + f;
    }
}

// ---------------------------------------------------------------------------
// Q fragments: bf16-split, built directly from gmem.
// ---------------------------------------------------------------------------
template <int STAGE>
__device__ __forceinline__ void load_q_frags(
    const float* __restrict__ qkv, int g, int h, int p0,
    int tr, uint32_t qh[2][4], uint32_t ql[2][4])
{
    const float SCALE = 0.17677669529663687f;   // 1/sqrt(32)
    #pragma unroll
    for (int kt = 0; kt < 2; kt++)
        #pragma unroll
        for (int hv = 0; hv < 2; hv++) {
            int j = kt * 8 + tr + 4 * hv;
            #pragma unroll
            for (int rr = 0; rr < 2; rr++) {
                int p = p0 + rr * 8;
                int tok = tok_of<STAGE>(g, p);
                float2 q = *(const float2*)(qkv + (size_t)tok * 768 + h * 32 + 2 * j);
                float2 cs = g_rope[p * 16 + j];
                float q0 = (q.x * cs.x - q.y * cs.y) * SCALE;
                float q1 = (q.y * cs.x + q.x * cs.y) * SCALE;
                float r0, r1;
                qh[kt][hv * 2 + rr] = pack_bf16_hi(q0, q1, r0, r1);
                ql[kt][hv * 2 + rr] = pack_bf16(r0, r1);
            }
        }
}

// ---------------------------------------------------------------------------
// P C-fragment -> A-fragment via shuffles (no smem round-trip).
// P[tq][kt2*8+c'] lives in lane tq*4+(c'>>1), reg parity c'&1.
// ---------------------------------------------------------------------------
__device__ __forceinline__ void p_frag_shfl(const float sc4[4], int sl, bool odd,
                                            uint32_t a[4]) {
    float u0 = __shfl_sync(0xFFFFFFFFu, sc4[0], sl);
    float u1 = __shfl_sync(0xFFFFFFFFu, sc4[1], sl);
    float u2 = __shfl_sync(0xFFFFFFFFu, sc4[2], sl);
    float u3 = __shfl_sync(0xFFFFFFFFu, sc4[3], sl);
    float w0 = __shfl_sync(0xFFFFFFFFu, sc4[0], sl + 2);
    float w1 = __shfl_sync(0xFFFFFFFFu, sc4[1], sl + 2);
    float w2 = __shfl_sync(0xFFFFFFFFu, sc4[2], sl + 2);
    float w3 = __shfl_sync(0xFFFFFFFFu, sc4[3], sl + 2);
    a[0] = __float_as_uint(odd ? u1 : u0);
    a[1] = __float_as_uint(odd ? u3 : u2);
    a[2] = __float_as_uint(odd ? w1 : w0);
    a[3] = __float_as_uint(odd ? w3 : w2);
}

// ---------------------------------------------------------------------------
// Stage-1 attention: S=256, streamed KV, P via shuffle. Static smem 19.4KB.
// ---------------------------------------------------------------------------
__global__ __launch_bounds__(256, 3) void attn1_kernel(const float* __restrict__ qkv) {
    constexpr int BUF = 2432;              // u32 per KV buffer
    __shared__ uint32_t smu[2 * BUF];
    float* smf = (float*)smu;

    const int g = blockIdx.x;              // b*64+f
    const int h = blockIdx.y;
    const int qoff = blockIdx.z * 128;
    const int tid = threadIdx.x;
    const int w = tid >> 5, lane = tid & 31, tq = lane >> 2, tr = lane & 3;
    const int m_base = w * 16;
    const int sl = (tq << 2) | (tr >> 1);
    const bool odd = tr & 1;

    uint32_t qh[2][4], ql[2][4];
    load_q_frags<1>(qkv, g, h, qoff + m_base + tq, tr, qh, ql);

    const int kj = tid & 15;
    const int kk0 = tid >> 4;
    const int vd = tid & 31;
    const int vk0 = tid >> 5;
    float2 kx[2];
    float vx[4];

    auto load_chunk = [&](int c) {
        int kb = c * 32;
        #pragma unroll
        for (int r = 0; r < 2; r++) {
            int tok = tok_of<1>(g, kb + r * 16 + kk0);
            kx[r] = *(const float2*)(qkv + (size_t)tok * 768 + 256 + h * 32 + 2 * kj);
        }
        #pragma unroll
        for (int r = 0; r < 4; r++) {
            int tok = tok_of<1>(g, kb + r * 8 + vk0);
            vx[r] = qkv[(size_t)tok * 768 + 512 + h * 32 + vd];
        }
    };
    auto store_chunk = [&](int c, int base) {
        int kb = c * 32;
        #pragma unroll
        for (int r = 0; r < 2; r++) {
            int k = r * 16 + kk0;
            float2 cs = g_rope[(kb + k) * 16 + kj];
            float k0 = kx[r].x * cs.x - kx[r].y * cs.y;
            float k1 = kx[r].y * cs.x + kx[r].x * cs.y;
            float r0, r1;
            smu[base + k * 20 + kj] = pack_bf16_hi(k0, k1, r0, r1);
            smu[base + 640 + k * 20 + kj] = pack_bf16(r0, r1);
        }
        #pragma unroll
        for (int r = 0; r < 4; r++)
            smf[base + 1280 + vd * 36 + (r * 8 + vk0)] = tf32r(vx[r]);
    };

    load_chunk(0);
    store_chunk(0, 0);
    __syncthreads();

    float co[4][4];
    #pragma unroll
    for (int i = 0; i < 4; i++)
        #pragma unroll
        for (int j = 0; j < 4; j++) co[i][j] = 0.0f;
    float mrun0 = -1e30f, mrun1 = -1e30f, lrun0 = 0.0f, lrun1 = 0.0f;

    for (int c = 0; c < 8; c++) {
        const uint32_t* Khi = smu + (c & 1) * BUF;
        const uint32_t* Klo = Khi + 640;
        const float* Vt = (const float*)(Khi + 1280);

        if (c < 7) load_chunk(c + 1);

        float sc[4][4];
        #pragma unroll
        for (int nt = 0; nt < 4; nt++) {
            const uint32_t* Krh = Khi + (nt * 8 + tq) * 20;
            const uint32_t* Krl = Klo + (nt * 8 + tq) * 20;
            float c0[4] = {0, 0, 0, 0}, c1[4] = {0, 0, 0, 0}, c2[4] = {0, 0, 0, 0};
            #pragma unroll
            for (int kt = 0; kt < 2; kt++) {
                uint32_t bh[2] = {Krh[kt * 8 + tr], Krh[kt * 8 + tr + 4]};
                uint32_t bl[2] = {Krl[kt * 8 + tr], Krl[kt * 8 + tr + 4]};
                mma_bf16(c0, qh[kt], bh);
                mma_bf16(c1, ql[kt], bh);
                mma_bf16(c2, qh[kt], bl);
            }
            #pragma unroll
            for (int r = 0; r < 4; r++) sc[nt][r] = c0[r] + c1[r] + c2[r];
        }

        float mx0 = -1e30f, mx1 = -1e30f;
        #pragma unroll
        for (int nt = 0; nt < 4; nt++) {
            mx0 = fmaxf(mx0, fmaxf(sc[nt][0], sc[nt][1]));
            mx1 = fmaxf(mx1, fmaxf(sc[nt][2], sc[nt][3]));
        }
        mx0 = fmaxf(mx0, __shfl_xor_sync(0xFFFFFFFFu, mx0, 1));
        mx0 = fmaxf(mx0, __shfl_xor_sync(0xFFFFFFFFu, mx0, 2));
        mx1 = fmaxf(mx1, __shfl_xor_sync(0xFFFFFFFFu, mx1, 1));
        mx1 = fmaxf(mx1, __shfl_xor_sync(0xFFFFFFFFu, mx1, 2));
        float mn0 = fmaxf(mrun0, mx0), mn1 = fmaxf(mrun1, mx1);
        float esc0 = __expf(mrun0 - mn0), esc1 = __expf(mrun1 - mn1);
        float s0 = 0.0f, s1 = 0.0f;
        #pragma unroll
        for (int nt = 0; nt < 4; nt++) {
            float p0 = __expf(sc[nt][0] - mn0);
            float p1 = __expf(sc[nt][1] - mn0);
            float p2 = __expf(sc[nt][2] - mn1);
            float p3 = __expf(sc[nt][3] - mn1);
            s0 += p0 + p1;
            s1 += p2 + p3;
            sc[nt][0] = tf32r(p0);
            sc[nt][1] = tf32r(p1);
            sc[nt][2] = tf32r(p2);
            sc[nt][3] = tf32r(p3);
        }
        s0 += __shfl_xor_sync(0xFFFFFFFFu, s0, 1);
        s0 += __shfl_xor_sync(0xFFFFFFFFu, s0, 2);
        s1 += __shfl_xor_sync(0xFFFFFFFFu, s1, 1);
        s1 += __shfl_xor_sync(0xFFFFFFFFu, s1, 2);
        lrun0 = lrun0 * esc0 + s0;
        lrun1 = lrun1 * esc1 + s1;
        mrun0 = mn0; mrun1 = mn1;
        #pragma unroll
        for (int nt2 = 0; nt2 < 4; nt2++) {
            co[nt2][0] *= esc0; co[nt2][1] *= esc0;
            co[nt2][2] *= esc1; co[nt2][3] *= esc1;
        }

        // PV: a-frags by shuffle from score C-frag
        #pragma unroll
        for (int kt2 = 0; kt2 < 4; kt2++) {
            uint32_t a[4];
            p_frag_shfl(sc[kt2], sl, odd, a);
            int kc = kt2 * 8 + tr;
            #pragma unroll
            for (int nt2 = 0; nt2 < 4; nt2++) {
                const float* vrow = Vt + (nt2 * 8 + tq) * 36 + kc;
                uint32_t b[2] = {__float_as_uint(vrow[0]), __float_as_uint(vrow[4])};
                mma_tf32(co[nt2], a, b);
            }
        }

        if (c < 7) store_chunk(c + 1, ((c + 1) & 1) * BUF);
        __syncthreads();
    }

    float inv0 = 1.0f / lrun0, inv1 = 1.0f / lrun1;
    int p0r = qoff + m_base + tq;
    size_t o0 = (size_t)tok_of<1>(g, p0r) * 256 + h * 32;
    size_t o1 = (size_t)tok_of<1>(g, p0r + 8) * 256 + h * 32;
    #pragma unroll
    for (int nt2 = 0; nt2 < 4; nt2++) {
        int cc = nt2 * 8 + 2 * tr;
        *(float2*)&g_X[o0 + cc] = make_float2(tf32r(co[nt2][0] * inv0), tf32r(co[nt2][1] * inv0));
        *(float2*)&g_X[o1 + cc] = make_float2(tf32r(co[nt2][2] * inv1), tf32r(co[nt2][3] * inv1));
    }
}

// ---------------------------------------------------------------------------
// Stage-2/3 attention: S=64, 2 heads per block, P via shuffle.
// ---------------------------------------------------------------------------
template <int STAGE>
__global__ __launch_bounds__(256, 3) void attn64_kernel(const float* __restrict__ qkv) {
    constexpr int HS = 4736;               // u32 per head block
    extern __shared__ uint32_t smu2[];
    float* smf = (float*)smu2;

    const int g = blockIdx.x;
    const int tid = threadIdx.x;
    const int w = tid >> 5, lane = tid & 31, tq = lane >> 2, tr = lane & 3;
    const int hh = w >> 2;
    const int h = blockIdx.y * 2 + hh;
    const int m_base = (w & 3) * 16;
    const int sl = (tq << 2) | (tr >> 1);
    const bool odd = tr & 1;

    for (int idx = tid; idx < 2048; idx += 256) {
        int hl = idx >> 10, rem = idx & 1023;
        int k = rem >> 4, j = rem & 15;
        int tok = tok_of<STAGE>(g, k);
        const float* bp = qkv + (size_t)tok * 768 + 256 + (blockIdx.y * 2 + hl) * 32;
        float x0 = bp[2 * j], x1 = bp[2 * j + 1];
        float2 cs = g_rope[k * 16 + j];
        float k0 = x0 * cs.x - x1 * cs.y;
        float k1 = x1 * cs.x + x0 * cs.y;
        float r0, r1;
        int base = hl * HS;
        smu2[base + k * 20 + j] = pack_bf16_hi(k0, k1, r0, r1);
        smu2[base + 1280 + k * 20 + j] = pack_bf16(r0, r1);
    }
    for (int idx = tid; idx < 4096; idx += 256) {
        int hl = idx >> 11, rem = idx & 2047;
        int k = rem >> 5, d = rem & 31;
        float v = qkv[(size_t)tok_of<STAGE>(g, k) * 768 + 512 + (blockIdx.y * 2 + hl) * 32 + d];
        smf[hl * HS + 2560 + d * 68 + k] = tf32r(v);
    }

    uint32_t qh[2][4], ql[2][4];
    load_q_frags<STAGE>(qkv, g, h, m_base + tq, tr, qh, ql);
    __syncthreads();

    const uint32_t* KhiB = smu2 + hh * HS;
    const uint32_t* KloB = KhiB + 1280;
    const float* VtB = (const float*)(KhiB + 2560);

    float co[4][4];
    #pragma unroll
    for (int i = 0; i < 4; i++)
        #pragma unroll
        for (int j = 0; j < 4; j++) co[i][j] = 0.0f;
    float mrun0 = -1e30f, mrun1 = -1e30f, lrun0 = 0.0f, lrun1 = 0.0f;

    #pragma unroll
    for (int j0 = 0; j0 < 64; j0 += 32) {
        float sc[4][4];
        #pragma unroll
        for (int nt = 0; nt < 4; nt++) {
            const uint32_t* Krh = KhiB + (j0 + nt * 8 + tq) * 20;
            const uint32_t* Krl = KloB + (j0 + nt * 8 + tq) * 20;
            float c0[4] = {0, 0, 0, 0}, c1[4] = {0, 0, 0, 0}, c2[4] = {0, 0, 0, 0};
            #pragma unroll
            for (int kt = 0; kt < 2; kt++) {
                uint32_t bh[2] = {Krh[kt * 8 + tr], Krh[kt * 8 + tr + 4]};
                uint32_t bl[2] = {Krl[kt * 8 + tr], Krl[kt * 8 + tr + 4]};
                mma_bf16(c0, qh[kt], bh);
                mma_bf16(c1, ql[kt], bh);
                mma_bf16(c2, qh[kt], bl);
            }
            #pragma unroll
            for (int r = 0; r < 4; r++) sc[nt][r] = c0[r] + c1[r] + c2[r];
        }

        float mx0 = -1e30f, mx1 = -1e30f;
        #pragma unroll
        for (int nt = 0; nt < 4; nt++) {
            mx0 = fmaxf(mx0, fmaxf(sc[nt][0], sc[nt][1]));
            mx1 = fmaxf(mx1, fmaxf(sc[nt][2], sc[nt][3]));
        }
        mx0 = fmaxf(mx0, __shfl_xor_sync(0xFFFFFFFFu, mx0, 1));
        mx0 = fmaxf(mx0, __shfl_xor_sync(0xFFFFFFFFu, mx0, 2));
        mx1 = fmaxf(mx1, __shfl_xor_sync(0xFFFFFFFFu, mx1, 1));
        mx1 = fmaxf(mx1, __shfl_xor_sync(0xFFFFFFFFu, mx1, 2));
        float mn0 = fmaxf(mrun0, mx0), mn1 = fmaxf(mrun1, mx1);
        float esc0 = __expf(mrun0 - mn0), esc1 = __expf(mrun1 - mn1);
        float s0 = 0.0f, s1 = 0.0f;
        #pragma unroll
        for (int nt = 0; nt < 4; nt++) {
            float p0 = __expf(sc[nt][0] - mn0);
            float p1 = __expf(sc[nt][1] - mn0);
            float p2 = __expf(sc[nt][2] - mn1);
            float p3 = __expf(sc[nt][3] - mn1);
            s0 += p0 + p1;
            s1 += p2 + p3;
            sc[nt][0] = tf32r(p0);
            sc[nt][1] = tf32r(p1);
            sc[nt][2] = tf32r(p2);
            sc[nt][3] = tf32r(p3);
        }
        s0 += __shfl_xor_sync(0xFFFFFFFFu, s0, 1);
        s0 += __shfl_xor_sync(0xFFFFFFFFu, s0, 2);
        s1 += __shfl_xor_sync(0xFFFFFFFFu, s1, 1);
        s1 += __shfl_xor_sync(0xFFFFFFFFu, s1, 2);
        lrun0 = lrun0 * esc0 + s0;
        lrun1 = lrun1 * esc1 + s1;
        mrun0 = mn0; mrun1 = mn1;
        #pragma unroll
        for (int nt2 = 0; nt2 < 4; nt2++) {
            co[nt2][0] *= esc0; co[nt2][1] *= esc0;
            co[nt2][2] *= esc1; co[nt2][3] *= esc1;
        }

        #pragma unroll
        for (int kt2 = 0; kt2 < 4; kt2++) {
            uint32_t a[4];
            p_frag_shfl(sc[kt2], sl, odd, a);
            int kc = kt2 * 8 + tr;
            #pragma unroll
            for (int nt2 = 0; nt2 < 4; nt2++) {
                const float* vrow = VtB + (nt2 * 8 + tq) * 68 + j0 + kc;
                uint32_t b[2] = {__float_as_uint(vrow[0]), __float_as_uint(vrow[4])};
                mma_tf32(co[nt2], a, b);
            }
        }
    }

    float inv0 = 1.0f / lrun0, inv1 = 1.0f / lrun1;
    int p0r = m_base + tq;
    size_t o0 = (size_t)tok_of<STAGE>(g, p0r) * 256 + h * 32;
    size_t o1 = (size_t)tok_of<STAGE>(g, p0r + 8) * 256 + h * 32;
    #pragma unroll
    for (int nt2 = 0; nt2 < 4; nt2++) {
        int cc = nt2 * 8 + 2 * tr;
        *(float2*)&g_X[o0 + cc] = make_float2(tf32r(co[nt2][0] * inv0), tf32r(co[nt2][1] * inv0));
        *(float2*)&g_X[o1 + cc] = make_float2(tf32r(co[nt2][2] * inv1), tf32r(co[nt2][3] * inv1));
    }
}

// ---------------------------------------------------------------------------
extern "C" void kernel_launch(void* const* d_in, const int* in_sizes, int n_in,
                              void* d_out, int out_size) {
    const float* x  = (const float*)d_in[0];
    const float* W1 = (const float*)d_in[1];
    const float* W2 = (const float*)d_in[2];
    const float* W3 = (const float*)d_in[3];
    const float* Wp = (const float*)d_in[4];
    float* out = (float*)d_out;

    float* Xp;   cudaGetSymbolAddress((void**)&Xp,   g_X);
    float* QKVp; cudaGetSymbolAddress((void**)&QKVp, g_QKV);
    float* Wr;   cudaGetSymbolAddress((void**)&Wr,   g_W);

    const int SMEMG = 3 * 8960 * 4;            // 107520
    const int SMEM64 = 2 * 4736 * 4;           // 37888

    cudaFuncSetAttribute(tf32_gemm_kernel,
                         cudaFuncAttributeMaxDynamicSharedMemorySize, SMEMG);
    cudaFuncSetAttribute(attn64_kernel<2>,
                         cudaFuncAttributeMaxDynamicSharedMemorySize, SMEM64);
    cudaFuncSetAttribute(attn64_kernel<3>,
                         cudaFuncAttributeMaxDynamicSharedMemorySize, SMEM64);

    rope_table_kernel<<<16, 256>>>();
    round_w_kernel<<<2560, 256>>>(W1, W2, W3, Wp);
    permute_in_kernel<<<dim3(512, 8, 4), dim3(32, 8)>>>(x);

    // Stage 1: time-axis attention (S=256), streamed KV
    tf32_gemm_kernel<<<dim3(6, 512), 256, SMEMG>>>(Xp, Wr, QKVp, NT, 768, 256);
    attn1_kernel<<<dim3(256, 8, 2), 256>>>(QKVp);

    // Stage 2: freq-axis attention (S=64)
    tf32_gemm_kernel<<<dim3(6, 512), 256, SMEMG>>>(Xp, Wr + 196608, QKVp, NT, 768, 256);
    attn64_kernel<2><<<dim3(1024, 4), 256, SMEM64>>>(QKVp);

    // Stage 3: windowed attention (S=64)
    tf32_gemm_kernel<<<dim3(6, 512), 256, SMEMG>>>(Xp, Wr + 393216, QKVp, NT, 768, 256);
    attn64_kernel<3><<<dim3(1024, 4), 256, SMEM64>>>(QKVp);

    // Projection
    tf32_gemm_kernel<<<dim3(2, 512), 256, SMEMG>>>(Xp, Wr + 589824, QKVp, NT, 256, 256);

    permute_out_kernel<<<dim3(8, 512, 4), dim3(32, 8)>>>(out);
}

// round 11
// speedup vs baseline: 4.2539x; 1.3673x over previous
#include <cuda_runtime.h>
#include <cuda_bf16.h>
#include <cuda_fp16.h>
#include <math.h>
#include <stdint.h>

// Problem constants
#define BB 4
#define DD 256
#define TT 256
#define FF 64
#define HH 8
#define HD 32
#define NT (BB*TT*FF)          // 65536 tokens

// Scratch (no allocations allowed -> device globals)
__device__ __half g_Xh[(size_t)NT * DD];      // activations fp16 [tok][256]
__device__ float g_QKV[(size_t)NT * 3 * DD];  // qkv / proj output (f32)
__device__ __half g_W[655360];                // weights fp16, B-layout [n][k]
__device__ float2 g_rope[256 * 16];           // cos/sin table [pos][j]

// ---------------------------------------------------------------------------
// Helpers
// ---------------------------------------------------------------------------
__device__ __forceinline__ void mma_f16(float* c, const uint32_t* a, const uint32_t* b) {
    asm volatile(
        "mma.sync.aligned.m16n8k16.row.col.f32.f16.f16.f32 "
        "{%0,%1,%2,%3}, {%4,%5,%6,%7}, {%8,%9}, {%0,%1,%2,%3};"
        : "+f"(c[0]), "+f"(c[1]), "+f"(c[2]), "+f"(c[3])
        : "r"(a[0]), "r"(a[1]), "r"(a[2]), "r"(a[3]), "r"(b[0]), "r"(b[1]));
}

__device__ __forceinline__ void mma_bf16(float* c, const uint32_t* a, const uint32_t* b) {
    asm volatile(
        "mma.sync.aligned.m16n8k16.row.col.f32.bf16.bf16.f32 "
        "{%0,%1,%2,%3}, {%4,%5,%6,%7}, {%8,%9}, {%0,%1,%2,%3};"
        : "+f"(c[0]), "+f"(c[1]), "+f"(c[2]), "+f"(c[3])
        : "r"(a[0]), "r"(a[1]), "r"(a[2]), "r"(a[3]), "r"(b[0]), "r"(b[1]));
}

__device__ __forceinline__ uint32_t pack_bf16_hi(float x0, float x1, float& r0, float& r1) {
    __nv_bfloat16 h0 = __float2bfloat16(x0);
    __nv_bfloat16 h1 = __float2bfloat16(x1);
    r0 = x0 - __bfloat162float(h0);
    r1 = x1 - __bfloat162float(h1);
    __nv_bfloat162 p = {h0, h1};
    return *(uint32_t*)&p;
}
__device__ __forceinline__ uint32_t pack_bf16(float x0, float x1) {
    __nv_bfloat162 p = {__float2bfloat16(x0), __float2bfloat16(x1)};
    return *(uint32_t*)&p;
}
__device__ __forceinline__ uint32_t pack_half2(float x0, float x1) {
    __half2 p = __floats2half2_rn(x0, x1);
    return *(uint32_t*)&p;
}

// cp.async helpers
__device__ __forceinline__ void cp_async16(uint32_t saddr, const void* g) {
    asm volatile("cp.async.cg.shared.global [%0], [%1], 16;" :: "r"(saddr), "l"(g));
}
__device__ __forceinline__ void cp_commit() {
    asm volatile("cp.async.commit_group;");
}
template <int N> __device__ __forceinline__ void cp_wait() {
    asm volatile("cp.async.wait_group %0;" :: "n"(N));
}
__device__ __forceinline__ uint32_t smem_u32(const void* p) {
    uint32_t a;
    asm("{ .reg .u64 t; cvta.to.shared.u64 t, %1; cvt.u32.u64 %0, t; }" : "=r"(a) : "l"(p));
    return a;
}

// ---------------------------------------------------------------------------
// RoPE table + weight prep (fp16, transposed to B-layout [n][k])
// ---------------------------------------------------------------------------
__global__ __launch_bounds__(256) void rope_table_kernel() {
    int i = blockIdx.x * 256 + threadIdx.x;   // 4096
    int p = i >> 4, j = i & 15;
    const float CEXP = 0.830482023721841f;
    float inv = exp2f(-(float)j * CEXP);
    float sn, cs;
    sincosf((float)p * inv, &sn, &cs);
    g_rope[i] = make_float2(cs, sn);
}

__global__ __launch_bounds__(256) void round_w_kernel(
    const float* __restrict__ W1, const float* __restrict__ W2,
    const float* __restrict__ W3, const float* __restrict__ Wp) {
    int i = blockIdx.x * 256 + threadIdx.x;   // 655360
    const float* src; int N; int base;
    if (i < 196608)      { src = W1; N = 768; base = 0; }
    else if (i < 393216) { src = W2; N = 768; base = 196608; }
    else if (i < 589824) { src = W3; N = 768; base = 393216; }
    else                 { src = Wp; N = 256; base = 589824; }
    int j = i - base;
    int n = j >> 8, k = j & 255;
    g_W[i] = __float2half(src[k * N + n]);
}

// ---------------------------------------------------------------------------
// Permutes
// ---------------------------------------------------------------------------
__global__ __launch_bounds__(256) void permute_in_kernel(const float* __restrict__ x) {
    __shared__ float tile[32][33];
    const int b = blockIdx.z;
    const int tf0 = blockIdx.x * 32;
    const int d0 = blockIdx.y * 32;
    const int tx = threadIdx.x, ty = threadIdx.y;
    #pragma unroll
    for (int i = 0; i < 4; i++)
        tile[ty + 8 * i][tx] = x[((size_t)(b * 256 + d0 + ty + 8 * i) * 16384) + tf0 + tx];
    __syncthreads();
    #pragma unroll
    for (int i = 0; i < 4; i++)
        g_Xh[((size_t)(b * 16384 + tf0 + ty + 8 * i)) * 256 + d0 + tx] =
            __float2half(tile[tx][ty + 8 * i]);
}

__global__ __launch_bounds__(256) void permute_out_kernel(float* __restrict__ out) {
    __shared__ float tile[32][33];
    const int b = blockIdx.z;
    const int d0 = blockIdx.x * 32;
    const int tf0 = blockIdx.y * 32;
    const int tx = threadIdx.x, ty = threadIdx.y;
    #pragma unroll
    for (int i = 0; i < 4; i++)
        tile[ty + 8 * i][tx] = g_QKV[((size_t)(b * 16384 + tf0 + ty + 8 * i)) * 256 + d0 + tx];
    __syncthreads();
    #pragma unroll
    for (int i = 0; i < 4; i++)
        out[((size_t)(b * 256 + d0 + ty + 8 * i) * 16384) + tf0 + tx] = tile[tx][ty + 8 * i];
}

// ---------------------------------------------------------------------------
// FP16 GEMM, cp.async 3-stage: C[M,N] = A[M,256] @ B[N,256]^T.
// A,B fp16 u32-packed pairs in smem; tile 128x128x32; 8 warps of 64x32.
// Stage (u32): As[128][20] | Bs[128][20] = 5120 u32 = 20480 B.
// ---------------------------------------------------------------------------
__global__ __launch_bounds__(256, 2) void fp16_gemm_kernel(
    const __half* __restrict__ A, const __half* __restrict__ B,
    float* __restrict__ C, int N)
{
    extern __shared__ uint32_t smg[];
    const uint32_t smem_addr = smem_u32(smg);

    const int tid = threadIdx.x;
    const int wid = tid >> 5;
    const int lane = tid & 31;
    const int tq = lane >> 2;
    const int tr = lane & 3;
    const int warp_m = (wid & 1) * 64;
    const int warp_n = (wid >> 1) * 32;
    const int bx = blockIdx.x * 128;
    const int by = blockIdx.y * 128;

    float acc[4][4][4];
    #pragma unroll
    for (int i = 0; i < 4; i++)
        #pragma unroll
        for (int j = 0; j < 4; j++)
            #pragma unroll
            for (int r = 0; r < 4; r++) acc[i][j][r] = 0.0f;

    const char* Ag = (const char*)(A + (size_t)by * 256);
    const char* Bg = (const char*)(B + (size_t)bx * 256);

    auto issue = [&](int kt, int s) {
        uint32_t stA = smem_addr + s * 20480;
        uint32_t stB = stA + 10240;
        #pragma unroll
        for (int r = 0; r < 2; r++) {
            int idx = tid + r * 256;          // 0..511
            int row = idx >> 2, cc = idx & 3;
            cp_async16(stA + row * 80 + cc * 16, Ag + (size_t)row * 512 + kt * 64 + cc * 16);
            cp_async16(stB + row * 80 + cc * 16, Bg + (size_t)row * 512 + kt * 64 + cc * 16);
        }
        cp_commit();
    };

    const int nt = 8;   // K=256 / 32
    issue(0, 0);
    issue(1, 1);
    cp_wait<1>();
    __syncthreads();

    for (int kt = 0; kt < nt; kt++) {
        const uint32_t* As = smg + (kt % 3) * 5120;
        const uint32_t* Bs = As + 2560;

        #pragma unroll
        for (int s = 0; s < 2; s++) {
            const int ks = s * 8;
            uint32_t a[4][4], b[4][2];
            #pragma unroll
            for (int i = 0; i < 4; i++) {
                int row = warp_m + i * 16 + tq;
                a[i][0] = As[row * 20 + ks + tr];
                a[i][1] = As[(row + 8) * 20 + ks + tr];
                a[i][2] = As[row * 20 + ks + tr + 4];
                a[i][3] = As[(row + 8) * 20 + ks + tr + 4];
            }
            #pragma unroll
            for (int j = 0; j < 4; j++) {
                int col = warp_n + j * 8 + tq;
                b[j][0] = Bs[col * 20 + ks + tr];
                b[j][1] = Bs[col * 20 + ks + tr + 4];
            }
            #pragma unroll
            for (int i = 0; i < 4; i++)
                #pragma unroll
                for (int j = 0; j < 4; j++)
                    mma_f16(acc[i][j], a[i], b[j]);
        }

        if (kt + 1 < nt) {
            if (kt + 2 < nt) {
                issue(kt + 2, (kt + 2) % 3);
                cp_wait<1>();
            } else {
                cp_wait<0>();
            }
            __syncthreads();
        }
    }

    #pragma unroll
    for (int i = 0; i < 4; i++) {
        int row0 = by + warp_m + i * 16 + tq;
        #pragma unroll
        for (int j = 0; j < 4; j++) {
            int col0 = bx + warp_n + j * 8 + 2 * tr;
            *(float2*)&C[(size_t)row0 * N + col0] = make_float2(acc[i][j][0], acc[i][j][1]);
            *(float2*)&C[(size_t)(row0 + 8) * N + col0] = make_float2(acc[i][j][2], acc[i][j][3]);
        }
    }
}

// ---------------------------------------------------------------------------
// Token index per stage.
// ---------------------------------------------------------------------------
template <int STAGE>
__device__ __forceinline__ int tok_of(int g, int p) {
    if (STAGE == 1) {
        int b = g >> 6, f = g & 63;
        return (b * 256 + p) * 64 + f;
    } else if (STAGE == 2) {
        return g * 64 + p;
    } else {
        int b = g >> 8, rem = g & 255;
        int i = rem >> 3, jf = rem & 7;
        int t = i * 8 + (p >> 3);
        int f = jf * 8 + (p & 7);
        return (b * 256 + t) * 64 + f;
    }
}

// ---------------------------------------------------------------------------
// Q fragments: bf16-split, built directly from gmem.
// ---------------------------------------------------------------------------
template <int STAGE>
__device__ __forceinline__ void load_q_frags(
    const float* __restrict__ qkv, int g, int h, int p0,
    int tr, uint32_t qh[2][4], uint32_t ql[2][4])
{
    const float SCALE = 0.17677669529663687f;
    #pragma unroll
    for (int kt = 0; kt < 2; kt++)
        #pragma unroll
        for (int hv = 0; hv < 2; hv++) {
            int j = kt * 8 + tr + 4 * hv;
            #pragma unroll
            for (int rr = 0; rr < 2; rr++) {
                int p = p0 + rr * 8;
                int tok = tok_of<STAGE>(g, p);
                float2 q = *(const float2*)(qkv + (size_t)tok * 768 + h * 32 + 2 * j);
                float2 cs = g_rope[p * 16 + j];
                float q0 = (q.x * cs.x - q.y * cs.y) * SCALE;
                float q1 = (q.y * cs.x + q.x * cs.y) * SCALE;
                float r0, r1;
                qh[kt][hv * 2 + rr] = pack_bf16_hi(q0, q1, r0, r1);
                ql[kt][hv * 2 + rr] = pack_bf16(r0, r1);
            }
        }
}

// X writer: fp16 pair
__device__ __forceinline__ void write_x_pair(size_t o, float v0, float v1) {
    *(uint32_t*)&g_Xh[o] = pack_half2(v0, v1);
}

// ---------------------------------------------------------------------------
// Stage-1 attention: S=256, streamed KV; scores bf16-split, PV fp16-k16.
// BUF per chunk (u32): Khi 640 | Klo 640 | V 640 (32 d x 20).
// ---------------------------------------------------------------------------
__global__ __launch_bounds__(256, 3) void attn1_kernel(const float* __restrict__ qkv) {
    constexpr int BUF = 1920;
    __shared__ uint32_t smu[2 * BUF];

    const int g = blockIdx.x;
    const int h = blockIdx.y;
    const int qoff = blockIdx.z * 128;
    const int tid = threadIdx.x;
    const int w = tid >> 5, lane = tid & 31, tq = lane >> 2, tr = lane & 3;
    const int m_base = w * 16;

    uint32_t qh[2][4], ql[2][4];
    load_q_frags<1>(qkv, g, h, qoff + m_base + tq, tr, qh, ql);

    const int kj = tid & 15;
    const int kk0 = tid >> 4;
    const int vd = tid & 31;
    const int vp0 = tid >> 5;      // half2-pair base
    float2 kx[2];
    float2 vx[2];

    auto load_chunk = [&](int c) {
        int kb = c * 32;
        #pragma unroll
        for (int r = 0; r < 2; r++) {
            int tok = tok_of<1>(g, kb + r * 16 + kk0);
            kx[r] = *(const float2*)(qkv + (size_t)tok * 768 + 256 + h * 32 + 2 * kj);
        }
        #pragma unroll
        for (int r = 0; r < 2; r++) {
            int kp = r * 8 + vp0;
            vx[r].x = qkv[(size_t)tok_of<1>(g, kb + 2 * kp) * 768 + 512 + h * 32 + vd];
            vx[r].y = qkv[(size_t)tok_of<1>(g, kb + 2 * kp + 1) * 768 + 512 + h * 32 + vd];
        }
    };
    auto store_chunk = [&](int c, int base) {
        int kb = c * 32;
        #pragma unroll
        for (int r = 0; r < 2; r++) {
            int k = r * 16 + kk0;
            float2 cs = g_rope[(kb + k) * 16 + kj];
            float k0 = kx[r].x * cs.x - kx[r].y * cs.y;
            float k1 = kx[r].y * cs.x + kx[r].x * cs.y;
            float r0, r1;
            smu[base + k * 20 + kj] = pack_bf16_hi(k0, k1, r0, r1);
            smu[base + 640 + k * 20 + kj] = pack_bf16(r0, r1);
        }
        #pragma unroll
        for (int r = 0; r < 2; r++) {
            int kp = r * 8 + vp0;
            smu[base + 1280 + vd * 20 + kp] = pack_half2(vx[r].x, vx[r].y);
        }
    };

    load_chunk(0);
    store_chunk(0, 0);
    __syncthreads();

    float co[4][4];
    #pragma unroll
    for (int i = 0; i < 4; i++)
        #pragma unroll
        for (int j = 0; j < 4; j++) co[i][j] = 0.0f;
    float mrun0 = -1e30f, mrun1 = -1e30f, lrun0 = 0.0f, lrun1 = 0.0f;

    for (int c = 0; c < 8; c++) {
        const uint32_t* Khi = smu + (c & 1) * BUF;
        const uint32_t* Klo = Khi + 640;
        const uint32_t* Vt = Khi + 1280;

        if (c < 7) load_chunk(c + 1);

        float sc[4][4];
        #pragma unroll
        for (int nt = 0; nt < 4; nt++) {
            const uint32_t* Krh = Khi + (nt * 8 + tq) * 20;
            const uint32_t* Krl = Klo + (nt * 8 + tq) * 20;
            float c0[4] = {0, 0, 0, 0}, c1[4] = {0, 0, 0, 0}, c2[4] = {0, 0, 0, 0};
            #pragma unroll
            for (int kt = 0; kt < 2; kt++) {
                uint32_t bh[2] = {Krh[kt * 8 + tr], Krh[kt * 8 + tr + 4]};
                uint32_t bl[2] = {Krl[kt * 8 + tr], Krl[kt * 8 + tr + 4]};
                mma_bf16(c0, qh[kt], bh);
                mma_bf16(c1, ql[kt], bh);
                mma_bf16(c2, qh[kt], bl);
            }
            #pragma unroll
            for (int r = 0; r < 4; r++) sc[nt][r] = c0[r] + c1[r] + c2[r];
        }

        float mx0 = -1e30f, mx1 = -1e30f;
        #pragma unroll
        for (int nt = 0; nt < 4; nt++) {
            mx0 = fmaxf(mx0, fmaxf(sc[nt][0], sc[nt][1]));
            mx1 = fmaxf(mx1, fmaxf(sc[nt][2], sc[nt][3]));
        }
        mx0 = fmaxf(mx0, __shfl_xor_sync(0xFFFFFFFFu, mx0, 1));
        mx0 = fmaxf(mx0, __shfl_xor_sync(0xFFFFFFFFu, mx0, 2));
        mx1 = fmaxf(mx1, __shfl_xor_sync(0xFFFFFFFFu, mx1, 1));
        mx1 = fmaxf(mx1, __shfl_xor_sync(0xFFFFFFFFu, mx1, 2));
        float mn0 = fmaxf(mrun0, mx0), mn1 = fmaxf(mrun1, mx1);
        float esc0 = __expf(mrun0 - mn0), esc1 = __expf(mrun1 - mn1);
        float s0 = 0.0f, s1 = 0.0f;
        #pragma unroll
        for (int nt = 0; nt < 4; nt++) {
            sc[nt][0] = __expf(sc[nt][0] - mn0);
            sc[nt][1] = __expf(sc[nt][1] - mn0);
            sc[nt][2] = __expf(sc[nt][2] - mn1);
            sc[nt][3] = __expf(sc[nt][3] - mn1);
            s0 += sc[nt][0] + sc[nt][1];
            s1 += sc[nt][2] + sc[nt][3];
        }
        s0 += __shfl_xor_sync(0xFFFFFFFFu, s0, 1);
        s0 += __shfl_xor_sync(0xFFFFFFFFu, s0, 2);
        s1 += __shfl_xor_sync(0xFFFFFFFFu, s1, 1);
        s1 += __shfl_xor_sync(0xFFFFFFFFu, s1, 2);
        lrun0 = lrun0 * esc0 + s0;
        lrun1 = lrun1 * esc1 + s1;
        mrun0 = mn0; mrun1 = mn1;
        #pragma unroll
        for (int nt2 = 0; nt2 < 4; nt2++) {
            co[nt2][0] *= esc0; co[nt2][1] *= esc0;
            co[nt2][2] *= esc1; co[nt2][3] *= esc1;
        }

        // PV fp16: a-frags packed straight from score C-frags
        #pragma unroll
        for (int kt2 = 0; kt2 < 2; kt2++) {
            uint32_t a[4];
            a[0] = pack_half2(sc[2 * kt2][0], sc[2 * kt2][1]);
            a[1] = pack_half2(sc[2 * kt2][2], sc[2 * kt2][3]);
            a[2] = pack_half2(sc[2 * kt2 + 1][0], sc[2 * kt2 + 1][1]);
            a[3] = pack_half2(sc[2 * kt2 + 1][2], sc[2 * kt2 + 1][3]);
            #pragma unroll
            for (int nt2 = 0; nt2 < 4; nt2++) {
                const uint32_t* vr = Vt + (nt2 * 8 + tq) * 20 + kt2 * 8 + tr;
                uint32_t b[2] = {vr[0], vr[4]};
                mma_f16(co[nt2], a, b);
            }
        }

        if (c < 7) store_chunk(c + 1, ((c + 1) & 1) * BUF);
        __syncthreads();
    }

    float inv0 = 1.0f / lrun0, inv1 = 1.0f / lrun1;
    int p0r = qoff + m_base + tq;
    size_t o0 = (size_t)tok_of<1>(g, p0r) * 256 + h * 32;
    size_t o1 = (size_t)tok_of<1>(g, p0r + 8) * 256 + h * 32;
    #pragma unroll
    for (int nt2 = 0; nt2 < 4; nt2++) {
        int cc = nt2 * 8 + 2 * tr;
        write_x_pair(o0 + cc, co[nt2][0] * inv0, co[nt2][1] * inv0);
        write_x_pair(o1 + cc, co[nt2][2] * inv1, co[nt2][3] * inv1);
    }
}

// ---------------------------------------------------------------------------
// Stage-2/3 attention: S=64, 2 heads per block; PV fp16, V packed half2.
// HS (u32): Khi 1280 | Klo 1280 | V 1152 (32 d x 36).
// ---------------------------------------------------------------------------
template <int STAGE>
__global__ __launch_bounds__(256, 3) void attn64_kernel(const float* __restrict__ qkv) {
    constexpr int HS = 3712;
    extern __shared__ uint32_t smu2[];

    const int g = blockIdx.x;
    const int tid = threadIdx.x;
    const int w = tid >> 5, lane = tid & 31, tq = lane >> 2, tr = lane & 3;
    const int hh = w >> 2;
    const int h = blockIdx.y * 2 + hh;
    const int m_base = (w & 3) * 16;

    for (int idx = tid; idx < 2048; idx += 256) {
        int hl = idx >> 10, rem = idx & 1023;
        int k = rem >> 4, j = rem & 15;
        int tok = tok_of<STAGE>(g, k);
        const float* bp = qkv + (size_t)tok * 768 + 256 + (blockIdx.y * 2 + hl) * 32;
        float x0 = bp[2 * j], x1 = bp[2 * j + 1];
        float2 cs = g_rope[k * 16 + j];
        float k0 = x0 * cs.x - x1 * cs.y;
        float k1 = x1 * cs.x + x0 * cs.y;
        float r0, r1;
        int base = hl * HS;
        smu2[base + k * 20 + j] = pack_bf16_hi(k0, k1, r0, r1);
        smu2[base + 1280 + k * 20 + j] = pack_bf16(r0, r1);
    }
    // V: 2 heads x 32 pairs x 32 dims
    for (int idx = tid; idx < 2048; idx += 256) {
        int hl = idx >> 10, rem = idx & 1023;
        int kp = rem >> 5, d = rem & 31;
        int hcur = blockIdx.y * 2 + hl;
        float v0 = qkv[(size_t)tok_of<STAGE>(g, 2 * kp) * 768 + 512 + hcur * 32 + d];
        float v1 = qkv[(size_t)tok_of<STAGE>(g, 2 * kp + 1) * 768 + 512 + hcur * 32 + d];
        smu2[hl * HS + 2560 + d * 36 + kp] = pack_half2(v0, v1);
    }

    uint32_t qh[2][4], ql[2][4];
    load_q_frags<STAGE>(qkv, g, h, m_base + tq, tr, qh, ql);
    __syncthreads();

    const uint32_t* KhiB = smu2 + hh * HS;
    const uint32_t* KloB = KhiB + 1280;
    const uint32_t* VtB = KhiB + 2560;

    float co[4][4];
    #pragma unroll
    for (int i = 0; i < 4; i++)
        #pragma unroll
        for (int j = 0; j < 4; j++) co[i][j] = 0.0f;
    float mrun0 = -1e30f, mrun1 = -1e30f, lrun0 = 0.0f, lrun1 = 0.0f;

    #pragma unroll
    for (int j0 = 0; j0 < 64; j0 += 32) {
        float sc[4][4];
        #pragma unroll
        for (int nt = 0; nt < 4; nt++) {
            const uint32_t* Krh = KhiB + (j0 + nt * 8 + tq) * 20;
            const uint32_t* Krl = KloB + (j0 + nt * 8 + tq) * 20;
            float c0[4] = {0, 0, 0, 0}, c1[4] = {0, 0, 0, 0}, c2[4] = {0, 0, 0, 0};
            #pragma unroll
            for (int kt = 0; kt < 2; kt++) {
                uint32_t bh[2] = {Krh[kt * 8 + tr], Krh[kt * 8 + tr + 4]};
                uint32_t bl[2] = {Krl[kt * 8 + tr], Krl[kt * 8 + tr + 4]};
                mma_bf16(c0, qh[kt], bh);
                mma_bf16(c1, ql[kt], bh);
                mma_bf16(c2, qh[kt], bl);
            }
            #pragma unroll
            for (int r = 0; r < 4; r++) sc[nt][r] = c0[r] + c1[r] + c2[r];
        }

        float mx0 = -1e30f, mx1 = -1e30f;
        #pragma unroll
        for (int nt = 0; nt < 4; nt++) {
            mx0 = fmaxf(mx0, fmaxf(sc[nt][0], sc[nt][1]));
            mx1 = fmaxf(mx1, fmaxf(sc[nt][2], sc[nt][3]));
        }
        mx0 = fmaxf(mx0, __shfl_xor_sync(0xFFFFFFFFu, mx0, 1));
        mx0 = fmaxf(mx0, __shfl_xor_sync(0xFFFFFFFFu, mx0, 2));
        mx1 = fmaxf(mx1, __shfl_xor_sync(0xFFFFFFFFu, mx1, 1));
        mx1 = fmaxf(mx1, __shfl_xor_sync(0xFFFFFFFFu, mx1, 2));
        float mn0 = fmaxf(mrun0, mx0), mn1 = fmaxf(mrun1, mx1);
        float esc0 = __expf(mrun0 - mn0), esc1 = __expf(mrun1 - mn1);
        float s0 = 0.0f, s1 = 0.0f;
        #pragma unroll
        for (int nt = 0; nt < 4; nt++) {
            sc[nt][0] = __expf(sc[nt][0] - mn0);
            sc[nt][1] = __expf(sc[nt][1] - mn0);
            sc[nt][2] = __expf(sc[nt][2] - mn1);
            sc[nt][3] = __expf(sc[nt][3] - mn1);
            s0 += sc[nt][0] + sc[nt][1];
            s1 += sc[nt][2] + sc[nt][3];
        }
        s0 += __shfl_xor_sync(0xFFFFFFFFu, s0, 1);
        s0 += __shfl_xor_sync(0xFFFFFFFFu, s0, 2);
        s1 += __shfl_xor_sync(0xFFFFFFFFu, s1, 1);
        s1 += __shfl_xor_sync(0xFFFFFFFFu, s1, 2);
        lrun0 = lrun0 * esc0 + s0;
        lrun1 = lrun1 * esc1 + s1;
        mrun0 = mn0; mrun1 = mn1;
        #pragma unroll
        for (int nt2 = 0; nt2 < 4; nt2++) {
            co[nt2][0] *= esc0; co[nt2][1] *= esc0;
            co[nt2][2] *= esc1; co[nt2][3] *= esc1;
        }

        #pragma unroll
        for (int kt2 = 0; kt2 < 2; kt2++) {
            uint32_t a[4];
            a[0] = pack_half2(sc[2 * kt2][0], sc[2 * kt2][1]);
            a[1] = pack_half2(sc[2 * kt2][2], sc[2 * kt2][3]);
            a[2] = pack_half2(sc[2 * kt2 + 1][0], sc[2 * kt2 + 1][1]);
            a[3] = pack_half2(sc[2 * kt2 + 1][2], sc[2 * kt2 + 1][3]);
            #pragma unroll
            for (int nt2 = 0; nt2 < 4; nt2++) {
                const uint32_t* vr = VtB + (nt2 * 8 + tq) * 36 + (j0 >> 1) + kt2 * 8 + tr;
                uint32_t b[2] = {vr[0], vr[4]};
                mma_f16(co[nt2], a, b);
            }
        }
    }

    float inv0 = 1.0f / lrun0, inv1 = 1.0f / lrun1;
    int p0r = m_base + tq;
    size_t o0 = (size_t)tok_of<STAGE>(g, p0r) * 256 + h * 32;
    size_t o1 = (size_t)tok_of<STAGE>(g, p0r + 8) * 256 + h * 32;
    #pragma unroll
    for (int nt2 = 0; nt2 < 4; nt2++) {
        int cc = nt2 * 8 + 2 * tr;
        write_x_pair(o0 + cc, co[nt2][0] * inv0, co[nt2][1] * inv0);
        write_x_pair(o1 + cc, co[nt2][2] * inv1, co[nt2][3] * inv1);
    }
}

// ---------------------------------------------------------------------------
extern "C" void kernel_launch(void* const* d_in, const int* in_sizes, int n_in,
                              void* d_out, int out_size) {
    const float* x  = (const float*)d_in[0];
    const float* W1 = (const float*)d_in[1];
    const float* W2 = (const float*)d_in[2];
    const float* W3 = (const float*)d_in[3];
    const float* Wp = (const float*)d_in[4];
    float* out = (float*)d_out;

    __half* Xh; cudaGetSymbolAddress((void**)&Xh, g_Xh);
    __half* Wr; cudaGetSymbolAddress((void**)&Wr, g_W);
    float* QKVp; cudaGetSymbolAddress((void**)&QKVp, g_QKV);

    const int SMEMG = 3 * 20480;               // 61440
    const int SMEM64 = 2 * 3712 * 4;           // 29696

    cudaFuncSetAttribute(fp16_gemm_kernel,
                         cudaFuncAttributeMaxDynamicSharedMemorySize, SMEMG);
    cudaFuncSetAttribute(attn64_kernel<2>,
                         cudaFuncAttributeMaxDynamicSharedMemorySize, SMEM64);
    cudaFuncSetAttribute(attn64_kernel<3>,
                         cudaFuncAttributeMaxDynamicSharedMemorySize, SMEM64);

    rope_table_kernel<<<16, 256>>>();
    round_w_kernel<<<2560, 256>>>(W1, W2, W3, Wp);
    permute_in_kernel<<<dim3(512, 8, 4), dim3(32, 8)>>>(x);

    // Stage 1: time-axis attention (S=256)
    fp16_gemm_kernel<<<dim3(6, 512), 256, SMEMG>>>(Xh, Wr, QKVp, 768);
    attn1_kernel<<<dim3(256, 8, 2), 256>>>(QKVp);

    // Stage 2: freq-axis attention (S=64)
    fp16_gemm_kernel<<<dim3(6, 512), 256, SMEMG>>>(Xh, Wr + 196608, QKVp, 768);
    attn64_kernel<2><<<dim3(1024, 4), 256, SMEM64>>>(QKVp);

    // Stage 3: windowed attention (S=64)
    fp16_gemm_kernel<<<dim3(6, 512), 256, SMEMG>>>(Xh, Wr + 393216, QKVp, 768);
    attn64_kernel<3><<<dim3(1024, 4), 256, SMEM64>>>(QKVp);

    // Projection
    fp16_gemm_kernel<<<dim3(2, 512), 256, SMEMG>>>(Xh, Wr + 589824, QKVp, 256);

    permute_out_kernel<<<dim3(8, 512, 4), dim3(32, 8)>>>(out);
}

// round 12
// speedup vs baseline: 4.3783x; 1.0292x over previous
#include <cuda_runtime.h>
#include <cuda_bf16.h>
#include <cuda_fp16.h>
#include <math.h>
#include <stdint.h>

// Problem constants
#define BB 4
#define DD 256
#define TT 256
#define FF 64
#define HH 8
#define HD 32
#define NT (BB*TT*FF)          // 65536 tokens

// Scratch (no allocations allowed -> device globals)
__device__ __half g_Xh[(size_t)NT * DD];      // activations fp16 [tok][256]
__device__ float g_QKV[(size_t)NT * 3 * DD];  // qkv / proj output (f32)
__device__ __half g_W[655360];                // weights fp16, B-layout [n][k]
__device__ float2 g_rope[256 * 16];           // cos/sin table [pos][j]

// ---------------------------------------------------------------------------
// Helpers
// ---------------------------------------------------------------------------
__device__ __forceinline__ void mma_f16(float* c, const uint32_t* a, const uint32_t* b) {
    asm volatile(
        "mma.sync.aligned.m16n8k16.row.col.f32.f16.f16.f32 "
        "{%0,%1,%2,%3}, {%4,%5,%6,%7}, {%8,%9}, {%0,%1,%2,%3};"
        : "+f"(c[0]), "+f"(c[1]), "+f"(c[2]), "+f"(c[3])
        : "r"(a[0]), "r"(a[1]), "r"(a[2]), "r"(a[3]), "r"(b[0]), "r"(b[1]));
}

__device__ __forceinline__ void mma_bf16(float* c, const uint32_t* a, const uint32_t* b) {
    asm volatile(
        "mma.sync.aligned.m16n8k16.row.col.f32.bf16.bf16.f32 "
        "{%0,%1,%2,%3}, {%4,%5,%6,%7}, {%8,%9}, {%0,%1,%2,%3};"
        : "+f"(c[0]), "+f"(c[1]), "+f"(c[2]), "+f"(c[3])
        : "r"(a[0]), "r"(a[1]), "r"(a[2]), "r"(a[3]), "r"(b[0]), "r"(b[1]));
}

__device__ __forceinline__ void ldsm_x4(uint32_t& r0, uint32_t& r1, uint32_t& r2,
                                        uint32_t& r3, uint32_t addr) {
    asm volatile("ldmatrix.sync.aligned.m8n8.x4.shared.b16 {%0,%1,%2,%3}, [%4];"
                 : "=r"(r0), "=r"(r1), "=r"(r2), "=r"(r3) : "r"(addr));
}
__device__ __forceinline__ void ldsm_x2(uint32_t& r0, uint32_t& r1, uint32_t addr) {
    asm volatile("ldmatrix.sync.aligned.m8n8.x2.shared.b16 {%0,%1}, [%2];"
                 : "=r"(r0), "=r"(r1) : "r"(addr));
}

__device__ __forceinline__ uint32_t pack_bf16_hi(float x0, float x1, float& r0, float& r1) {
    __nv_bfloat16 h0 = __float2bfloat16(x0);
    __nv_bfloat16 h1 = __float2bfloat16(x1);
    r0 = x0 - __bfloat162float(h0);
    r1 = x1 - __bfloat162float(h1);
    __nv_bfloat162 p = {h0, h1};
    return *(uint32_t*)&p;
}
__device__ __forceinline__ uint32_t pack_bf16(float x0, float x1) {
    __nv_bfloat162 p = {__float2bfloat16(x0), __float2bfloat16(x1)};
    return *(uint32_t*)&p;
}
__device__ __forceinline__ uint32_t pack_half2(float x0, float x1) {
    __half2 p = __floats2half2_rn(x0, x1);
    return *(uint32_t*)&p;
}

// cp.async helpers
__device__ __forceinline__ void cp_async16(uint32_t saddr, const void* g) {
    asm volatile("cp.async.cg.shared.global [%0], [%1], 16;" :: "r"(saddr), "l"(g));
}
__device__ __forceinline__ void cp_commit() {
    asm volatile("cp.async.commit_group;");
}
template <int N> __device__ __forceinline__ void cp_wait() {
    asm volatile("cp.async.wait_group %0;" :: "n"(N));
}
__device__ __forceinline__ uint32_t smem_u32(const void* p) {
    uint32_t a;
    asm("{ .reg .u64 t; cvta.to.shared.u64 t, %1; cvt.u32.u64 %0, t; }" : "=r"(a) : "l"(p));
    return a;
}

// ---------------------------------------------------------------------------
// RoPE table + weight prep (fp16, transposed to B-layout [n][k])
// ---------------------------------------------------------------------------
__global__ __launch_bounds__(256) void rope_table_kernel() {
    int i = blockIdx.x * 256 + threadIdx.x;   // 4096
    int p = i >> 4, j = i & 15;
    const float CEXP = 0.830482023721841f;
    float inv = exp2f(-(float)j * CEXP);
    float sn, cs;
    sincosf((float)p * inv, &sn, &cs);
    g_rope[i] = make_float2(cs, sn);
}

__global__ __launch_bounds__(256) void round_w_kernel(
    const float* __restrict__ W1, const float* __restrict__ W2,
    const float* __restrict__ W3, const float* __restrict__ Wp) {
    int i = blockIdx.x * 256 + threadIdx.x;   // 655360
    const float* src; int N; int base;
    if (i < 196608)      { src = W1; N = 768; base = 0; }
    else if (i < 393216) { src = W2; N = 768; base = 196608; }
    else if (i < 589824) { src = W3; N = 768; base = 393216; }
    else                 { src = Wp; N = 256; base = 589824; }
    int j = i - base;
    int n = j >> 8, k = j & 255;
    g_W[i] = __float2half(src[k * N + n]);
}

// ---------------------------------------------------------------------------
// Permutes
// ---------------------------------------------------------------------------
__global__ __launch_bounds__(256) void permute_in_kernel(const float* __restrict__ x) {
    __shared__ float tile[32][33];
    const int b = blockIdx.z;
    const int tf0 = blockIdx.x * 32;
    const int d0 = blockIdx.y * 32;
    const int tx = threadIdx.x, ty = threadIdx.y;
    #pragma unroll
    for (int i = 0; i < 4; i++)
        tile[ty + 8 * i][tx] = x[((size_t)(b * 256 + d0 + ty + 8 * i) * 16384) + tf0 + tx];
    __syncthreads();
    #pragma unroll
    for (int i = 0; i < 4; i++)
        g_Xh[((size_t)(b * 16384 + tf0 + ty + 8 * i)) * 256 + d0 + tx] =
            __float2half(tile[tx][ty + 8 * i]);
}

__global__ __launch_bounds__(256) void permute_out_kernel(float* __restrict__ out) {
    __shared__ float tile[32][33];
    const int b = blockIdx.z;
    const int d0 = blockIdx.x * 32;
    const int tf0 = blockIdx.y * 32;
    const int tx = threadIdx.x, ty = threadIdx.y;
    #pragma unroll
    for (int i = 0; i < 4; i++)
        tile[ty + 8 * i][tx] = g_QKV[((size_t)(b * 16384 + tf0 + ty + 8 * i)) * 256 + d0 + tx];
    __syncthreads();
    #pragma unroll
    for (int i = 0; i < 4; i++)
        out[((size_t)(b * 256 + d0 + ty + 8 * i) * 16384) + tf0 + tx] = tile[tx][ty + 8 * i];
}

// ---------------------------------------------------------------------------
// FP16 GEMM, cp.async 3-stage + ldmatrix fragment loads.
// C[M,N] = A[M,256] @ B[N,256]^T; tile 128x128x32; 8 warps of 64x32.
// Stage (u32): As[128][20] | Bs[128][20] = 5120 u32 = 20480 B.
// ldmatrix phase banks: rows stride 20 u32 -> 20r mod 32 all distinct,
// each 16B fetch covers disjoint 4-bank groups -> conflict-free.
// ---------------------------------------------------------------------------
__global__ __launch_bounds__(256, 2) void fp16_gemm_kernel(
    const __half* __restrict__ A, const __half* __restrict__ B,
    float* __restrict__ C, int N)
{
    extern __shared__ uint32_t smg[];
    const uint32_t smem_addr = smem_u32(smg);

    const int tid = threadIdx.x;
    const int wid = tid >> 5;
    const int lane = tid & 31;
    const int tq = lane >> 2;
    const int tr = lane & 3;
    const int warp_m = (wid & 1) * 64;
    const int warp_n = (wid >> 1) * 32;
    const int bx = blockIdx.x * 128;
    const int by = blockIdx.y * 128;

    float acc[4][4][4];
    #pragma unroll
    for (int i = 0; i < 4; i++)
        #pragma unroll
        for (int j = 0; j < 4; j++)
            #pragma unroll
            for (int r = 0; r < 4; r++) acc[i][j][r] = 0.0f;

    const char* Ag = (const char*)(A + (size_t)by * 256);
    const char* Bg = (const char*)(B + (size_t)bx * 256);

    auto issue = [&](int kt, int s) {
        uint32_t stA = smem_addr + s * 20480;
        uint32_t stB = stA + 10240;
        #pragma unroll
        for (int r = 0; r < 2; r++) {
            int idx = tid + r * 256;          // 0..511
            int row = idx >> 2, cc = idx & 3;
            cp_async16(stA + row * 80 + cc * 16, Ag + (size_t)row * 512 + kt * 64 + cc * 16);
            cp_async16(stB + row * 80 + cc * 16, Bg + (size_t)row * 512 + kt * 64 + cc * 16);
        }
        cp_commit();
    };

    // ldmatrix per-lane offsets (bytes)
    const int l7 = lane & 7;
    const uint32_t aOff = (uint32_t)((warp_m + l7 + ((lane >> 3) & 1) * 8) * 20 +
                                     (lane >> 4) * 4) * 4;
    const uint32_t bOff = (uint32_t)((warp_n + l7) * 20 + ((lane >> 3) & 1) * 4) * 4;

    const int nt = 8;   // K=256 / 32
    issue(0, 0);
    issue(1, 1);
    cp_wait<1>();
    __syncthreads();

    for (int kt = 0; kt < nt; kt++) {
        uint32_t stA = smem_addr + (kt % 3) * 20480;
        uint32_t stB = stA + 10240;

        #pragma unroll
        for (int s = 0; s < 2; s++) {
            uint32_t a[4][4], b[4][2];
            #pragma unroll
            for (int i = 0; i < 4; i++)
                ldsm_x4(a[i][0], a[i][1], a[i][2], a[i][3],
                        stA + aOff + i * 1280 + s * 32);
            #pragma unroll
            for (int j = 0; j < 4; j++)
                ldsm_x2(b[j][0], b[j][1], stB + bOff + j * 640 + s * 32);
            #pragma unroll
            for (int i = 0; i < 4; i++)
                #pragma unroll
                for (int j = 0; j < 4; j++)
                    mma_f16(acc[i][j], a[i], b[j]);
        }

        if (kt + 1 < nt) {
            if (kt + 2 < nt) {
                issue(kt + 2, (kt + 2) % 3);
                cp_wait<1>();
            } else {
                cp_wait<0>();
            }
            __syncthreads();
        }
    }

    #pragma unroll
    for (int i = 0; i < 4; i++) {
        int row0 = by + warp_m + i * 16 + tq;
        #pragma unroll
        for (int j = 0; j < 4; j++) {
            int col0 = bx + warp_n + j * 8 + 2 * tr;
            *(float2*)&C[(size_t)row0 * N + col0] = make_float2(acc[i][j][0], acc[i][j][1]);
            *(float2*)&C[(size_t)(row0 + 8) * N + col0] = make_float2(acc[i][j][2], acc[i][j][3]);
        }
    }
}

// ---------------------------------------------------------------------------
// Token index per stage.
// ---------------------------------------------------------------------------
template <int STAGE>
__device__ __forceinline__ int tok_of(int g, int p) {
    if (STAGE == 1) {
        int b = g >> 6, f = g & 63;
        return (b * 256 + p) * 64 + f;
    } else if (STAGE == 2) {
        return g * 64 + p;
    } else {
        int b = g >> 8, rem = g & 255;
        int i = rem >> 3, jf = rem & 7;
        int t = i * 8 + (p >> 3);
        int f = jf * 8 + (p & 7);
        return (b * 256 + t) * 64 + f;
    }
}

// ---------------------------------------------------------------------------
// Q fragments: bf16-split, built directly from gmem.
// ---------------------------------------------------------------------------
template <int STAGE>
__device__ __forceinline__ void load_q_frags(
    const float* __restrict__ qkv, int g, int h, int p0,
    int tr, uint32_t qh[2][4], uint32_t ql[2][4])
{
    const float SCALE = 0.17677669529663687f;
    #pragma unroll
    for (int kt = 0; kt < 2; kt++)
        #pragma unroll
        for (int hv = 0; hv < 2; hv++) {
            int j = kt * 8 + tr + 4 * hv;
            #pragma unroll
            for (int rr = 0; rr < 2; rr++) {
                int p = p0 + rr * 8;
                int tok = tok_of<STAGE>(g, p);
                float2 q = *(const float2*)(qkv + (size_t)tok * 768 + h * 32 + 2 * j);
                float2 cs = g_rope[p * 16 + j];
                float q0 = (q.x * cs.x - q.y * cs.y) * SCALE;
                float q1 = (q.y * cs.x + q.x * cs.y) * SCALE;
                float r0, r1;
                qh[kt][hv * 2 + rr] = pack_bf16_hi(q0, q1, r0, r1);
                ql[kt][hv * 2 + rr] = pack_bf16(r0, r1);
            }
        }
}

// X writer: fp16 pair
__device__ __forceinline__ void write_x_pair(size_t o, float v0, float v1) {
    *(uint32_t*)&g_Xh[o] = pack_half2(v0, v1);
}

// ---------------------------------------------------------------------------
// Stage-1 attention: S=256, streamed KV; scores bf16-split, PV fp16-k16.
// ---------------------------------------------------------------------------
__global__ __launch_bounds__(256, 3) void attn1_kernel(const float* __restrict__ qkv) {
    constexpr int BUF = 1920;
    __shared__ uint32_t smu[2 * BUF];

    const int g = blockIdx.x;
    const int h = blockIdx.y;
    const int qoff = blockIdx.z * 128;
    const int tid = threadIdx.x;
    const int w = tid >> 5, lane = tid & 31, tq = lane >> 2, tr = lane & 3;
    const int m_base = w * 16;

    uint32_t qh[2][4], ql[2][4];
    load_q_frags<1>(qkv, g, h, qoff + m_base + tq, tr, qh, ql);

    const int kj = tid & 15;
    const int kk0 = tid >> 4;
    const int vd = tid & 31;
    const int vp0 = tid >> 5;
    float2 kx[2];
    float2 vx[2];

    auto load_chunk = [&](int c) {
        int kb = c * 32;
        #pragma unroll
        for (int r = 0; r < 2; r++) {
            int tok = tok_of<1>(g, kb + r * 16 + kk0);
            kx[r] = *(const float2*)(qkv + (size_t)tok * 768 + 256 + h * 32 + 2 * kj);
        }
        #pragma unroll
        for (int r = 0; r < 2; r++) {
            int kp = r * 8 + vp0;
            vx[r].x = qkv[(size_t)tok_of<1>(g, kb + 2 * kp) * 768 + 512 + h * 32 + vd];
            vx[r].y = qkv[(size_t)tok_of<1>(g, kb + 2 * kp + 1) * 768 + 512 + h * 32 + vd];
        }
    };
    auto store_chunk = [&](int c, int base) {
        int kb = c * 32;
        #pragma unroll
        for (int r = 0; r < 2; r++) {
            int k = r * 16 + kk0;
            float2 cs = g_rope[(kb + k) * 16 + kj];
            float k0 = kx[r].x * cs.x - kx[r].y * cs.y;
            float k1 = kx[r].y * cs.x + kx[r].x * cs.y;
            float r0, r1;
            smu[base + k * 20 + kj] = pack_bf16_hi(k0, k1, r0, r1);
            smu[base + 640 + k * 20 + kj] = pack_bf16(r0, r1);
        }
        #pragma unroll
        for (int r = 0; r < 2; r++) {
            int kp = r * 8 + vp0;
            smu[base + 1280 + vd * 20 + kp] = pack_half2(vx[r].x, vx[r].y);
        }
    };

    load_chunk(0);
    store_chunk(0, 0);
    __syncthreads();

    float co[4][4];
    #pragma unroll
    for (int i = 0; i < 4; i++)
        #pragma unroll
        for (int j = 0; j < 4; j++) co[i][j] = 0.0f;
    float mrun0 = -1e30f, mrun1 = -1e30f, lrun0 = 0.0f, lrun1 = 0.0f;

    for (int c = 0; c < 8; c++) {
        const uint32_t* Khi = smu + (c & 1) * BUF;
        const uint32_t* Klo = Khi + 640;
        const uint32_t* Vt = Khi + 1280;

        if (c < 7) load_chunk(c + 1);

        float sc[4][4];
        #pragma unroll
        for (int nt = 0; nt < 4; nt++) {
            const uint32_t* Krh = Khi + (nt * 8 + tq) * 20;
            const uint32_t* Krl = Klo + (nt * 8 + tq) * 20;
            float c0[4] = {0, 0, 0, 0}, c1[4] = {0, 0, 0, 0}, c2[4] = {0, 0, 0, 0};
            #pragma unroll
            for (int kt = 0; kt < 2; kt++) {
                uint32_t bh[2] = {Krh[kt * 8 + tr], Krh[kt * 8 + tr + 4]};
                uint32_t bl[2] = {Krl[kt * 8 + tr], Krl[kt * 8 + tr + 4]};
                mma_bf16(c0, qh[kt], bh);
                mma_bf16(c1, ql[kt], bh);
                mma_bf16(c2, qh[kt], bl);
            }
            #pragma unroll
            for (int r = 0; r < 4; r++) sc[nt][r] = c0[r] + c1[r] + c2[r];
        }

        float mx0 = -1e30f, mx1 = -1e30f;
        #pragma unroll
        for (int nt = 0; nt < 4; nt++) {
            mx0 = fmaxf(mx0, fmaxf(sc[nt][0], sc[nt][1]));
            mx1 = fmaxf(mx1, fmaxf(sc[nt][2], sc[nt][3]));
        }
        mx0 = fmaxf(mx0, __shfl_xor_sync(0xFFFFFFFFu, mx0, 1));
        mx0 = fmaxf(mx0, __shfl_xor_sync(0xFFFFFFFFu, mx0, 2));
        mx1 = fmaxf(mx1, __shfl_xor_sync(0xFFFFFFFFu, mx1, 1));
        mx1 = fmaxf(mx1, __shfl_xor_sync(0xFFFFFFFFu, mx1, 2));
        float mn0 = fmaxf(mrun0, mx0), mn1 = fmaxf(mrun1, mx1);
        float esc0 = __expf(mrun0 - mn0), esc1 = __expf(mrun1 - mn1);
        float s0 = 0.0f, s1 = 0.0f;
        #pragma unroll
        for (int nt = 0; nt < 4; nt++) {
            sc[nt][0] = __expf(sc[nt][0] - mn0);
            sc[nt][1] = __expf(sc[nt][1] - mn0);
            sc[nt][2] = __expf(sc[nt][2] - mn1);
            sc[nt][3] = __expf(sc[nt][3] - mn1);
            s0 += sc[nt][0] + sc[nt][1];
            s1 += sc[nt][2] + sc[nt][3];
        }
        s0 += __shfl_xor_sync(0xFFFFFFFFu, s0, 1);
        s0 += __shfl_xor_sync(0xFFFFFFFFu, s0, 2);
        s1 += __shfl_xor_sync(0xFFFFFFFFu, s1, 1);
        s1 += __shfl_xor_sync(0xFFFFFFFFu, s1, 2);
        lrun0 = lrun0 * esc0 + s0;
        lrun1 = lrun1 * esc1 + s1;
        mrun0 = mn0; mrun1 = mn1;
        #pragma unroll
        for (int nt2 = 0; nt2 < 4; nt2++) {
            co[nt2][0] *= esc0; co[nt2][1] *= esc0;
            co[nt2][2] *= esc1; co[nt2][3] *= esc1;
        }

        #pragma unroll
        for (int kt2 = 0; kt2 < 2; kt2++) {
            uint32_t a[4];
            a[0] = pack_half2(sc[2 * kt2][0], sc[2 * kt2][1]);
            a[1] = pack_half2(sc[2 * kt2][2], sc[2 * kt2][3]);
            a[2] = pack_half2(sc[2 * kt2 + 1][0], sc[2 * kt2 + 1][1]);
            a[3] = pack_half2(sc[2 * kt2 + 1][2], sc[2 * kt2 + 1][3]);
            #pragma unroll
            for (int nt2 = 0; nt2 < 4; nt2++) {
                const uint32_t* vr = Vt + (nt2 * 8 + tq) * 20 + kt2 * 8 + tr;
                uint32_t b[2] = {vr[0], vr[4]};
                mma_f16(co[nt2], a, b);
            }
        }

        if (c < 7) store_chunk(c + 1, ((c + 1) & 1) * BUF);
        __syncthreads();
    }

    float inv0 = 1.0f / lrun0, inv1 = 1.0f / lrun1;
    int p0r = qoff + m_base + tq;
    size_t o0 = (size_t)tok_of<1>(g, p0r) * 256 + h * 32;
    size_t o1 = (size_t)tok_of<1>(g, p0r + 8) * 256 + h * 32;
    #pragma unroll
    for (int nt2 = 0; nt2 < 4; nt2++) {
        int cc = nt2 * 8 + 2 * tr;
        write_x_pair(o0 + cc, co[nt2][0] * inv0, co[nt2][1] * inv0);
        write_x_pair(o1 + cc, co[nt2][2] * inv1, co[nt2][3] * inv1);
    }
}

// ---------------------------------------------------------------------------
// Stage-2/3 attention: S=64, 2 heads per block; PV fp16, V packed half2.
// ---------------------------------------------------------------------------
template <int STAGE>
__global__ __launch_bounds__(256, 3) void attn64_kernel(const float* __restrict__ qkv) {
    constexpr int HS = 3712;
    extern __shared__ uint32_t smu2[];

    const int g = blockIdx.x;
    const int tid = threadIdx.x;
    const int w = tid >> 5, lane = tid & 31, tq = lane >> 2, tr = lane & 3;
    const int hh = w >> 2;
    const int h = blockIdx.y * 2 + hh;
    const int m_base = (w & 3) * 16;

    for (int idx = tid; idx < 2048; idx += 256) {
        int hl = idx >> 10, rem = idx & 1023;
        int k = rem >> 4, j = rem & 15;
        int tok = tok_of<STAGE>(g, k);
        const float* bp = qkv + (size_t)tok * 768 + 256 + (blockIdx.y * 2 + hl) * 32;
        float x0 = bp[2 * j], x1 = bp[2 * j + 1];
        float2 cs = g_rope[k * 16 + j];
        float k0 = x0 * cs.x - x1 * cs.y;
        float k1 = x1 * cs.x + x0 * cs.y;
        float r0, r1;
        int base = hl * HS;
        smu2[base + k * 20 + j] = pack_bf16_hi(k0, k1, r0, r1);
        smu2[base + 1280 + k * 20 + j] = pack_bf16(r0, r1);
    }
    for (int idx = tid; idx < 2048; idx += 256) {
        int hl = idx >> 10, rem = idx & 1023;
        int kp = rem >> 5, d = rem & 31;
        int hcur = blockIdx.y * 2 + hl;
        float v0 = qkv[(size_t)tok_of<STAGE>(g, 2 * kp) * 768 + 512 + hcur * 32 + d];
        float v1 = qkv[(size_t)tok_of<STAGE>(g, 2 * kp + 1) * 768 + 512 + hcur * 32 + d];
        smu2[hl * HS + 2560 + d * 36 + kp] = pack_half2(v0, v1);
    }

    uint32_t qh[2][4], ql[2][4];
    load_q_frags<STAGE>(qkv, g, h, m_base + tq, tr, qh, ql);
    __syncthreads();

    const uint32_t* KhiB = smu2 + hh * HS;
    const uint32_t* KloB = KhiB + 1280;
    const uint32_t* VtB = KhiB + 2560;

    float co[4][4];
    #pragma unroll
    for (int i = 0; i < 4; i++)
        #pragma unroll
        for (int j = 0; j < 4; j++) co[i][j] = 0.0f;
    float mrun0 = -1e30f, mrun1 = -1e30f, lrun0 = 0.0f, lrun1 = 0.0f;

    #pragma unroll
    for (int j0 = 0; j0 < 64; j0 += 32) {
        float sc[4][4];
        #pragma unroll
        for (int nt = 0; nt < 4; nt++) {
            const uint32_t* Krh = KhiB + (j0 + nt * 8 + tq) * 20;
            const uint32_t* Krl = KloB + (j0 + nt * 8 + tq) * 20;
            float c0[4] = {0, 0, 0, 0}, c1[4] = {0, 0, 0, 0}, c2[4] = {0, 0, 0, 0};
            #pragma unroll
            for (int kt = 0; kt < 2; kt++) {
                uint32_t bh[2] = {Krh[kt * 8 + tr], Krh[kt * 8 + tr + 4]};
                uint32_t bl[2] = {Krl[kt * 8 + tr], Krl[kt * 8 + tr + 4]};
                mma_bf16(c0, qh[kt], bh);
                mma_bf16(c1, ql[kt], bh);
                mma_bf16(c2, qh[kt], bl);
            }
            #pragma unroll
            for (int r = 0; r < 4; r++) sc[nt][r] = c0[r] + c1[r] + c2[r];
        }

        float mx0 = -1e30f, mx1 = -1e30f;
        #pragma unroll
        for (int nt = 0; nt < 4; nt++) {
            mx0 = fmaxf(mx0, fmaxf(sc[nt][0], sc[nt][1]));
            mx1 = fmaxf(mx1, fmaxf(sc[nt][2], sc[nt][3]));
        }
        mx0 = fmaxf(mx0, __shfl_xor_sync(0xFFFFFFFFu, mx0, 1));
        mx0 = fmaxf(mx0, __shfl_xor_sync(0xFFFFFFFFu, mx0, 2));
        mx1 = fmaxf(mx1, __shfl_xor_sync(0xFFFFFFFFu, mx1, 1));
        mx1 = fmaxf(mx1, __shfl_xor_sync(0xFFFFFFFFu, mx1, 2));
        float mn0 = fmaxf(mrun0, mx0), mn1 = fmaxf(mrun1, mx1);
        float esc0 = __expf(mrun0 - mn0), esc1 = __expf(mrun1 - mn1);
        float s0 = 0.0f, s1 = 0.0f;
        #pragma unroll
        for (int nt = 0; nt < 4; nt++) {
            sc[nt][0] = __expf(sc[nt][0] - mn0);
            sc[nt][1] = __expf(sc[nt][1] - mn0);
            sc[nt][2] = __expf(sc[nt][2] - mn1);
            sc[nt][3] = __expf(sc[nt][3] - mn1);
            s0 += sc[nt][0] + sc[nt][1];
            s1 += sc[nt][2] + sc[nt][3];
        }
        s0 += __shfl_xor_sync(0xFFFFFFFFu, s0, 1);
        s0 += __shfl_xor_sync(0xFFFFFFFFu, s0, 2);
        s1 += __shfl_xor_sync(0xFFFFFFFFu, s1, 1);
        s1 += __shfl_xor_sync(0xFFFFFFFFu, s1, 2);
        lrun0 = lrun0 * esc0 + s0;
        lrun1 = lrun1 * esc1 + s1;
        mrun0 = mn0; mrun1 = mn1;
        #pragma unroll
        for (int nt2 = 0; nt2 < 4; nt2++) {
            co[nt2][0] *= esc0; co[nt2][1] *= esc0;
            co[nt2][2] *= esc1; co[nt2][3] *= esc1;
        }

        #pragma unroll
        for (int kt2 = 0; kt2 < 2; kt2++) {
            uint32_t a[4];
            a[0] = pack_half2(sc[2 * kt2][0], sc[2 * kt2][1]);
            a[1] = pack_half2(sc[2 * kt2][2], sc[2 * kt2][3]);
            a[2] = pack_half2(sc[2 * kt2 + 1][0], sc[2 * kt2 + 1][1]);
            a[3] = pack_half2(sc[2 * kt2 + 1][2], sc[2 * kt2 + 1][3]);
            #pragma unroll
            for (int nt2 = 0; nt2 < 4; nt2++) {
                const uint32_t* vr = VtB + (nt2 * 8 + tq) * 36 + (j0 >> 1) + kt2 * 8 + tr;
                uint32_t b[2] = {vr[0], vr[4]};
                mma_f16(co[nt2], a, b);
            }
        }
    }

    float inv0 = 1.0f / lrun0, inv1 = 1.0f / lrun1;
    int p0r = m_base + tq;
    size_t o0 = (size_t)tok_of<STAGE>(g, p0r) * 256 + h * 32;
    size_t o1 = (size_t)tok_of<STAGE>(g, p0r + 8) * 256 + h * 32;
    #pragma unroll
    for (int nt2 = 0; nt2 < 4; nt2++) {
        int cc = nt2 * 8 + 2 * tr;
        write_x_pair(o0 + cc, co[nt2][0] * inv0, co[nt2][1] * inv0);
        write_x_pair(o1 + cc, co[nt2][2] * inv1, co[nt2][3] * inv1);
    }
}

// ---------------------------------------------------------------------------
extern "C" void kernel_launch(void* const* d_in, const int* in_sizes, int n_in,
                              void* d_out, int out_size) {
    const float* x  = (const float*)d_in[0];
    const float* W1 = (const float*)d_in[1];
    const float* W2 = (const float*)d_in[2];
    const float* W3 = (const float*)d_in[3];
    const float* Wp = (const float*)d_in[4];
    float* out = (float*)d_out;

    __half* Xh; cudaGetSymbolAddress((void**)&Xh, g_Xh);
    __half* Wr; cudaGetSymbolAddress((void**)&Wr, g_W);
    float* QKVp; cudaGetSymbolAddress((void**)&QKVp, g_QKV);

    const int SMEMG = 3 * 20480;               // 61440
    const int SMEM64 = 2 * 3712 * 4;           // 29696

    cudaFuncSetAttribute(fp16_gemm_kernel,
                         cudaFuncAttributeMaxDynamicSharedMemorySize, SMEMG);
    cudaFuncSetAttribute(attn64_kernel<2>,
                         cudaFuncAttributeMaxDynamicSharedMemorySize, SMEM64);
    cudaFuncSetAttribute(attn64_kernel<3>,
                         cudaFuncAttributeMaxDynamicSharedMemorySize, SMEM64);

    rope_table_kernel<<<16, 256>>>();
    round_w_kernel<<<2560, 256>>>(W1, W2, W3, Wp);
    permute_in_kernel<<<dim3(512, 8, 4), dim3(32, 8)>>>(x);

    // Stage 1: time-axis attention (S=256)
    fp16_gemm_kernel<<<dim3(6, 512), 256, SMEMG>>>(Xh, Wr, QKVp, 768);
    attn1_kernel<<<dim3(256, 8, 2), 256>>>(QKVp);

    // Stage 2: freq-axis attention (S=64)
    fp16_gemm_kernel<<<dim3(6, 512), 256, SMEMG>>>(Xh, Wr + 196608, QKVp, 768);
    attn64_kernel<2><<<dim3(1024, 4), 256, SMEM64>>>(QKVp);

    // Stage 3: windowed attention (S=64)
    fp16_gemm_kernel<<<dim3(6, 512), 256, SMEMG>>>(Xh, Wr + 393216, QKVp, 768);
    attn64_kernel<3><<<dim3(1024, 4), 256, SMEM64>>>(QKVp);

    // Projection
    fp16_gemm_kernel<<<dim3(2, 512), 256, SMEMG>>>(Xh, Wr + 589824, QKVp, 256);

    permute_out_kernel<<<dim3(8, 512, 4), dim3(32, 8)>>>(out);
}

// round 14
// speedup vs baseline: 4.3903x; 1.0027x over previous
#include <cuda_runtime.h>
#include <cuda_bf16.h>
#include <cuda_fp16.h>
#include <math.h>
#include <stdint.h>

// Problem constants
#define BB 4
#define DD 256
#define TT 256
#define FF 64
#define HH 8
#define HD 32
#define NT (BB*TT*FF)          // 65536 tokens

// Scratch (no allocations allowed -> device globals)
__device__ __half g_Xh[(size_t)NT * DD];      // activations fp16 [tok][256]
__device__ float g_QKV[(size_t)NT * 3 * DD];  // qkv (f32)
__device__ __half g_W[655360];                // weights fp16, B-layout [n][k]
__device__ float2 g_rope[256 * 16];           // cos/sin table [pos][j]

// ---------------------------------------------------------------------------
// Helpers
// ---------------------------------------------------------------------------
__device__ __forceinline__ void mma_f16(float* c, const uint32_t* a, const uint32_t* b) {
    asm volatile(
        "mma.sync.aligned.m16n8k16.row.col.f32.f16.f16.f32 "
        "{%0,%1,%2,%3}, {%4,%5,%6,%7}, {%8,%9}, {%0,%1,%2,%3};"
        : "+f"(c[0]), "+f"(c[1]), "+f"(c[2]), "+f"(c[3])
        : "r"(a[0]), "r"(a[1]), "r"(a[2]), "r"(a[3]), "r"(b[0]), "r"(b[1]));
}

__device__ __forceinline__ void mma_bf16(float* c, const uint32_t* a, const uint32_t* b) {
    asm volatile(
        "mma.sync.aligned.m16n8k16.row.col.f32.bf16.bf16.f32 "
        "{%0,%1,%2,%3}, {%4,%5,%6,%7}, {%8,%9}, {%0,%1,%2,%3};"
        : "+f"(c[0]), "+f"(c[1]), "+f"(c[2]), "+f"(c[3])
        : "r"(a[0]), "r"(a[1]), "r"(a[2]), "r"(a[3]), "r"(b[0]), "r"(b[1]));
}

__device__ __forceinline__ void ldsm_x4(uint32_t& r0, uint32_t& r1, uint32_t& r2,
                                        uint32_t& r3, uint32_t addr) {
    asm volatile("ldmatrix.sync.aligned.m8n8.x4.shared.b16 {%0,%1,%2,%3}, [%4];"
                 : "=r"(r0), "=r"(r1), "=r"(r2), "=r"(r3) : "r"(addr));
}
__device__ __forceinline__ void ldsm_x2(uint32_t& r0, uint32_t& r1, uint32_t addr) {
    asm volatile("ldmatrix.sync.aligned.m8n8.x2.shared.b16 {%0,%1}, [%2];"
                 : "=r"(r0), "=r"(r1) : "r"(addr));
}

__device__ __forceinline__ uint32_t pack_bf16_hi(float x0, float x1, float& r0, float& r1) {
    __nv_bfloat16 h0 = __float2bfloat16(x0);
    __nv_bfloat16 h1 = __float2bfloat16(x1);
    r0 = x0 - __bfloat162float(h0);
    r1 = x1 - __bfloat162float(h1);
    __nv_bfloat162 p = {h0, h1};
    return *(uint32_t*)&p;
}
__device__ __forceinline__ uint32_t pack_bf16(float x0, float x1) {
    __nv_bfloat162 p = {__float2bfloat16(x0), __float2bfloat16(x1)};
    return *(uint32_t*)&p;
}
__device__ __forceinline__ uint32_t pack_half2(float x0, float x1) {
    __half2 p = __floats2half2_rn(x0, x1);
    return *(uint32_t*)&p;
}

// cp.async helpers
__device__ __forceinline__ void cp_async16(uint32_t saddr, const void* g) {
    asm volatile("cp.async.cg.shared.global [%0], [%1], 16;" :: "r"(saddr), "l"(g));
}
__device__ __forceinline__ void cp_commit() {
    asm volatile("cp.async.commit_group;");
}
template <int N> __device__ __forceinline__ void cp_wait() {
    asm volatile("cp.async.wait_group %0;" :: "n"(N));
}
__device__ __forceinline__ uint32_t smem_u32(const void* p) {
    uint32_t a;
    asm("{ .reg .u64 t; cvta.to.shared.u64 t, %1; cvt.u32.u64 %0, t; }" : "=r"(a) : "l"(p));
    return a;
}

// ---------------------------------------------------------------------------
// RoPE table + weight prep (fp16, transposed to B-layout [n][k])
// ---------------------------------------------------------------------------
__global__ __launch_bounds__(256) void rope_table_kernel() {
    int i = blockIdx.x * 256 + threadIdx.x;   // 4096
    int p = i >> 4, j = i & 15;
    const float CEXP = 0.830482023721841f;
    float inv = exp2f(-(float)j * CEXP);
    float sn, cs;
    sincosf((float)p * inv, &sn, &cs);
    g_rope[i] = make_float2(cs, sn);
}

__global__ __launch_bounds__(256) void round_w_kernel(
    const float* __restrict__ W1, const float* __restrict__ W2,
    const float* __restrict__ W3, const float* __restrict__ Wp) {
    int i = blockIdx.x * 256 + threadIdx.x;   // 655360
    const float* src; int N; int base;
    if (i < 196608)      { src = W1; N = 768; base = 0; }
    else if (i < 393216) { src = W2; N = 768; base = 196608; }
    else if (i < 589824) { src = W3; N = 768; base = 393216; }
    else                 { src = Wp; N = 256; base = 589824; }
    int j = i - base;
    int n = j >> 8, k = j & 255;
    g_W[i] = __float2half(src[k * N + n]);
}

// ---------------------------------------------------------------------------
// Input permute
// ---------------------------------------------------------------------------
__global__ __launch_bounds__(256) void permute_in_kernel(const float* __restrict__ x) {
    __shared__ float tile[32][33];
    const int b = blockIdx.z;
    const int tf0 = blockIdx.x * 32;
    const int d0 = blockIdx.y * 32;
    const int tx = threadIdx.x, ty = threadIdx.y;
    #pragma unroll
    for (int i = 0; i < 4; i++)
        tile[ty + 8 * i][tx] = x[((size_t)(b * 256 + d0 + ty + 8 * i) * 16384) + tf0 + tx];
    __syncthreads();
    #pragma unroll
    for (int i = 0; i < 4; i++)
        g_Xh[((size_t)(b * 16384 + tf0 + ty + 8 * i)) * 256 + d0 + tx] =
            __float2half(tile[tx][ty + 8 * i]);
}

// ---------------------------------------------------------------------------
// FP16 GEMM, cp.async 4-stage + ldmatrix. C[M,N] = A[M,256] @ B[N,256]^T.
// Tile 128x128x32; 8 warps of 64x32. Stage = 20480 B.
// ---------------------------------------------------------------------------
__global__ __launch_bounds__(256, 2) void fp16_gemm_kernel(
    const __half* __restrict__ A, const __half* __restrict__ B,
    float* __restrict__ C, int N)
{
    extern __shared__ uint32_t smg[];
    const uint32_t smem_addr = smem_u32(smg);

    const int tid = threadIdx.x;
    const int wid = tid >> 5;
    const int lane = tid & 31;
    const int tq = lane >> 2;
    const int tr = lane & 3;
    const int warp_m = (wid & 1) * 64;
    const int warp_n = (wid >> 1) * 32;
    const int bx = blockIdx.x * 128;
    const int by = blockIdx.y * 128;

    float acc[4][4][4];
    #pragma unroll
    for (int i = 0; i < 4; i++)
        #pragma unroll
        for (int j = 0; j < 4; j++)
            #pragma unroll
            for (int r = 0; r < 4; r++) acc[i][j][r] = 0.0f;

    const char* Ag = (const char*)(A + (size_t)by * 256);
    const char* Bg = (const char*)(B + (size_t)bx * 256);

    auto issue = [&](int kt) {
        uint32_t stA = smem_addr + (kt & 3) * 20480;
        uint32_t stB = stA + 10240;
        #pragma unroll
        for (int r = 0; r < 2; r++) {
            int idx = tid + r * 256;
            int row = idx >> 2, cc = idx & 3;
            cp_async16(stA + row * 80 + cc * 16, Ag + (size_t)row * 512 + kt * 64 + cc * 16);
            cp_async16(stB + row * 80 + cc * 16, Bg + (size_t)row * 512 + kt * 64 + cc * 16);
        }
        cp_commit();
    };

    const int l7 = lane & 7;
    const uint32_t aOff = (uint32_t)((warp_m + l7 + ((lane >> 3) & 1) * 8) * 20 +
                                     (lane >> 4) * 4) * 4;
    const uint32_t bOff = (uint32_t)((warp_n + l7) * 20 + ((lane >> 3) & 1) * 4) * 4;

    const int nt = 8;   // K=256 / 32
    issue(0);
    issue(1);
    issue(2);
    cp_wait<2>();
    __syncthreads();

    for (int kt = 0; kt < nt; kt++) {
        uint32_t stA = smem_addr + (kt & 3) * 20480;
        uint32_t stB = stA + 10240;

        #pragma unroll
        for (int s = 0; s < 2; s++) {
            uint32_t a[4][4], b[4][2];
            #pragma unroll
            for (int i = 0; i < 4; i++)
                ldsm_x4(a[i][0], a[i][1], a[i][2], a[i][3],
                        stA + aOff + i * 1280 + s * 32);
            #pragma unroll
            for (int j = 0; j < 4; j++)
                ldsm_x2(b[j][0], b[j][1], stB + bOff + j * 640 + s * 32);
            #pragma unroll
            for (int i = 0; i < 4; i++)
                #pragma unroll
                for (int j = 0; j < 4; j++)
                    mma_f16(acc[i][j], a[i], b[j]);
        }

        if (kt + 1 < nt) {
            if (kt + 3 < nt) {
                issue(kt + 3);
                cp_wait<2>();
            } else if (kt + 2 < nt) {
                cp_wait<1>();
            } else {
                cp_wait<0>();
            }
            __syncthreads();
        }
    }

    #pragma unroll
    for (int i = 0; i < 4; i++) {
        int row0 = by + warp_m + i * 16 + tq;
        #pragma unroll
        for (int j = 0; j < 4; j++) {
            int col0 = bx + warp_n + j * 8 + 2 * tr;
            *(float2*)&C[(size_t)row0 * N + col0] = make_float2(acc[i][j][0], acc[i][j][1]);
            *(float2*)&C[(size_t)(row0 + 8) * N + col0] = make_float2(acc[i][j][2], acc[i][j][3]);
        }
    }
}

// ---------------------------------------------------------------------------
// Fused projection GEMM + output permute. N=256 fixed.
// C-tile (128 tok x 128 d) written transposed via smem into out[b][d][t][f].
// ---------------------------------------------------------------------------
__global__ __launch_bounds__(256, 2) void fp16_gemm_out_kernel(
    const __half* __restrict__ A, const __half* __restrict__ B,
    float* __restrict__ out)
{
    extern __shared__ uint32_t smg[];
    const uint32_t smem_addr = smem_u32(smg);

    const int tid = threadIdx.x;
    const int wid = tid >> 5;
    const int lane = tid & 31;
    const int tq = lane >> 2;
    const int tr = lane & 3;
    const int warp_m = (wid & 1) * 64;
    const int warp_n = (wid >> 1) * 32;
    const int bx = blockIdx.x * 128;
    const int by = blockIdx.y * 128;

    float acc[4][4][4];
    #pragma unroll
    for (int i = 0; i < 4; i++)
        #pragma unroll
        for (int j = 0; j < 4; j++)
            #pragma unroll
            for (int r = 0; r < 4; r++) acc[i][j][r] = 0.0f;

    const char* Ag = (const char*)(A + (size_t)by * 256);
    const char* Bg = (const char*)(B + (size_t)bx * 256);

    auto issue = [&](int kt) {
        uint32_t stA = smem_addr + (kt & 3) * 20480;
        uint32_t stB = stA + 10240;
        #pragma unroll
        for (int r = 0; r < 2; r++) {
            int idx = tid + r * 256;
            int row = idx >> 2, cc = idx & 3;
            cp_async16(stA + row * 80 + cc * 16, Ag + (size_t)row * 512 + kt * 64 + cc * 16);
            cp_async16(stB + row * 80 + cc * 16, Bg + (size_t)row * 512 + kt * 64 + cc * 16);
        }
        cp_commit();
    };

    const int l7 = lane & 7;
    const uint32_t aOff = (uint32_t)((warp_m + l7 + ((lane >> 3) & 1) * 8) * 20 +
                                     (lane >> 4) * 4) * 4;
    const uint32_t bOff = (uint32_t)((warp_n + l7) * 20 + ((lane >> 3) & 1) * 4) * 4;

    const int nt = 8;
    issue(0);
    issue(1);
    issue(2);
    cp_wait<2>();
    __syncthreads();

    for (int kt = 0; kt < nt; kt++) {
        uint32_t stA = smem_addr + (kt & 3) * 20480;
        uint32_t stB = stA + 10240;

        #pragma unroll
        for (int s = 0; s < 2; s++) {
            uint32_t a[4][4], b[4][2];
            #pragma unroll
            for (int i = 0; i < 4; i++)
                ldsm_x4(a[i][0], a[i][1], a[i][2], a[i][3],
                        stA + aOff + i * 1280 + s * 32);
            #pragma unroll
            for (int j = 0; j < 4; j++)
                ldsm_x2(b[j][0], b[j][1], stB + bOff + j * 640 + s * 32);
            #pragma unroll
            for (int i = 0; i < 4; i++)
                #pragma unroll
                for (int j = 0; j < 4; j++)
                    mma_f16(acc[i][j], a[i], b[j]);
        }

        if (kt + 1 < nt) {
            if (kt + 3 < nt) {
                issue(kt + 3);
                cp_wait<2>();
            } else if (kt + 2 < nt) {
                cp_wait<1>();
            } else {
                cp_wait<0>();
            }
            __syncthreads();
        }
    }

    // transpose through smem: smT[d][tok], stride 132
    __syncthreads();
    float* smT = (float*)smg;
    #pragma unroll
    for (int i = 0; i < 4; i++) {
        int row = warp_m + i * 16 + tq;
        #pragma unroll
        for (int j = 0; j < 4; j++) {
            int col = warp_n + j * 8 + 2 * tr;
            smT[col * 132 + row]           = acc[i][j][0];
            smT[(col + 1) * 132 + row]     = acc[i][j][1];
            smT[col * 132 + row + 8]       = acc[i][j][2];
            smT[(col + 1) * 132 + row + 8] = acc[i][j][3];
        }
    }
    __syncthreads();

    const int b = blockIdx.y >> 7;
    const int tf0 = (blockIdx.y << 7) & 16383;
    const int drow = tid >> 1, half = (tid & 1) * 64;
    const float* src = smT + drow * 132 + half;
    float* dst = out + ((size_t)(b * 256 + bx + drow) * 16384) + tf0 + half;
    #pragma unroll
    for (int q = 0; q < 16; q++)
        *(float4*)(dst + q * 4) = *(const float4*)(src + q * 4);
}

// ---------------------------------------------------------------------------
// Token index per stage.
// ---------------------------------------------------------------------------
template <int STAGE>
__device__ __forceinline__ int tok_of(int g, int p) {
    if (STAGE == 1) {
        int b = g >> 6, f = g & 63;
        return (b * 256 + p) * 64 + f;
    } else if (STAGE == 2) {
        return g * 64 + p;
    } else {
        int b = g >> 8, rem = g & 255;
        int i = rem >> 3, jf = rem & 7;
        int t = i * 8 + (p >> 3);
        int f = jf * 8 + (p & 7);
        return (b * 256 + t) * 64 + f;
    }
}

// ---------------------------------------------------------------------------
// Q fragments: bf16-split, built directly from gmem.
// ---------------------------------------------------------------------------
template <int STAGE>
__device__ __forceinline__ void load_q_frags(
    const float* __restrict__ qkv, int g, int h, int p0,
    int tr, uint32_t qh[2][4], uint32_t ql[2][4])
{
    const float SCALE = 0.17677669529663687f;
    #pragma unroll
    for (int kt = 0; kt < 2; kt++)
        #pragma unroll
        for (int hv = 0; hv < 2; hv++) {
            int j = kt * 8 + tr + 4 * hv;
            #pragma unroll
            for (int rr = 0; rr < 2; rr++) {
                int p = p0 + rr * 8;
                int tok = tok_of<STAGE>(g, p);
                float2 q = *(const float2*)(qkv + (size_t)tok * 768 + h * 32 + 2 * j);
                float2 cs = g_rope[p * 16 + j];
                float q0 = (q.x * cs.x - q.y * cs.y) * SCALE;
                float q1 = (q.y * cs.x + q.x * cs.y) * SCALE;
                float r0, r1;
                qh[kt][hv * 2 + rr] = pack_bf16_hi(q0, q1, r0, r1);
                ql[kt][hv * 2 + rr] = pack_bf16(r0, r1);
            }
        }
}

// X writer: fp16 pair
__device__ __forceinline__ void write_x_pair(size_t o, float v0, float v1) {
    *(uint32_t*)&g_Xh[o] = pack_half2(v0, v1);
}

// ---------------------------------------------------------------------------
// Stage-1 attention: S=256, streamed KV; scores bf16-split, PV fp16-k16.
// ---------------------------------------------------------------------------
__global__ __launch_bounds__(256, 3) void attn1_kernel(const float* __restrict__ qkv) {
    constexpr int BUF = 1920;
    __shared__ uint32_t smu[2 * BUF];

    const int g = blockIdx.x;
    const int h = blockIdx.y;
    const int qoff = blockIdx.z * 128;
    const int tid = threadIdx.x;
    const int w = tid >> 5, lane = tid & 31, tq = lane >> 2, tr = lane & 3;
    const int m_base = w * 16;

    uint32_t qh[2][4], ql[2][4];
    load_q_frags<1>(qkv, g, h, qoff + m_base + tq, tr, qh, ql);

    const int kj = tid & 15;
    const int kk0 = tid >> 4;
    const int vd = tid & 31;
    const int vp0 = tid >> 5;
    float2 kx[2];
    float2 vx[2];

    auto load_chunk = [&](int c) {
        int kb = c * 32;
        #pragma unroll
        for (int r = 0; r < 2; r++) {
            int tok = tok_of<1>(g, kb + r * 16 + kk0);
            kx[r] = *(const float2*)(qkv + (size_t)tok * 768 + 256 + h * 32 + 2 * kj);
        }
        #pragma unroll
        for (int r = 0; r < 2; r++) {
            int kp = r * 8 + vp0;
            vx[r].x = qkv[(size_t)tok_of<1>(g, kb + 2 * kp) * 768 + 512 + h * 32 + vd];
            vx[r].y = qkv[(size_t)tok_of<1>(g, kb + 2 * kp + 1) * 768 + 512 + h * 32 + vd];
        }
    };
    auto store_chunk = [&](int c, int base) {
        int kb = c * 32;
        #pragma unroll
        for (int r = 0; r < 2; r++) {
            int k = r * 16 + kk0;
            float2 cs = g_rope[(kb + k) * 16 + kj];
            float k0 = kx[r].x * cs.x - kx[r].y * cs.y;
            float k1 = kx[r].y * cs.x + kx[r].x * cs.y;
            float r0, r1;
            smu[base + k * 20 + kj] = pack_bf16_hi(k0, k1, r0, r1);
            smu[base + 640 + k * 20 + kj] = pack_bf16(r0, r1);
        }
        #pragma unroll
        for (int r = 0; r < 2; r++) {
            int kp = r * 8 + vp0;
            smu[base + 1280 + vd * 20 + kp] = pack_half2(vx[r].x, vx[r].y);
        }
    };

    load_chunk(0);
    store_chunk(0, 0);
    __syncthreads();

    float co[4][4];
    #pragma unroll
    for (int i = 0; i < 4; i++)
        #pragma unroll
        for (int j = 0; j < 4; j++) co[i][j] = 0.0f;
    float mrun0 = -1e30f, mrun1 = -1e30f, lrun0 = 0.0f, lrun1 = 0.0f;

    for (int c = 0; c < 8; c++) {
        const uint32_t* Khi = smu + (c & 1) * BUF;
        const uint32_t* Klo = Khi + 640;
        const uint32_t* Vt = Khi + 1280;

        if (c < 7) load_chunk(c + 1);

        float sc[4][4];
        #pragma unroll
        for (int nt = 0; nt < 4; nt++) {
            const uint32_t* Krh = Khi + (nt * 8 + tq) * 20;
            const uint32_t* Krl = Klo + (nt * 8 + tq) * 20;
            float c0[4] = {0, 0, 0, 0}, c1[4] = {0, 0, 0, 0}, c2[4] = {0, 0, 0, 0};
            #pragma unroll
            for (int kt = 0; kt < 2; kt++) {
                uint32_t bh[2] = {Krh[kt * 8 + tr], Krh[kt * 8 + tr + 4]};
                uint32_t bl[2] = {Krl[kt * 8 + tr], Krl[kt * 8 + tr + 4]};
                mma_bf16(c0, qh[kt], bh);
                mma_bf16(c1, ql[kt], bh);
                mma_bf16(c2, qh[kt], bl);
            }
            #pragma unroll
            for (int r = 0; r < 4; r++) sc[nt][r] = c0[r] + c1[r] + c2[r];
        }

        float mx0 = -1e30f, mx1 = -1e30f;
        #pragma unroll
        for (int nt = 0; nt < 4; nt++) {
            mx0 = fmaxf(mx0, fmaxf(sc[nt][0], sc[nt][1]));
            mx1 = fmaxf(mx1, fmaxf(sc[nt][2], sc[nt][3]));
        }
        mx0 = fmaxf(mx0, __shfl_xor_sync(0xFFFFFFFFu, mx0, 1));
        mx0 = fmaxf(mx0, __shfl_xor_sync(0xFFFFFFFFu, mx0, 2));
        mx1 = fmaxf(mx1, __shfl_xor_sync(0xFFFFFFFFu, mx1, 1));
        mx1 = fmaxf(mx1, __shfl_xor_sync(0xFFFFFFFFu, mx1, 2));
        float mn0 = fmaxf(mrun0, mx0), mn1 = fmaxf(mrun1, mx1);
        float esc0 = __expf(mrun0 - mn0), esc1 = __expf(mrun1 - mn1);
        float s0 = 0.0f, s1 = 0.0f;
        #pragma unroll
        for (int nt = 0; nt < 4; nt++) {
            sc[nt][0] = __expf(sc[nt][0] - mn0);
            sc[nt][1] = __expf(sc[nt][1] - mn0);
            sc[nt][2] = __expf(sc[nt][2] - mn1);
            sc[nt][3] = __expf(sc[nt][3] - mn1);
            s0 += sc[nt][0] + sc[nt][1];
            s1 += sc[nt][2] + sc[nt][3];
        }
        s0 += __shfl_xor_sync(0xFFFFFFFFu, s0, 1);
        s0 += __shfl_xor_sync(0xFFFFFFFFu, s0, 2);
        s1 += __shfl_xor_sync(0xFFFFFFFFu, s1, 1);
        s1 += __shfl_xor_sync(0xFFFFFFFFu, s1, 2);
        lrun0 = lrun0 * esc0 + s0;
        lrun1 = lrun1 * esc1 + s1;
        mrun0 = mn0; mrun1 = mn1;
        #pragma unroll
        for (int nt2 = 0; nt2 < 4; nt2++) {
            co[nt2][0] *= esc0; co[nt2][1] *= esc0;
            co[nt2][2] *= esc1; co[nt2][3] *= esc1;
        }

        #pragma unroll
        for (int kt2 = 0; kt2 < 2; kt2++) {
            uint32_t a[4];
            a[0] = pack_half2(sc[2 * kt2][0], sc[2 * kt2][1]);
            a[1] = pack_half2(sc[2 * kt2][2], sc[2 * kt2][3]);
            a[2] = pack_half2(sc[2 * kt2 + 1][0], sc[2 * kt2 + 1][1]);
            a[3] = pack_half2(sc[2 * kt2 + 1][2], sc[2 * kt2 + 1][3]);
            #pragma unroll
            for (int nt2 = 0; nt2 < 4; nt2++) {
                const uint32_t* vr = Vt + (nt2 * 8 + tq) * 20 + kt2 * 8 + tr;
                uint32_t b[2] = {vr[0], vr[4]};
                mma_f16(co[nt2], a, b);
            }
        }

        if (c < 7) store_chunk(c + 1, ((c + 1) & 1) * BUF);
        __syncthreads();
    }

    float inv0 = 1.0f / lrun0, inv1 = 1.0f / lrun1;
    int p0r = qoff + m_base + tq;
    size_t o0 = (size_t)tok_of<1>(g, p0r) * 256 + h * 32;
    size_t o1 = (size_t)tok_of<1>(g, p0r + 8) * 256 + h * 32;
    #pragma unroll
    for (int nt2 = 0; nt2 < 4; nt2++) {
        int cc = nt2 * 8 + 2 * tr;
        write_x_pair(o0 + cc, co[nt2][0] * inv0, co[nt2][1] * inv0);
        write_x_pair(o1 + cc, co[nt2][2] * inv1, co[nt2][3] * inv1);
    }
}

// ---------------------------------------------------------------------------
// Stage-2/3 attention: S=64, 2 heads per block; PV fp16, V packed half2.
// ---------------------------------------------------------------------------
template <int STAGE>
__global__ __launch_bounds__(256, 3) void attn64_kernel(const float* __restrict__ qkv) {
    constexpr int HS = 3712;
    extern __shared__ uint32_t smu2[];

    const int g = blockIdx.x;
    const int tid = threadIdx.x;
    const int w = tid >> 5, lane = tid & 31, tq = lane >> 2, tr = lane & 3;
    const int hh = w >> 2;
    const int h = blockIdx.y * 2 + hh;
    const int m_base = (w & 3) * 16;

    for (int idx = tid; idx < 2048; idx += 256) {
        int hl = idx >> 10, rem = idx & 1023;
        int k = rem >> 4, j = rem & 15;
        int tok = tok_of<STAGE>(g, k);
        const float* bp = qkv + (size_t)tok * 768 + 256 + (blockIdx.y * 2 + hl) * 32;
        float x0 = bp[2 * j], x1 = bp[2 * j + 1];
        float2 cs = g_rope[k * 16 + j];
        float k0 = x0 * cs.x - x1 * cs.y;
        float k1 = x1 * cs.x + x0 * cs.y;
        float r0, r1;
        int base = hl * HS;
        smu2[base + k * 20 + j] = pack_bf16_hi(k0, k1, r0, r1);
        smu2[base + 1280 + k * 20 + j] = pack_bf16(r0, r1);
    }
    for (int idx = tid; idx < 2048; idx += 256) {
        int hl = idx >> 10, rem = idx & 1023;
        int kp = rem >> 5, d = rem & 31;
        int hcur = blockIdx.y * 2 + hl;
        float v0 = qkv[(size_t)tok_of<STAGE>(g, 2 * kp) * 768 + 512 + hcur * 32 + d];
        float v1 = qkv[(size_t)tok_of<STAGE>(g, 2 * kp + 1) * 768 + 512 + hcur * 32 + d];
        smu2[hl * HS + 2560 + d * 36 + kp] = pack_half2(v0, v1);
    }

    uint32_t qh[2][4], ql[2][4];
    load_q_frags<STAGE>(qkv, g, h, m_base + tq, tr, qh, ql);
    __syncthreads();

    const uint32_t* KhiB = smu2 + hh * HS;
    const uint32_t* KloB = KhiB + 1280;
    const uint32_t* VtB = KhiB + 2560;

    float co[4][4];
    #pragma unroll
    for (int i = 0; i < 4; i++)
        #pragma unroll
        for (int j = 0; j < 4; j++) co[i][j] = 0.0f;
    float mrun0 = -1e30f, mrun1 = -1e30f, lrun0 = 0.0f, lrun1 = 0.0f;

    #pragma unroll
    for (int j0 = 0; j0 < 64; j0 += 32) {
        float sc[4][4];
        #pragma unroll
        for (int nt = 0; nt < 4; nt++) {
            const uint32_t* Krh = KhiB + (j0 + nt * 8 + tq) * 20;
            const uint32_t* Krl = KloB + (j0 + nt * 8 + tq) * 20;
            float c0[4] = {0, 0, 0, 0}, c1[4] = {0, 0, 0, 0}, c2[4] = {0, 0, 0, 0};
            #pragma unroll
            for (int kt = 0; kt < 2; kt++) {
                uint32_t bh[2] = {Krh[kt * 8 + tr], Krh[kt * 8 + tr + 4]};
                uint32_t bl[2] = {Krl[kt * 8 + tr], Krl[kt * 8 + tr + 4]};
                mma_bf16(c0, qh[kt], bh);
                mma_bf16(c1, ql[kt], bh);
                mma_bf16(c2, qh[kt], bl);
            }
            #pragma unroll
            for (int r = 0; r < 4; r++) sc[nt][r] = c0[r] + c1[r] + c2[r];
        }

        float mx0 = -1e30f, mx1 = -1e30f;
        #pragma unroll
        for (int nt = 0; nt < 4; nt++) {
            mx0 = fmaxf(mx0, fmaxf(sc[nt][0], sc[nt][1]));
            mx1 = fmaxf(mx1, fmaxf(sc[nt][2], sc[nt][3]));
        }
        mx0 = fmaxf(mx0, __shfl_xor_sync(0xFFFFFFFFu, mx0, 1));
        mx0 = fmaxf(mx0, __shfl_xor_sync(0xFFFFFFFFu, mx0, 2));
        mx1 = fmaxf(mx1, __shfl_xor_sync(0xFFFFFFFFu, mx1, 1));
        mx1 = fmaxf(mx1, __shfl_xor_sync(0xFFFFFFFFu, mx1, 2));
        float mn0 = fmaxf(mrun0, mx0), mn1 = fmaxf(mrun1, mx1);
        float esc0 = __expf(mrun0 - mn0), esc1 = __expf(mrun1 - mn1);
        float s0 = 0.0f, s1 = 0.0f;
        #pragma unroll
        for (int nt = 0; nt < 4; nt++) {
            sc[nt][0] = __expf(sc[nt][0] - mn0);
            sc[nt][1] = __expf(sc[nt][1] - mn0);
            sc[nt][2] = __expf(sc[nt][2] - mn1);
            sc[nt][3] = __expf(sc[nt][3] - mn1);
            s0 += sc[nt][0] + sc[nt][1];
            s1 += sc[nt][2] + sc[nt][3];
        }
        s0 += __shfl_xor_sync(0xFFFFFFFFu, s0, 1);
        s0 += __shfl_xor_sync(0xFFFFFFFFu, s0, 2);
        s1 += __shfl_xor_sync(0xFFFFFFFFu, s1, 1);
        s1 += __shfl_xor_sync(0xFFFFFFFFu, s1, 2);
        lrun0 = lrun0 * esc0 + s0;
        lrun1 = lrun1 * esc1 + s1;
        mrun0 = mn0; mrun1 = mn1;
        #pragma unroll
        for (int nt2 = 0; nt2 < 4; nt2++) {
            co[nt2][0] *= esc0; co[nt2][1] *= esc0;
            co[nt2][2] *= esc1; co[nt2][3] *= esc1;
        }

        #pragma unroll
        for (int kt2 = 0; kt2 < 2; kt2++) {
            uint32_t a[4];
            a[0] = pack_half2(sc[2 * kt2][0], sc[2 * kt2][1]);
            a[1] = pack_half2(sc[2 * kt2][2], sc[2 * kt2][3]);
            a[2] = pack_half2(sc[2 * kt2 + 1][0], sc[2 * kt2 + 1][1]);
            a[3] = pack_half2(sc[2 * kt2 + 1][2], sc[2 * kt2 + 1][3]);
            #pragma unroll
            for (int nt2 = 0; nt2 < 4; nt2++) {
                const uint32_t* vr = VtB + (nt2 * 8 + tq) * 36 + (j0 >> 1) + kt2 * 8 + tr;
                uint32_t b[2] = {vr[0], vr[4]};
                mma_f16(co[nt2], a, b);
            }
        }
    }

    float inv0 = 1.0f / lrun0, inv1 = 1.0f / lrun1;
    int p0r = m_base + tq;
    size_t o0 = (size_t)tok_of<STAGE>(g, p0r) * 256 + h * 32;
    size_t o1 = (size_t)tok_of<STAGE>(g, p0r + 8) * 256 + h * 32;
    #pragma unroll
    for (int nt2 = 0; nt2 < 4; nt2++) {
        int cc = nt2 * 8 + 2 * tr;
        write_x_pair(o0 + cc, co[nt2][0] * inv0, co[nt2][1] * inv0);
        write_x_pair(o1 + cc, co[nt2][2] * inv1, co[nt2][3] * inv1);
    }
}

// ---------------------------------------------------------------------------
extern "C" void kernel_launch(void* const* d_in, const int* in_sizes, int n_in,
                              void* d_out, int out_size) {
    const float* x  = (const float*)d_in[0];
    const float* W1 = (const float*)d_in[1];
    const float* W2 = (const float*)d_in[2];
    const float* W3 = (const float*)d_in[3];
    const float* Wp = (const float*)d_in[4];
    float* out = (float*)d_out;

    __half* Xh; cudaGetSymbolAddress((void**)&Xh, g_Xh);
    __half* Wr; cudaGetSymbolAddress((void**)&Wr, g_W);
    float* QKVp; cudaGetSymbolAddress((void**)&QKVp, g_QKV);

    const int SMEMG = 4 * 20480;               // 81920
    const int SMEMO = 81920;                   // max(pipeline, 128*132*4=67584)
    const int SMEM64 = 2 * 3712 * 4;           // 29696

    cudaFuncSetAttribute(fp16_gemm_kernel,
                         cudaFuncAttributeMaxDynamicSharedMemorySize, SMEMG);
    cudaFuncSetAttribute(fp16_gemm_out_kernel,
                         cudaFuncAttributeMaxDynamicSharedMemorySize, SMEMO);
    cudaFuncSetAttribute(attn64_kernel<2>,
                         cudaFuncAttributeMaxDynamicSharedMemorySize, SMEM64);
    cudaFuncSetAttribute(attn64_kernel<3>,
                         cudaFuncAttributeMaxDynamicSharedMemorySize, SMEM64);

    rope_table_kernel<<<16, 256>>>();
    round_w_kernel<<<2560, 256>>>(W1, W2, W3, Wp);
    permute_in_kernel<<<dim3(512, 8, 4), dim3(32, 8)>>>(x);

    // Stage 1: time-axis attention (S=256)
    fp16_gemm_kernel<<<dim3(6, 512), 256, SMEMG>>>(Xh, Wr, QKVp, 768);
    attn1_kernel<<<dim3(256, 8, 2), 256>>>(QKVp);

    // Stage 2: freq-axis attention (S=64)
    fp16_gemm_kernel<<<dim3(6, 512), 256, SMEMG>>>(Xh, Wr + 196608, QKVp, 768);
    attn64_kernel<2><<<dim3(1024, 4), 256, SMEM64>>>(QKVp);

    // Stage 3: windowed attention (S=64)
    fp16_gemm_kernel<<<dim3(6, 512), 256, SMEMG>>>(Xh, Wr + 393216, QKVp, 768);
    attn64_kernel<3><<<dim3(1024, 4), 256, SMEM64>>>(QKVp);

    // Projection fused with output permute
    fp16_gemm_out_kernel<<<dim3(2, 512), 256, SMEMO>>>(Xh, Wr + 589824, out);
}

// round 15
// speedup vs baseline: 4.7337x; 1.0782x over previous
#include <cuda_runtime.h>
#include <cuda_bf16.h>
#include <cuda_fp16.h>
#include <math.h>
#include <stdint.h>

// Problem constants
#define BB 4
#define DD 256
#define TT 256
#define FF 64
#define HH 8
#define HD 32
#define NT (BB*TT*FF)          // 65536 tokens

// Scratch (no allocations allowed -> device globals)
__device__ __half g_Xh[(size_t)NT * DD];      // activations fp16 [tok][256]
__device__ float g_QK[(size_t)NT * 512];      // q|k (f32) [tok][512]
__device__ __half g_Vh[(size_t)NT * DD];      // v (fp16) [tok][256]
__device__ __half g_W[655360];                // weights fp16, B-layout [n][k]
__device__ float2 g_rope[256 * 16];           // cos/sin table [pos][j]

// ---------------------------------------------------------------------------
// Helpers
// ---------------------------------------------------------------------------
__device__ __forceinline__ void mma_f16(float* c, const uint32_t* a, const uint32_t* b) {
    asm volatile(
        "mma.sync.aligned.m16n8k16.row.col.f32.f16.f16.f32 "
        "{%0,%1,%2,%3}, {%4,%5,%6,%7}, {%8,%9}, {%0,%1,%2,%3};"
        : "+f"(c[0]), "+f"(c[1]), "+f"(c[2]), "+f"(c[3])
        : "r"(a[0]), "r"(a[1]), "r"(a[2]), "r"(a[3]), "r"(b[0]), "r"(b[1]));
}

__device__ __forceinline__ void mma_bf16(float* c, const uint32_t* a, const uint32_t* b) {
    asm volatile(
        "mma.sync.aligned.m16n8k16.row.col.f32.bf16.bf16.f32 "
        "{%0,%1,%2,%3}, {%4,%5,%6,%7}, {%8,%9}, {%0,%1,%2,%3};"
        : "+f"(c[0]), "+f"(c[1]), "+f"(c[2]), "+f"(c[3])
        : "r"(a[0]), "r"(a[1]), "r"(a[2]), "r"(a[3]), "r"(b[0]), "r"(b[1]));
}

__device__ __forceinline__ void ldsm_x4(uint32_t& r0, uint32_t& r1, uint32_t& r2,
                                        uint32_t& r3, uint32_t addr) {
    asm volatile("ldmatrix.sync.aligned.m8n8.x4.shared.b16 {%0,%1,%2,%3}, [%4];"
                 : "=r"(r0), "=r"(r1), "=r"(r2), "=r"(r3) : "r"(addr));
}
__device__ __forceinline__ void ldsm_x2(uint32_t& r0, uint32_t& r1, uint32_t addr) {
    asm volatile("ldmatrix.sync.aligned.m8n8.x2.shared.b16 {%0,%1}, [%2];"
                 : "=r"(r0), "=r"(r1) : "r"(addr));
}

__device__ __forceinline__ uint32_t pack_bf16_hi(float x0, float x1, float& r0, float& r1) {
    __nv_bfloat16 h0 = __float2bfloat16(x0);
    __nv_bfloat16 h1 = __float2bfloat16(x1);
    r0 = x0 - __bfloat162float(h0);
    r1 = x1 - __bfloat162float(h1);
    __nv_bfloat162 p = {h0, h1};
    return *(uint32_t*)&p;
}
__device__ __forceinline__ uint32_t pack_bf16(float x0, float x1) {
    __nv_bfloat162 p = {__float2bfloat16(x0), __float2bfloat16(x1)};
    return *(uint32_t*)&p;
}
__device__ __forceinline__ uint32_t pack_half2(float x0, float x1) {
    __half2 p = __floats2half2_rn(x0, x1);
    return *(uint32_t*)&p;
}

// cp.async helpers
__device__ __forceinline__ void cp_async16(uint32_t saddr, const void* g) {
    asm volatile("cp.async.cg.shared.global [%0], [%1], 16;" :: "r"(saddr), "l"(g));
}
__device__ __forceinline__ void cp_commit() {
    asm volatile("cp.async.commit_group;");
}
template <int N> __device__ __forceinline__ void cp_wait() {
    asm volatile("cp.async.wait_group %0;" :: "n"(N));
}
__device__ __forceinline__ uint32_t smem_u32(const void* p) {
    uint32_t a;
    asm("{ .reg .u64 t; cvta.to.shared.u64 t, %1; cvt.u32.u64 %0, t; }" : "=r"(a) : "l"(p));
    return a;
}

// ---------------------------------------------------------------------------
// RoPE table + weight prep (fp16, transposed to B-layout [n][k])
// ---------------------------------------------------------------------------
__global__ __launch_bounds__(256) void rope_table_kernel() {
    int i = blockIdx.x * 256 + threadIdx.x;   // 4096
    int p = i >> 4, j = i & 15;
    const float CEXP = 0.830482023721841f;
    float inv = exp2f(-(float)j * CEXP);
    float sn, cs;
    sincosf((float)p * inv, &sn, &cs);
    g_rope[i] = make_float2(cs, sn);
}

__global__ __launch_bounds__(256) void round_w_kernel(
    const float* __restrict__ W1, const float* __restrict__ W2,
    const float* __restrict__ W3, const float* __restrict__ Wp) {
    int i = blockIdx.x * 256 + threadIdx.x;   // 655360
    const float* src; int N; int base;
    if (i < 196608)      { src = W1; N = 768; base = 0; }
    else if (i < 393216) { src = W2; N = 768; base = 196608; }
    else if (i < 589824) { src = W3; N = 768; base = 393216; }
    else                 { src = Wp; N = 256; base = 589824; }
    int j = i - base;
    int n = j >> 8, k = j & 255;
    g_W[i] = __float2half(src[k * N + n]);
}

// ---------------------------------------------------------------------------
// Input permute
// ---------------------------------------------------------------------------
__global__ __launch_bounds__(256) void permute_in_kernel(const float* __restrict__ x) {
    __shared__ float tile[32][33];
    const int b = blockIdx.z;
    const int tf0 = blockIdx.x * 32;
    const int d0 = blockIdx.y * 32;
    const int tx = threadIdx.x, ty = threadIdx.y;
    #pragma unroll
    for (int i = 0; i < 4; i++)
        tile[ty + 8 * i][tx] = x[((size_t)(b * 256 + d0 + ty + 8 * i) * 16384) + tf0 + tx];
    __syncthreads();
    #pragma unroll
    for (int i = 0; i < 4; i++)
        g_Xh[((size_t)(b * 16384 + tf0 + ty + 8 * i)) * 256 + d0 + tx] =
            __float2half(tile[tx][ty + 8 * i]);
}

// ---------------------------------------------------------------------------
// FP16 GEMM for QKV: A[M,256] @ W[768,256]^T.
// q,k tiles (n < 512) -> g_QK f32 stride 512; v tiles -> g_Vh fp16 stride 256.
// cp.async 4-stage + ldmatrix; tile 128x128x32; 8 warps of 64x32.
// ---------------------------------------------------------------------------
__global__ __launch_bounds__(256, 2) void fp16_gemm_qkv_kernel(
    const __half* __restrict__ A, const __half* __restrict__ B,
    float* __restrict__ Cqk, __half* __restrict__ Vh)
{
    extern __shared__ uint32_t smg[];
    const uint32_t smem_addr = smem_u32(smg);

    const int tid = threadIdx.x;
    const int wid = tid >> 5;
    const int lane = tid & 31;
    const int tq = lane >> 2;
    const int tr = lane & 3;
    const int warp_m = (wid & 1) * 64;
    const int warp_n = (wid >> 1) * 32;
    const int bx = blockIdx.x * 128;
    const int by = blockIdx.y * 128;

    float acc[4][4][4];
    #pragma unroll
    for (int i = 0; i < 4; i++)
        #pragma unroll
        for (int j = 0; j < 4; j++)
            #pragma unroll
            for (int r = 0; r < 4; r++) acc[i][j][r] = 0.0f;

    const char* Ag = (const char*)(A + (size_t)by * 256);
    const char* Bg = (const char*)(B + (size_t)bx * 256);

    auto issue = [&](int kt) {
        uint32_t stA = smem_addr + (kt & 3) * 20480;
        uint32_t stB = stA + 10240;
        #pragma unroll
        for (int r = 0; r < 2; r++) {
            int idx = tid + r * 256;
            int row = idx >> 2, cc = idx & 3;
            cp_async16(stA + row * 80 + cc * 16, Ag + (size_t)row * 512 + kt * 64 + cc * 16);
            cp_async16(stB + row * 80 + cc * 16, Bg + (size_t)row * 512 + kt * 64 + cc * 16);
        }
        cp_commit();
    };

    const int l7 = lane & 7;
    const uint32_t aOff = (uint32_t)((warp_m + l7 + ((lane >> 3) & 1) * 8) * 20 +
                                     (lane >> 4) * 4) * 4;
    const uint32_t bOff = (uint32_t)((warp_n + l7) * 20 + ((lane >> 3) & 1) * 4) * 4;

    const int nt = 8;   // K=256 / 32
    issue(0);
    issue(1);
    issue(2);
    cp_wait<2>();
    __syncthreads();

    for (int kt = 0; kt < nt; kt++) {
        uint32_t stA = smem_addr + (kt & 3) * 20480;
        uint32_t stB = stA + 10240;

        #pragma unroll
        for (int s = 0; s < 2; s++) {
            uint32_t a[4][4], b[4][2];
            #pragma unroll
            for (int i = 0; i < 4; i++)
                ldsm_x4(a[i][0], a[i][1], a[i][2], a[i][3],
                        stA + aOff + i * 1280 + s * 32);
            #pragma unroll
            for (int j = 0; j < 4; j++)
                ldsm_x2(b[j][0], b[j][1], stB + bOff + j * 640 + s * 32);
            #pragma unroll
            for (int i = 0; i < 4; i++)
                #pragma unroll
                for (int j = 0; j < 4; j++)
                    mma_f16(acc[i][j], a[i], b[j]);
        }

        if (kt + 1 < nt) {
            if (kt + 3 < nt) {
                issue(kt + 3);
                cp_wait<2>();
            } else if (kt + 2 < nt) {
                cp_wait<1>();
            } else {
                cp_wait<0>();
            }
            __syncthreads();
        }
    }

    if (bx < 512) {
        // q,k: f32 into g_QK stride 512
        #pragma unroll
        for (int i = 0; i < 4; i++) {
            int row0 = by + warp_m + i * 16 + tq;
            #pragma unroll
            for (int j = 0; j < 4; j++) {
                int col0 = bx + warp_n + j * 8 + 2 * tr;
                *(float2*)&Cqk[(size_t)row0 * 512 + col0] =
                    make_float2(acc[i][j][0], acc[i][j][1]);
                *(float2*)&Cqk[(size_t)(row0 + 8) * 512 + col0] =
                    make_float2(acc[i][j][2], acc[i][j][3]);
            }
        }
    } else {
        // v: fp16 into g_Vh stride 256
        #pragma unroll
        for (int i = 0; i < 4; i++) {
            int row0 = by + warp_m + i * 16 + tq;
            #pragma unroll
            for (int j = 0; j < 4; j++) {
                int colv = (bx - 512) + warp_n + j * 8 + 2 * tr;
                *(uint32_t*)&Vh[(size_t)row0 * 256 + colv] =
                    pack_half2(acc[i][j][0], acc[i][j][1]);
                *(uint32_t*)&Vh[(size_t)(row0 + 8) * 256 + colv] =
                    pack_half2(acc[i][j][2], acc[i][j][3]);
            }
        }
    }
}

// ---------------------------------------------------------------------------
// Fused projection GEMM + output permute (unchanged from round 13/14).
// ---------------------------------------------------------------------------
__global__ __launch_bounds__(256, 2) void fp16_gemm_out_kernel(
    const __half* __restrict__ A, const __half* __restrict__ B,
    float* __restrict__ out)
{
    extern __shared__ uint32_t smg[];
    const uint32_t smem_addr = smem_u32(smg);

    const int tid = threadIdx.x;
    const int wid = tid >> 5;
    const int lane = tid & 31;
    const int tq = lane >> 2;
    const int tr = lane & 3;
    const int warp_m = (wid & 1) * 64;
    const int warp_n = (wid >> 1) * 32;
    const int bx = blockIdx.x * 128;
    const int by = blockIdx.y * 128;

    float acc[4][4][4];
    #pragma unroll
    for (int i = 0; i < 4; i++)
        #pragma unroll
        for (int j = 0; j < 4; j++)
            #pragma unroll
            for (int r = 0; r < 4; r++) acc[i][j][r] = 0.0f;

    const char* Ag = (const char*)(A + (size_t)by * 256);
    const char* Bg = (const char*)(B + (size_t)bx * 256);

    auto issue = [&](int kt) {
        uint32_t stA = smem_addr + (kt & 3) * 20480;
        uint32_t stB = stA + 10240;
        #pragma unroll
        for (int r = 0; r < 2; r++) {
            int idx = tid + r * 256;
            int row = idx >> 2, cc = idx & 3;
            cp_async16(stA + row * 80 + cc * 16, Ag + (size_t)row * 512 + kt * 64 + cc * 16);
            cp_async16(stB + row * 80 + cc * 16, Bg + (size_t)row * 512 + kt * 64 + cc * 16);
        }
        cp_commit();
    };

    const int l7 = lane & 7;
    const uint32_t aOff = (uint32_t)((warp_m + l7 + ((lane >> 3) & 1) * 8) * 20 +
                                     (lane >> 4) * 4) * 4;
    const uint32_t bOff = (uint32_t)((warp_n + l7) * 20 + ((lane >> 3) & 1) * 4) * 4;

    const int nt = 8;
    issue(0);
    issue(1);
    issue(2);
    cp_wait<2>();
    __syncthreads();

    for (int kt = 0; kt < nt; kt++) {
        uint32_t stA = smem_addr + (kt & 3) * 20480;
        uint32_t stB = stA + 10240;

        #pragma unroll
        for (int s = 0; s < 2; s++) {
            uint32_t a[4][4], b[4][2];
            #pragma unroll
            for (int i = 0; i < 4; i++)
                ldsm_x4(a[i][0], a[i][1], a[i][2], a[i][3],
                        stA + aOff + i * 1280 + s * 32);
            #pragma unroll
            for (int j = 0; j < 4; j++)
                ldsm_x2(b[j][0], b[j][1], stB + bOff + j * 640 + s * 32);
            #pragma unroll
            for (int i = 0; i < 4; i++)
                #pragma unroll
                for (int j = 0; j < 4; j++)
                    mma_f16(acc[i][j], a[i], b[j]);
        }

        if (kt + 1 < nt) {
            if (kt + 3 < nt) {
                issue(kt + 3);
                cp_wait<2>();
            } else if (kt + 2 < nt) {
                cp_wait<1>();
            } else {
                cp_wait<0>();
            }
            __syncthreads();
        }
    }

    __syncthreads();
    float* smT = (float*)smg;
    #pragma unroll
    for (int i = 0; i < 4; i++) {
        int row = warp_m + i * 16 + tq;
        #pragma unroll
        for (int j = 0; j < 4; j++) {
            int col = warp_n + j * 8 + 2 * tr;
            smT[col * 132 + row]           = acc[i][j][0];
            smT[(col + 1) * 132 + row]     = acc[i][j][1];
            smT[col * 132 + row + 8]       = acc[i][j][2];
            smT[(col + 1) * 132 + row + 8] = acc[i][j][3];
        }
    }
    __syncthreads();

    const int b = blockIdx.y >> 7;
    const int tf0 = (blockIdx.y << 7) & 16383;
    const int drow = tid >> 1, half = (tid & 1) * 64;
    const float* src = smT + drow * 132 + half;
    float* dst = out + ((size_t)(b * 256 + bx + drow) * 16384) + tf0 + half;
    #pragma unroll
    for (int q = 0; q < 16; q++)
        *(float4*)(dst + q * 4) = *(const float4*)(src + q * 4);
}

// ---------------------------------------------------------------------------
// Token index per stage.
// ---------------------------------------------------------------------------
template <int STAGE>
__device__ __forceinline__ int tok_of(int g, int p) {
    if (STAGE == 1) {
        int b = g >> 6, f = g & 63;
        return (b * 256 + p) * 64 + f;
    } else if (STAGE == 2) {
        return g * 64 + p;
    } else {
        int b = g >> 8, rem = g & 255;
        int i = rem >> 3, jf = rem & 7;
        int t = i * 8 + (p >> 3);
        int f = jf * 8 + (p & 7);
        return (b * 256 + t) * 64 + f;
    }
}

// ---------------------------------------------------------------------------
// Q fragments: bf16-split, built from g_QK (stride 512).
// ---------------------------------------------------------------------------
template <int STAGE>
__device__ __forceinline__ void load_q_frags(
    const float* __restrict__ qk, int g, int h, int p0,
    int tr, uint32_t qh[2][4], uint32_t ql[2][4])
{
    const float SCALE = 0.17677669529663687f;
    #pragma unroll
    for (int kt = 0; kt < 2; kt++)
        #pragma unroll
        for (int hv = 0; hv < 2; hv++) {
            int j = kt * 8 + tr + 4 * hv;
            #pragma unroll
            for (int rr = 0; rr < 2; rr++) {
                int p = p0 + rr * 8;
                int tok = tok_of<STAGE>(g, p);
                float2 q = *(const float2*)(qk + (size_t)tok * 512 + h * 32 + 2 * j);
                float2 cs = g_rope[p * 16 + j];
                float q0 = (q.x * cs.x - q.y * cs.y) * SCALE;
                float q1 = (q.y * cs.x + q.x * cs.y) * SCALE;
                float r0, r1;
                qh[kt][hv * 2 + rr] = pack_bf16_hi(q0, q1, r0, r1);
                ql[kt][hv * 2 + rr] = pack_bf16(r0, r1);
            }
        }
}

// X writer: fp16 pair
__device__ __forceinline__ void write_x_pair(size_t o, float v0, float v1) {
    *(uint32_t*)&g_Xh[o] = pack_half2(v0, v1);
}

// raw half pair fetch: (even tok, odd tok) at dim vd -> packed u32
template <int STAGE>
__device__ __forceinline__ uint32_t fetch_v_pair(const __half* __restrict__ vh,
                                                 int g, int h, int p_even, int vd) {
    uint16_t lo = *(const uint16_t*)(vh + (size_t)tok_of<STAGE>(g, p_even) * 256 + h * 32 + vd);
    uint16_t hi = *(const uint16_t*)(vh + (size_t)tok_of<STAGE>(g, p_even + 1) * 256 + h * 32 + vd);
    return (uint32_t)lo | ((uint32_t)hi << 16);
}

// ---------------------------------------------------------------------------
// Stage-1 attention: S=256, streamed KV; scores bf16-split, PV fp16-k16.
// ---------------------------------------------------------------------------
__global__ __launch_bounds__(256, 3) void attn1_kernel(
    const float* __restrict__ qk, const __half* __restrict__ vh)
{
    constexpr int BUF = 1920;
    __shared__ uint32_t smu[2 * BUF];

    const int g = blockIdx.x;
    const int h = blockIdx.y;
    const int qoff = blockIdx.z * 128;
    const int tid = threadIdx.x;
    const int w = tid >> 5, lane = tid & 31, tq = lane >> 2, tr = lane & 3;
    const int m_base = w * 16;

    uint32_t qh[2][4], ql[2][4];
    load_q_frags<1>(qk, g, h, qoff + m_base + tq, tr, qh, ql);

    const int kj = tid & 15;
    const int kk0 = tid >> 4;
    const int vd = tid & 31;
    const int vp0 = tid >> 5;
    float2 kx[2];
    uint32_t vxu[2];

    auto load_chunk = [&](int c) {
        int kb = c * 32;
        #pragma unroll
        for (int r = 0; r < 2; r++) {
            int tok = tok_of<1>(g, kb + r * 16 + kk0);
            kx[r] = *(const float2*)(qk + (size_t)tok * 512 + 256 + h * 32 + 2 * kj);
        }
        #pragma unroll
        for (int r = 0; r < 2; r++) {
            int kp = r * 8 + vp0;
            vxu[r] = fetch_v_pair<1>(vh, g, h, kb + 2 * kp, vd);
        }
    };
    auto store_chunk = [&](int c, int base) {
        int kb = c * 32;
        #pragma unroll
        for (int r = 0; r < 2; r++) {
            int k = r * 16 + kk0;
            float2 cs = g_rope[(kb + k) * 16 + kj];
            float k0 = kx[r].x * cs.x - kx[r].y * cs.y;
            float k1 = kx[r].y * cs.x + kx[r].x * cs.y;
            float r0, r1;
            smu[base + k * 20 + kj] = pack_bf16_hi(k0, k1, r0, r1);
            smu[base + 640 + k * 20 + kj] = pack_bf16(r0, r1);
        }
        #pragma unroll
        for (int r = 0; r < 2; r++) {
            int kp = r * 8 + vp0;
            smu[base + 1280 + vd * 20 + kp] = vxu[r];
        }
    };

    load_chunk(0);
    store_chunk(0, 0);
    __syncthreads();

    float co[4][4];
    #pragma unroll
    for (int i = 0; i < 4; i++)
        #pragma unroll
        for (int j = 0; j < 4; j++) co[i][j] = 0.0f;
    float mrun0 = -1e30f, mrun1 = -1e30f, lrun0 = 0.0f, lrun1 = 0.0f;

    for (int c = 0; c < 8; c++) {
        const uint32_t* Khi = smu + (c & 1) * BUF;
        const uint32_t* Klo = Khi + 640;
        const uint32_t* Vt = Khi + 1280;

        if (c < 7) load_chunk(c + 1);

        float sc[4][4];
        #pragma unroll
        for (int nt = 0; nt < 4; nt++) {
            const uint32_t* Krh = Khi + (nt * 8 + tq) * 20;
            const uint32_t* Krl = Klo + (nt * 8 + tq) * 20;
            float c0[4] = {0, 0, 0, 0}, c1[4] = {0, 0, 0, 0}, c2[4] = {0, 0, 0, 0};
            #pragma unroll
            for (int kt = 0; kt < 2; kt++) {
                uint32_t bh[2] = {Krh[kt * 8 + tr], Krh[kt * 8 + tr + 4]};
                uint32_t bl[2] = {Krl[kt * 8 + tr], Krl[kt * 8 + tr + 4]};
                mma_bf16(c0, qh[kt], bh);
                mma_bf16(c1, ql[kt], bh);
                mma_bf16(c2, qh[kt], bl);
            }
            #pragma unroll
            for (int r = 0; r < 4; r++) sc[nt][r] = c0[r] + c1[r] + c2[r];
        }

        float mx0 = -1e30f, mx1 = -1e30f;
        #pragma unroll
        for (int nt = 0; nt < 4; nt++) {
            mx0 = fmaxf(mx0, fmaxf(sc[nt][0], sc[nt][1]));
            mx1 = fmaxf(mx1, fmaxf(sc[nt][2], sc[nt][3]));
        }
        mx0 = fmaxf(mx0, __shfl_xor_sync(0xFFFFFFFFu, mx0, 1));
        mx0 = fmaxf(mx0, __shfl_xor_sync(0xFFFFFFFFu, mx0, 2));
        mx1 = fmaxf(mx1, __shfl_xor_sync(0xFFFFFFFFu, mx1, 1));
        mx1 = fmaxf(mx1, __shfl_xor_sync(0xFFFFFFFFu, mx1, 2));
        float mn0 = fmaxf(mrun0, mx0), mn1 = fmaxf(mrun1, mx1);
        float esc0 = __expf(mrun0 - mn0), esc1 = __expf(mrun1 - mn1);
        float s0 = 0.0f, s1 = 0.0f;
        #pragma unroll
        for (int nt = 0; nt < 4; nt++) {
            sc[nt][0] = __expf(sc[nt][0] - mn0);
            sc[nt][1] = __expf(sc[nt][1] - mn0);
            sc[nt][2] = __expf(sc[nt][2] - mn1);
            sc[nt][3] = __expf(sc[nt][3] - mn1);
            s0 += sc[nt][0] + sc[nt][1];
            s1 += sc[nt][2] + sc[nt][3];
        }
        s0 += __shfl_xor_sync(0xFFFFFFFFu, s0, 1);
        s0 += __shfl_xor_sync(0xFFFFFFFFu, s0, 2);
        s1 += __shfl_xor_sync(0xFFFFFFFFu, s1, 1);
        s1 += __shfl_xor_sync(0xFFFFFFFFu, s1, 2);
        lrun0 = lrun0 * esc0 + s0;
        lrun1 = lrun1 * esc1 + s1;
        mrun0 = mn0; mrun1 = mn1;
        #pragma unroll
        for (int nt2 = 0; nt2 < 4; nt2++) {
            co[nt2][0] *= esc0; co[nt2][1] *= esc0;
            co[nt2][2] *= esc1; co[nt2][3] *= esc1;
        }

        #pragma unroll
        for (int kt2 = 0; kt2 < 2; kt2++) {
            uint32_t a[4];
            a[0] = pack_half2(sc[2 * kt2][0], sc[2 * kt2][1]);
            a[1] = pack_half2(sc[2 * kt2][2], sc[2 * kt2][3]);
            a[2] = pack_half2(sc[2 * kt2 + 1][0], sc[2 * kt2 + 1][1]);
            a[3] = pack_half2(sc[2 * kt2 + 1][2], sc[2 * kt2 + 1][3]);
            #pragma unroll
            for (int nt2 = 0; nt2 < 4; nt2++) {
                const uint32_t* vr = Vt + (nt2 * 8 + tq) * 20 + kt2 * 8 + tr;
                uint32_t b[2] = {vr[0], vr[4]};
                mma_f16(co[nt2], a, b);
            }
        }

        if (c < 7) store_chunk(c + 1, ((c + 1) & 1) * BUF);
        __syncthreads();
    }

    float inv0 = 1.0f / lrun0, inv1 = 1.0f / lrun1;
    int p0r = qoff + m_base + tq;
    size_t o0 = (size_t)tok_of<1>(g, p0r) * 256 + h * 32;
    size_t o1 = (size_t)tok_of<1>(g, p0r + 8) * 256 + h * 32;
    #pragma unroll
    for (int nt2 = 0; nt2 < 4; nt2++) {
        int cc = nt2 * 8 + 2 * tr;
        write_x_pair(o0 + cc, co[nt2][0] * inv0, co[nt2][1] * inv0);
        write_x_pair(o1 + cc, co[nt2][2] * inv1, co[nt2][3] * inv1);
    }
}

// ---------------------------------------------------------------------------
// Stage-2/3 attention: S=64, 2 heads per block; PV fp16, V packed half2.
// ---------------------------------------------------------------------------
template <int STAGE>
__global__ __launch_bounds__(256, 3) void attn64_kernel(
    const float* __restrict__ qk, const __half* __restrict__ vh)
{
    constexpr int HS = 3712;
    extern __shared__ uint32_t smu2[];

    const int g = blockIdx.x;
    const int tid = threadIdx.x;
    const int w = tid >> 5, lane = tid & 31, tq = lane >> 2, tr = lane & 3;
    const int hh = w >> 2;
    const int h = blockIdx.y * 2 + hh;
    const int m_base = (w & 3) * 16;

    for (int idx = tid; idx < 2048; idx += 256) {
        int hl = idx >> 10, rem = idx & 1023;
        int k = rem >> 4, j = rem & 15;
        int tok = tok_of<STAGE>(g, k);
        const float* bp = qk + (size_t)tok * 512 + 256 + (blockIdx.y * 2 + hl) * 32;
        float x0 = bp[2 * j], x1 = bp[2 * j + 1];
        float2 cs = g_rope[k * 16 + j];
        float k0 = x0 * cs.x - x1 * cs.y;
        float k1 = x1 * cs.x + x0 * cs.y;
        float r0, r1;
        int base = hl * HS;
        smu2[base + k * 20 + j] = pack_bf16_hi(k0, k1, r0, r1);
        smu2[base + 1280 + k * 20 + j] = pack_bf16(r0, r1);
    }
    for (int idx = tid; idx < 2048; idx += 256) {
        int hl = idx >> 10, rem = idx & 1023;
        int kp = rem >> 5, d = rem & 31;
        smu2[hl * HS + 2560 + d * 36 + kp] =
            fetch_v_pair<STAGE>(vh, g, blockIdx.y * 2 + hl, 2 * kp, d);
    }

    uint32_t qh[2][4], ql[2][4];
    load_q_frags<STAGE>(qk, g, h, m_base + tq, tr, qh, ql);
    __syncthreads();

    const uint32_t* KhiB = smu2 + hh * HS;
    const uint32_t* KloB = KhiB + 1280;
    const uint32_t* VtB = KhiB + 2560;

    float co[4][4];
    #pragma unroll
    for (int i = 0; i < 4; i++)
        #pragma unroll
        for (int j = 0; j < 4; j++) co[i][j] = 0.0f;
    float mrun0 = -1e30f, mrun1 = -1e30f, lrun0 = 0.0f, lrun1 = 0.0f;

    #pragma unroll
    for (int j0 = 0; j0 < 64; j0 += 32) {
        float sc[4][4];
        #pragma unroll
        for (int nt = 0; nt < 4; nt++) {
            const uint32_t* Krh = KhiB + (j0 + nt * 8 + tq) * 20;
            const uint32_t* Krl = KloB + (j0 + nt * 8 + tq) * 20;
            float c0[4] = {0, 0, 0, 0}, c1[4] = {0, 0, 0, 0}, c2[4] = {0, 0, 0, 0};
            #pragma unroll
            for (int kt = 0; kt < 2; kt++) {
                uint32_t bh[2] = {Krh[kt * 8 + tr], Krh[kt * 8 + tr + 4]};
                uint32_t bl[2] = {Krl[kt * 8 + tr], Krl[kt * 8 + tr + 4]};
                mma_bf16(c0, qh[kt], bh);
                mma_bf16(c1, ql[kt], bh);
                mma_bf16(c2, qh[kt], bl);
            }
            #pragma unroll
            for (int r = 0; r < 4; r++) sc[nt][r] = c0[r] + c1[r] + c2[r];
        }

        float mx0 = -1e30f, mx1 = -1e30f;
        #pragma unroll
        for (int nt = 0; nt < 4; nt++) {
            mx0 = fmaxf(mx0, fmaxf(sc[nt][0], sc[nt][1]));
            mx1 = fmaxf(mx1, fmaxf(sc[nt][2], sc[nt][3]));
        }
        mx0 = fmaxf(mx0, __shfl_xor_sync(0xFFFFFFFFu, mx0, 1));
        mx0 = fmaxf(mx0, __shfl_xor_sync(0xFFFFFFFFu, mx0, 2));
        mx1 = fmaxf(mx1, __shfl_xor_sync(0xFFFFFFFFu, mx1, 1));
        mx1 = fmaxf(mx1, __shfl_xor_sync(0xFFFFFFFFu, mx1, 2));
        float mn0 = fmaxf(mrun0, mx0), mn1 = fmaxf(mrun1, mx1);
        float esc0 = __expf(mrun0 - mn0), esc1 = __expf(mrun1 - mn1);
        float s0 = 0.0f, s1 = 0.0f;
        #pragma unroll
        for (int nt = 0; nt < 4; nt++) {
            sc[nt][0] = __expf(sc[nt][0] - mn0);
            sc[nt][1] = __expf(sc[nt][1] - mn0);
            sc[nt][2] = __expf(sc[nt][2] - mn1);
            sc[nt][3] = __expf(sc[nt][3] - mn1);
            s0 += sc[nt][0] + sc[nt][1];
            s1 += sc[nt][2] + sc[nt][3];
        }
        s0 += __shfl_xor_sync(0xFFFFFFFFu, s0, 1);
        s0 += __shfl_xor_sync(0xFFFFFFFFu, s0, 2);
        s1 += __shfl_xor_sync(0xFFFFFFFFu, s1, 1);
        s1 += __shfl_xor_sync(0xFFFFFFFFu, s1, 2);
        lrun0 = lrun0 * esc0 + s0;
        lrun1 = lrun1 * esc1 + s1;
        mrun0 = mn0; mrun1 = mn1;
        #pragma unroll
        for (int nt2 = 0; nt2 < 4; nt2++) {
            co[nt2][0] *= esc0; co[nt2][1] *= esc0;
            co[nt2][2] *= esc1; co[nt2][3] *= esc1;
        }

        #pragma unroll
        for (int kt2 = 0; kt2 < 2; kt2++) {
            uint32_t a[4];
            a[0] = pack_half2(sc[2 * kt2][0], sc[2 * kt2][1]);
            a[1] = pack_half2(sc[2 * kt2][2], sc[2 * kt2][3]);
            a[2] = pack_half2(sc[2 * kt2 + 1][0], sc[2 * kt2 + 1][1]);
            a[3] = pack_half2(sc[2 * kt2 + 1][2], sc[2 * kt2 + 1][3]);
            #pragma unroll
            for (int nt2 = 0; nt2 < 4; nt2++) {
                const uint32_t* vr = VtB + (nt2 * 8 + tq) * 36 + (j0 >> 1) + kt2 * 8 + tr;
                uint32_t b[2] = {vr[0], vr[4]};
                mma_f16(co[nt2], a, b);
            }
        }
    }

    float inv0 = 1.0f / lrun0, inv1 = 1.0f / lrun1;
    int p0r = m_base + tq;
    size_t o0 = (size_t)tok_of<STAGE>(g, p0r) * 256 + h * 32;
    size_t o1 = (size_t)tok_of<STAGE>(g, p0r + 8) * 256 + h * 32;
    #pragma unroll
    for (int nt2 = 0; nt2 < 4; nt2++) {
        int cc = nt2 * 8 + 2 * tr;
        write_x_pair(o0 + cc, co[nt2][0] * inv0, co[nt2][1] * inv0);
        write_x_pair(o1 + cc, co[nt2][2] * inv1, co[nt2][3] * inv1);
    }
}

// ---------------------------------------------------------------------------
extern "C" void kernel_launch(void* const* d_in, const int* in_sizes, int n_in,
                              void* d_out, int out_size) {
    const float* x  = (const float*)d_in[0];
    const float* W1 = (const float*)d_in[1];
    const float* W2 = (const float*)d_in[2];
    const float* W3 = (const float*)d_in[3];
    const float* Wp = (const float*)d_in[4];
    float* out = (float*)d_out;

    __half* Xh; cudaGetSymbolAddress((void**)&Xh, g_Xh);
    __half* Wr; cudaGetSymbolAddress((void**)&Wr, g_W);
    float* QKp; cudaGetSymbolAddress((void**)&QKp, g_QK);
    __half* Vhp; cudaGetSymbolAddress((void**)&Vhp, g_Vh);

    const int SMEMG = 4 * 20480;               // 81920
    const int SMEMO = 81920;
    const int SMEM64 = 2 * 3712 * 4;           // 29696

    cudaFuncSetAttribute(fp16_gemm_qkv_kernel,
                         cudaFuncAttributeMaxDynamicSharedMemorySize, SMEMG);
    cudaFuncSetAttribute(fp16_gemm_out_kernel,
                         cudaFuncAttributeMaxDynamicSharedMemorySize, SMEMO);
    cudaFuncSetAttribute(attn64_kernel<2>,
                         cudaFuncAttributeMaxDynamicSharedMemorySize, SMEM64);
    cudaFuncSetAttribute(attn64_kernel<3>,
                         cudaFuncAttributeMaxDynamicSharedMemorySize, SMEM64);

    rope_table_kernel<<<16, 256>>>();
    round_w_kernel<<<2560, 256>>>(W1, W2, W3, Wp);
    permute_in_kernel<<<dim3(512, 8, 4), dim3(32, 8)>>>(x);

    // Stage 1: time-axis attention (S=256)
    fp16_gemm_qkv_kernel<<<dim3(6, 512), 256, SMEMG>>>(Xh, Wr, QKp, Vhp);
    attn1_kernel<<<dim3(256, 8, 2), 256>>>(QKp, Vhp);

    // Stage 2: freq-axis attention (S=64)
    fp16_gemm_qkv_kernel<<<dim3(6, 512), 256, SMEMG>>>(Xh, Wr + 196608, QKp, Vhp);
    attn64_kernel<2><<<dim3(1024, 4), 256, SMEM64>>>(QKp, Vhp);

    // Stage 3: windowed attention (S=64)
    fp16_gemm_qkv_kernel<<<dim3(6, 512), 256, SMEMG>>>(Xh, Wr + 393216, QKp, Vhp);
    attn64_kernel<3><<<dim3(1024, 4), 256, SMEM64>>>(QKp, Vhp);

    // Projection fused with output permute
    fp16_gemm_out_kernel<<<dim3(2, 512), 256, SMEMO>>>(Xh, Wr + 589824, out);
}

// round 16
// speedup vs baseline: 4.8063x; 1.0153x over previous
#include <cuda_runtime.h>
#include <cuda_bf16.h>
#include <cuda_fp16.h>
#include <math.h>
#include <stdint.h>

// Problem constants
#define BB 4
#define DD 256
#define TT 256
#define FF 64
#define HH 8
#define HD 32
#define NT (BB*TT*FF)          // 65536 tokens

// Scratch (no allocations allowed -> device globals)
__device__ __half g_Xh[(size_t)NT * DD];      // activations fp16 [tok][256]
__device__ float g_QK[(size_t)NT * 512];      // q|k (f32) [tok][512]
__device__ __half g_Vh[(size_t)NT * DD];      // v (fp16) [tok][256]
__device__ __half g_W[655360];                // weights fp16, B-layout [n][k]
__device__ float2 g_rope[256 * 16];           // cos/sin table [pos][j]

// ---------------------------------------------------------------------------
// Helpers
// ---------------------------------------------------------------------------
__device__ __forceinline__ void mma_f16(float* c, const uint32_t* a, const uint32_t* b) {
    asm volatile(
        "mma.sync.aligned.m16n8k16.row.col.f32.f16.f16.f32 "
        "{%0,%1,%2,%3}, {%4,%5,%6,%7}, {%8,%9}, {%0,%1,%2,%3};"
        : "+f"(c[0]), "+f"(c[1]), "+f"(c[2]), "+f"(c[3])
        : "r"(a[0]), "r"(a[1]), "r"(a[2]), "r"(a[3]), "r"(b[0]), "r"(b[1]));
}

__device__ __forceinline__ void mma_bf16(float* c, const uint32_t* a, const uint32_t* b) {
    asm volatile(
        "mma.sync.aligned.m16n8k16.row.col.f32.bf16.bf16.f32 "
        "{%0,%1,%2,%3}, {%4,%5,%6,%7}, {%8,%9}, {%0,%1,%2,%3};"
        : "+f"(c[0]), "+f"(c[1]), "+f"(c[2]), "+f"(c[3])
        : "r"(a[0]), "r"(a[1]), "r"(a[2]), "r"(a[3]), "r"(b[0]), "r"(b[1]));
}

__device__ __forceinline__ void ldsm_x4(uint32_t& r0, uint32_t& r1, uint32_t& r2,
                                        uint32_t& r3, uint32_t addr) {
    asm volatile("ldmatrix.sync.aligned.m8n8.x4.shared.b16 {%0,%1,%2,%3}, [%4];"
                 : "=r"(r0), "=r"(r1), "=r"(r2), "=r"(r3) : "r"(addr));
}
__device__ __forceinline__ void ldsm_x2(uint32_t& r0, uint32_t& r1, uint32_t addr) {
    asm volatile("ldmatrix.sync.aligned.m8n8.x2.shared.b16 {%0,%1}, [%2];"
                 : "=r"(r0), "=r"(r1) : "r"(addr));
}

__device__ __forceinline__ uint32_t pack_bf16_hi(float x0, float x1, float& r0, float& r1) {
    __nv_bfloat16 h0 = __float2bfloat16(x0);
    __nv_bfloat16 h1 = __float2bfloat16(x1);
    r0 = x0 - __bfloat162float(h0);
    r1 = x1 - __bfloat162float(h1);
    __nv_bfloat162 p = {h0, h1};
    return *(uint32_t*)&p;
}
__device__ __forceinline__ uint32_t pack_bf16(float x0, float x1) {
    __nv_bfloat162 p = {__float2bfloat16(x0), __float2bfloat16(x1)};
    return *(uint32_t*)&p;
}
__device__ __forceinline__ uint32_t pack_half2(float x0, float x1) {
    __half2 p = __floats2half2_rn(x0, x1);
    return *(uint32_t*)&p;
}

// cp.async helpers
__device__ __forceinline__ void cp_async16(uint32_t saddr, const void* g) {
    asm volatile("cp.async.cg.shared.global [%0], [%1], 16;" :: "r"(saddr), "l"(g));
}
__device__ __forceinline__ void cp_commit() {
    asm volatile("cp.async.commit_group;");
}
template <int N> __device__ __forceinline__ void cp_wait() {
    asm volatile("cp.async.wait_group %0;" :: "n"(N));
}
__device__ __forceinline__ uint32_t smem_u32(const void* p) {
    uint32_t a;
    asm("{ .reg .u64 t; cvta.to.shared.u64 t, %1; cvt.u32.u64 %0, t; }" : "=r"(a) : "l"(p));
    return a;
}

// ---------------------------------------------------------------------------
// RoPE table + weight prep (fp16, transposed to B-layout [n][k])
// ---------------------------------------------------------------------------
__global__ __launch_bounds__(256) void rope_table_kernel() {
    int i = blockIdx.x * 256 + threadIdx.x;   // 4096
    int p = i >> 4, j = i & 15;
    const float CEXP = 0.830482023721841f;
    float inv = exp2f(-(float)j * CEXP);
    float sn, cs;
    sincosf((float)p * inv, &sn, &cs);
    g_rope[i] = make_float2(cs, sn);
}

__global__ __launch_bounds__(256) void round_w_kernel(
    const float* __restrict__ W1, const float* __restrict__ W2,
    const float* __restrict__ W3, const float* __restrict__ Wp) {
    int i = blockIdx.x * 256 + threadIdx.x;   // 655360
    const float* src; int N; int base;
    if (i < 196608)      { src = W1; N = 768; base = 0; }
    else if (i < 393216) { src = W2; N = 768; base = 196608; }
    else if (i < 589824) { src = W3; N = 768; base = 393216; }
    else                 { src = Wp; N = 256; base = 589824; }
    int j = i - base;
    int n = j >> 8, k = j & 255;
    g_W[i] = __float2half(src[k * N + n]);
}

// ---------------------------------------------------------------------------
// Input permute
// ---------------------------------------------------------------------------
__global__ __launch_bounds__(256) void permute_in_kernel(const float* __restrict__ x) {
    __shared__ float tile[32][33];
    const int b = blockIdx.z;
    const int tf0 = blockIdx.x * 32;
    const int d0 = blockIdx.y * 32;
    const int tx = threadIdx.x, ty = threadIdx.y;
    #pragma unroll
    for (int i = 0; i < 4; i++)
        tile[ty + 8 * i][tx] = x[((size_t)(b * 256 + d0 + ty + 8 * i) * 16384) + tf0 + tx];
    __syncthreads();
    #pragma unroll
    for (int i = 0; i < 4; i++)
        g_Xh[((size_t)(b * 16384 + tf0 + ty + 8 * i)) * 256 + d0 + tx] =
            __float2half(tile[tx][ty + 8 * i]);
}

// ---------------------------------------------------------------------------
// FP16 GEMM for QKV: A[M,256] @ W[768,256]^T.
// q,k tiles (n < 512) -> g_QK f32 stride 512; v tiles -> g_Vh fp16 stride 256.
// ---------------------------------------------------------------------------
__global__ __launch_bounds__(256, 2) void fp16_gemm_qkv_kernel(
    const __half* __restrict__ A, const __half* __restrict__ B,
    float* __restrict__ Cqk, __half* __restrict__ Vh)
{
    extern __shared__ uint32_t smg[];
    const uint32_t smem_addr = smem_u32(smg);

    const int tid = threadIdx.x;
    const int wid = tid >> 5;
    const int lane = tid & 31;
    const int tq = lane >> 2;
    const int tr = lane & 3;
    const int warp_m = (wid & 1) * 64;
    const int warp_n = (wid >> 1) * 32;
    const int bx = blockIdx.x * 128;
    const int by = blockIdx.y * 128;

    float acc[4][4][4];
    #pragma unroll
    for (int i = 0; i < 4; i++)
        #pragma unroll
        for (int j = 0; j < 4; j++)
            #pragma unroll
            for (int r = 0; r < 4; r++) acc[i][j][r] = 0.0f;

    const char* Ag = (const char*)(A + (size_t)by * 256);
    const char* Bg = (const char*)(B + (size_t)bx * 256);

    auto issue = [&](int kt) {
        uint32_t stA = smem_addr + (kt & 3) * 20480;
        uint32_t stB = stA + 10240;
        #pragma unroll
        for (int r = 0; r < 2; r++) {
            int idx = tid + r * 256;
            int row = idx >> 2, cc = idx & 3;
            cp_async16(stA + row * 80 + cc * 16, Ag + (size_t)row * 512 + kt * 64 + cc * 16);
            cp_async16(stB + row * 80 + cc * 16, Bg + (size_t)row * 512 + kt * 64 + cc * 16);
        }
        cp_commit();
    };

    const int l7 = lane & 7;
    const uint32_t aOff = (uint32_t)((warp_m + l7 + ((lane >> 3) & 1) * 8) * 20 +
                                     (lane >> 4) * 4) * 4;
    const uint32_t bOff = (uint32_t)((warp_n + l7) * 20 + ((lane >> 3) & 1) * 4) * 4;

    const int nt = 8;   // K=256 / 32
    issue(0);
    issue(1);
    issue(2);
    cp_wait<2>();
    __syncthreads();

    for (int kt = 0; kt < nt; kt++) {
        uint32_t stA = smem_addr + (kt & 3) * 20480;
        uint32_t stB = stA + 10240;

        #pragma unroll
        for (int s = 0; s < 2; s++) {
            uint32_t a[4][4], b[4][2];
            #pragma unroll
            for (int i = 0; i < 4; i++)
                ldsm_x4(a[i][0], a[i][1], a[i][2], a[i][3],
                        stA + aOff + i * 1280 + s * 32);
            #pragma unroll
            for (int j = 0; j < 4; j++)
                ldsm_x2(b[j][0], b[j][1], stB + bOff + j * 640 + s * 32);
            #pragma unroll
            for (int i = 0; i < 4; i++)
                #pragma unroll
                for (int j = 0; j < 4; j++)
                    mma_f16(acc[i][j], a[i], b[j]);
        }

        if (kt + 1 < nt) {
            if (kt + 3 < nt) {
                issue(kt + 3);
                cp_wait<2>();
            } else if (kt + 2 < nt) {
                cp_wait<1>();
            } else {
                cp_wait<0>();
            }
            __syncthreads();
        }
    }

    if (bx < 512) {
        #pragma unroll
        for (int i = 0; i < 4; i++) {
            int row0 = by + warp_m + i * 16 + tq;
            #pragma unroll
            for (int j = 0; j < 4; j++) {
                int col0 = bx + warp_n + j * 8 + 2 * tr;
                *(float2*)&Cqk[(size_t)row0 * 512 + col0] =
                    make_float2(acc[i][j][0], acc[i][j][1]);
                *(float2*)&Cqk[(size_t)(row0 + 8) * 512 + col0] =
                    make_float2(acc[i][j][2], acc[i][j][3]);
            }
        }
    } else {
        #pragma unroll
        for (int i = 0; i < 4; i++) {
            int row0 = by + warp_m + i * 16 + tq;
            #pragma unroll
            for (int j = 0; j < 4; j++) {
                int colv = (bx - 512) + warp_n + j * 8 + 2 * tr;
                *(uint32_t*)&Vh[(size_t)row0 * 256 + colv] =
                    pack_half2(acc[i][j][0], acc[i][j][1]);
                *(uint32_t*)&Vh[(size_t)(row0 + 8) * 256 + colv] =
                    pack_half2(acc[i][j][2], acc[i][j][3]);
            }
        }
    }
}

// ---------------------------------------------------------------------------
// Fused projection GEMM + output permute.
// ---------------------------------------------------------------------------
__global__ __launch_bounds__(256, 2) void fp16_gemm_out_kernel(
    const __half* __restrict__ A, const __half* __restrict__ B,
    float* __restrict__ out)
{
    extern __shared__ uint32_t smg[];
    const uint32_t smem_addr = smem_u32(smg);

    const int tid = threadIdx.x;
    const int wid = tid >> 5;
    const int lane = tid & 31;
    const int tq = lane >> 2;
    const int tr = lane & 3;
    const int warp_m = (wid & 1) * 64;
    const int warp_n = (wid >> 1) * 32;
    const int bx = blockIdx.x * 128;
    const int by = blockIdx.y * 128;

    float acc[4][4][4];
    #pragma unroll
    for (int i = 0; i < 4; i++)
        #pragma unroll
        for (int j = 0; j < 4; j++)
            #pragma unroll
            for (int r = 0; r < 4; r++) acc[i][j][r] = 0.0f;

    const char* Ag = (const char*)(A + (size_t)by * 256);
    const char* Bg = (const char*)(B + (size_t)bx * 256);

    auto issue = [&](int kt) {
        uint32_t stA = smem_addr + (kt & 3) * 20480;
        uint32_t stB = stA + 10240;
        #pragma unroll
        for (int r = 0; r < 2; r++) {
            int idx = tid + r * 256;
            int row = idx >> 2, cc = idx & 3;
            cp_async16(stA + row * 80 + cc * 16, Ag + (size_t)row * 512 + kt * 64 + cc * 16);
            cp_async16(stB + row * 80 + cc * 16, Bg + (size_t)row * 512 + kt * 64 + cc * 16);
        }
        cp_commit();
    };

    const int l7 = lane & 7;
    const uint32_t aOff = (uint32_t)((warp_m + l7 + ((lane >> 3) & 1) * 8) * 20 +
                                     (lane >> 4) * 4) * 4;
    const uint32_t bOff = (uint32_t)((warp_n + l7) * 20 + ((lane >> 3) & 1) * 4) * 4;

    const int nt = 8;
    issue(0);
    issue(1);
    issue(2);
    cp_wait<2>();
    __syncthreads();

    for (int kt = 0; kt < nt; kt++) {
        uint32_t stA = smem_addr + (kt & 3) * 20480;
        uint32_t stB = stA + 10240;

        #pragma unroll
        for (int s = 0; s < 2; s++) {
            uint32_t a[4][4], b[4][2];
            #pragma unroll
            for (int i = 0; i < 4; i++)
                ldsm_x4(a[i][0], a[i][1], a[i][2], a[i][3],
                        stA + aOff + i * 1280 + s * 32);
            #pragma unroll
            for (int j = 0; j < 4; j++)
                ldsm_x2(b[j][0], b[j][1], stB + bOff + j * 640 + s * 32);
            #pragma unroll
            for (int i = 0; i < 4; i++)
                #pragma unroll
                for (int j = 0; j < 4; j++)
                    mma_f16(acc[i][j], a[i], b[j]);
        }

        if (kt + 1 < nt) {
            if (kt + 3 < nt) {
                issue(kt + 3);
                cp_wait<2>();
            } else if (kt + 2 < nt) {
                cp_wait<1>();
            } else {
                cp_wait<0>();
            }
            __syncthreads();
        }
    }

    __syncthreads();
    float* smT = (float*)smg;
    #pragma unroll
    for (int i = 0; i < 4; i++) {
        int row = warp_m + i * 16 + tq;
        #pragma unroll
        for (int j = 0; j < 4; j++) {
            int col = warp_n + j * 8 + 2 * tr;
            smT[col * 132 + row]           = acc[i][j][0];
            smT[(col + 1) * 132 + row]     = acc[i][j][1];
            smT[col * 132 + row + 8]       = acc[i][j][2];
            smT[(col + 1) * 132 + row + 8] = acc[i][j][3];
        }
    }
    __syncthreads();

    const int b = blockIdx.y >> 7;
    const int tf0 = (blockIdx.y << 7) & 16383;
    const int drow = tid >> 1, half = (tid & 1) * 64;
    const float* src = smT + drow * 132 + half;
    float* dst = out + ((size_t)(b * 256 + bx + drow) * 16384) + tf0 + half;
    #pragma unroll
    for (int q = 0; q < 16; q++)
        *(float4*)(dst + q * 4) = *(const float4*)(src + q * 4);
}

// ---------------------------------------------------------------------------
// Token index per stage.
// ---------------------------------------------------------------------------
template <int STAGE>
__device__ __forceinline__ int tok_of(int g, int p) {
    if (STAGE == 1) {
        int b = g >> 6, f = g & 63;
        return (b * 256 + p) * 64 + f;
    } else if (STAGE == 2) {
        return g * 64 + p;
    } else {
        int b = g >> 8, rem = g & 255;
        int i = rem >> 3, jf = rem & 7;
        int t = i * 8 + (p >> 3);
        int f = jf * 8 + (p & 7);
        return (b * 256 + t) * 64 + f;
    }
}

// ---------------------------------------------------------------------------
// Q fragments: bf16-split, built from g_QK (stride 512).
// ---------------------------------------------------------------------------
template <int STAGE>
__device__ __forceinline__ void load_q_frags(
    const float* __restrict__ qk, int g, int h, int p0,
    int tr, uint32_t qh[2][4], uint32_t ql[2][4])
{
    const float SCALE = 0.17677669529663687f;
    #pragma unroll
    for (int kt = 0; kt < 2; kt++)
        #pragma unroll
        for (int hv = 0; hv < 2; hv++) {
            int j = kt * 8 + tr + 4 * hv;
            #pragma unroll
            for (int rr = 0; rr < 2; rr++) {
                int p = p0 + rr * 8;
                int tok = tok_of<STAGE>(g, p);
                float2 q = *(const float2*)(qk + (size_t)tok * 512 + h * 32 + 2 * j);
                float2 cs = g_rope[p * 16 + j];
                float q0 = (q.x * cs.x - q.y * cs.y) * SCALE;
                float q1 = (q.y * cs.x + q.x * cs.y) * SCALE;
                float r0, r1;
                qh[kt][hv * 2 + rr] = pack_bf16_hi(q0, q1, r0, r1);
                ql[kt][hv * 2 + rr] = pack_bf16(r0, r1);
            }
        }
}

// X writer: fp16 pair
__device__ __forceinline__ void write_x_pair(size_t o, float v0, float v1) {
    *(uint32_t*)&g_Xh[o] = pack_half2(v0, v1);
}

// raw half pair fetch: (even tok, odd tok) at dim vd -> packed u32
template <int STAGE>
__device__ __forceinline__ uint32_t fetch_v_pair(const __half* __restrict__ vh,
                                                 int g, int h, int p_even, int vd) {
    uint16_t lo = *(const uint16_t*)(vh + (size_t)tok_of<STAGE>(g, p_even) * 256 + h * 32 + vd);
    uint16_t hi = *(const uint16_t*)(vh + (size_t)tok_of<STAGE>(g, p_even + 1) * 256 + h * 32 + vd);
    return (uint32_t)lo | ((uint32_t)hi << 16);
}

// ---------------------------------------------------------------------------
// Stage-1 attention: S=256, streamed KV; ldmatrix fragment loads.
// ---------------------------------------------------------------------------
__global__ __launch_bounds__(256, 3) void attn1_kernel(
    const float* __restrict__ qk, const __half* __restrict__ vh)
{
    constexpr int BUF = 1920;
    __shared__ uint32_t smu[2 * BUF];
    const uint32_t smemb = smem_u32(smu);

    const int g = blockIdx.x;
    const int h = blockIdx.y;
    const int qoff = blockIdx.z * 128;
    const int tid = threadIdx.x;
    const int w = tid >> 5, lane = tid & 31, tq = lane >> 2, tr = lane & 3;
    const int m_base = w * 16;
    // b-frag ldmatrix per-lane offset, stride 20 u32 rows (verified in GEMM)
    const uint32_t frag20 = (uint32_t)((lane & 7) * 20 + ((lane >> 3) & 1) * 4) * 4;

    uint32_t qh[2][4], ql[2][4];
    load_q_frags<1>(qk, g, h, qoff + m_base + tq, tr, qh, ql);

    const int kj = tid & 15;
    const int kk0 = tid >> 4;
    const int vd = tid & 31;
    const int vp0 = tid >> 5;
    float2 kx[2];
    uint32_t vxu[2];

    auto load_chunk = [&](int c) {
        int kb = c * 32;
        #pragma unroll
        for (int r = 0; r < 2; r++) {
            int tok = tok_of<1>(g, kb + r * 16 + kk0);
            kx[r] = *(const float2*)(qk + (size_t)tok * 512 + 256 + h * 32 + 2 * kj);
        }
        #pragma unroll
        for (int r = 0; r < 2; r++) {
            int kp = r * 8 + vp0;
            vxu[r] = fetch_v_pair<1>(vh, g, h, kb + 2 * kp, vd);
        }
    };
    auto store_chunk = [&](int c, int base) {
        int kb = c * 32;
        #pragma unroll
        for (int r = 0; r < 2; r++) {
            int k = r * 16 + kk0;
            float2 cs = g_rope[(kb + k) * 16 + kj];
            float k0 = kx[r].x * cs.x - kx[r].y * cs.y;
            float k1 = kx[r].y * cs.x + kx[r].x * cs.y;
            float r0, r1;
            smu[base + k * 20 + kj] = pack_bf16_hi(k0, k1, r0, r1);
            smu[base + 640 + k * 20 + kj] = pack_bf16(r0, r1);
        }
        #pragma unroll
        for (int r = 0; r < 2; r++) {
            int kp = r * 8 + vp0;
            smu[base + 1280 + vd * 20 + kp] = vxu[r];
        }
    };

    load_chunk(0);
    store_chunk(0, 0);
    __syncthreads();

    float co[4][4];
    #pragma unroll
    for (int i = 0; i < 4; i++)
        #pragma unroll
        for (int j = 0; j < 4; j++) co[i][j] = 0.0f;
    float mrun0 = -1e30f, mrun1 = -1e30f, lrun0 = 0.0f, lrun1 = 0.0f;

    for (int c = 0; c < 8; c++) {
        const uint32_t KhiA = smemb + (c & 1) * BUF * 4;
        const uint32_t KloA = KhiA + 2560;
        const uint32_t VtA  = KhiA + 5120;

        if (c < 7) load_chunk(c + 1);

        float sc[4][4];
        #pragma unroll
        for (int nt = 0; nt < 4; nt++) {
            float c0[4] = {0, 0, 0, 0}, c1[4] = {0, 0, 0, 0}, c2[4] = {0, 0, 0, 0};
            #pragma unroll
            for (int kt = 0; kt < 2; kt++) {
                uint32_t bh[2], bl[2];
                ldsm_x2(bh[0], bh[1], KhiA + nt * 640 + kt * 32 + frag20);
                ldsm_x2(bl[0], bl[1], KloA + nt * 640 + kt * 32 + frag20);
                mma_bf16(c0, qh[kt], bh);
                mma_bf16(c1, ql[kt], bh);
                mma_bf16(c2, qh[kt], bl);
            }
            #pragma unroll
            for (int r = 0; r < 4; r++) sc[nt][r] = c0[r] + c1[r] + c2[r];
        }

        float mx0 = -1e30f, mx1 = -1e30f;
        #pragma unroll
        for (int nt = 0; nt < 4; nt++) {
            mx0 = fmaxf(mx0, fmaxf(sc[nt][0], sc[nt][1]));
            mx1 = fmaxf(mx1, fmaxf(sc[nt][2], sc[nt][3]));
        }
        mx0 = fmaxf(mx0, __shfl_xor_sync(0xFFFFFFFFu, mx0, 1));
        mx0 = fmaxf(mx0, __shfl_xor_sync(0xFFFFFFFFu, mx0, 2));
        mx1 = fmaxf(mx1, __shfl_xor_sync(0xFFFFFFFFu, mx1, 1));
        mx1 = fmaxf(mx1, __shfl_xor_sync(0xFFFFFFFFu, mx1, 2));
        float mn0 = fmaxf(mrun0, mx0), mn1 = fmaxf(mrun1, mx1);
        float esc0 = __expf(mrun0 - mn0), esc1 = __expf(mrun1 - mn1);
        float s0 = 0.0f, s1 = 0.0f;
        #pragma unroll
        for (int nt = 0; nt < 4; nt++) {
            sc[nt][0] = __expf(sc[nt][0] - mn0);
            sc[nt][1] = __expf(sc[nt][1] - mn0);
            sc[nt][2] = __expf(sc[nt][2] - mn1);
            sc[nt][3] = __expf(sc[nt][3] - mn1);
            s0 += sc[nt][0] + sc[nt][1];
            s1 += sc[nt][2] + sc[nt][3];
        }
        s0 += __shfl_xor_sync(0xFFFFFFFFu, s0, 1);
        s0 += __shfl_xor_sync(0xFFFFFFFFu, s0, 2);
        s1 += __shfl_xor_sync(0xFFFFFFFFu, s1, 1);
        s1 += __shfl_xor_sync(0xFFFFFFFFu, s1, 2);
        lrun0 = lrun0 * esc0 + s0;
        lrun1 = lrun1 * esc1 + s1;
        mrun0 = mn0; mrun1 = mn1;
        #pragma unroll
        for (int nt2 = 0; nt2 < 4; nt2++) {
            co[nt2][0] *= esc0; co[nt2][1] *= esc0;
            co[nt2][2] *= esc1; co[nt2][3] *= esc1;
        }

        #pragma unroll
        for (int kt2 = 0; kt2 < 2; kt2++) {
            uint32_t a[4];
            a[0] = pack_half2(sc[2 * kt2][0], sc[2 * kt2][1]);
            a[1] = pack_half2(sc[2 * kt2][2], sc[2 * kt2][3]);
            a[2] = pack_half2(sc[2 * kt2 + 1][0], sc[2 * kt2 + 1][1]);
            a[3] = pack_half2(sc[2 * kt2 + 1][2], sc[2 * kt2 + 1][3]);
            #pragma unroll
            for (int nt2 = 0; nt2 < 4; nt2++) {
                uint32_t b[2];
                ldsm_x2(b[0], b[1], VtA + nt2 * 640 + kt2 * 32 + frag20);
                mma_f16(co[nt2], a, b);
            }
        }

        if (c < 7) store_chunk(c + 1, ((c + 1) & 1) * BUF);
        __syncthreads();
    }

    float inv0 = 1.0f / lrun0, inv1 = 1.0f / lrun1;
    int p0r = qoff + m_base + tq;
    size_t o0 = (size_t)tok_of<1>(g, p0r) * 256 + h * 32;
    size_t o1 = (size_t)tok_of<1>(g, p0r + 8) * 256 + h * 32;
    #pragma unroll
    for (int nt2 = 0; nt2 < 4; nt2++) {
        int cc = nt2 * 8 + 2 * tr;
        write_x_pair(o0 + cc, co[nt2][0] * inv0, co[nt2][1] * inv0);
        write_x_pair(o1 + cc, co[nt2][2] * inv1, co[nt2][3] * inv1);
    }
}

// ---------------------------------------------------------------------------
// Stage-2/3 attention: S=64, 2 heads per block; ldmatrix fragment loads.
// ---------------------------------------------------------------------------
template <int STAGE>
__global__ __launch_bounds__(256, 3) void attn64_kernel(
    const float* __restrict__ qk, const __half* __restrict__ vh)
{
    constexpr int HS = 3712;
    extern __shared__ uint32_t smu2[];
    const uint32_t smemb = smem_u32(smu2);

    const int g = blockIdx.x;
    const int tid = threadIdx.x;
    const int w = tid >> 5, lane = tid & 31, tq = lane >> 2, tr = lane & 3;
    const int hh = w >> 2;
    const int h = blockIdx.y * 2 + hh;
    const int m_base = (w & 3) * 16;
    const uint32_t frag20 = (uint32_t)((lane & 7) * 20 + ((lane >> 3) & 1) * 4) * 4;
    const uint32_t frag36 = (uint32_t)((lane & 7) * 36 + ((lane >> 3) & 1) * 4) * 4;

    for (int idx = tid; idx < 2048; idx += 256) {
        int hl = idx >> 10, rem = idx & 1023;
        int k = rem >> 4, j = rem & 15;
        int tok = tok_of<STAGE>(g, k);
        const float* bp = qk + (size_t)tok * 512 + 256 + (blockIdx.y * 2 + hl) * 32;
        float x0 = bp[2 * j], x1 = bp[2 * j + 1];
        float2 cs = g_rope[k * 16 + j];
        float k0 = x0 * cs.x - x1 * cs.y;
        float k1 = x1 * cs.x + x0 * cs.y;
        float r0, r1;
        int base = hl * HS;
        smu2[base + k * 20 + j] = pack_bf16_hi(k0, k1, r0, r1);
        smu2[base + 1280 + k * 20 + j] = pack_bf16(r0, r1);
    }
    for (int idx = tid; idx < 2048; idx += 256) {
        int hl = idx >> 10, rem = idx & 1023;
        int kp = rem >> 5, d = rem & 31;
        smu2[hl * HS + 2560 + d * 36 + kp] =
            fetch_v_pair<STAGE>(vh, g, blockIdx.y * 2 + hl, 2 * kp, d);
    }

    uint32_t qh[2][4], ql[2][4];
    load_q_frags<STAGE>(qk, g, h, m_base + tq, tr, qh, ql);
    __syncthreads();

    const uint32_t KhiA = smemb + hh * HS * 4;
    const uint32_t KloA = KhiA + 5120;
    const uint32_t VtA  = KhiA + 10240;

    float co[4][4];
    #pragma unroll
    for (int i = 0; i < 4; i++)
        #pragma unroll
        for (int j = 0; j < 4; j++) co[i][j] = 0.0f;
    float mrun0 = -1e30f, mrun1 = -1e30f, lrun0 = 0.0f, lrun1 = 0.0f;

    #pragma unroll
    for (int j0 = 0; j0 < 64; j0 += 32) {
        float sc[4][4];
        #pragma unroll
        for (int nt = 0; nt < 4; nt++) {
            float c0[4] = {0, 0, 0, 0}, c1[4] = {0, 0, 0, 0}, c2[4] = {0, 0, 0, 0};
            #pragma unroll
            for (int kt = 0; kt < 2; kt++) {
                uint32_t bh[2], bl[2];
                ldsm_x2(bh[0], bh[1], KhiA + j0 * 80 + nt * 640 + kt * 32 + frag20);
                ldsm_x2(bl[0], bl[1], KloA + j0 * 80 + nt * 640 + kt * 32 + frag20);
                mma_bf16(c0, qh[kt], bh);
                mma_bf16(c1, ql[kt], bh);
                mma_bf16(c2, qh[kt], bl);
            }
            #pragma unroll
            for (int r = 0; r < 4; r++) sc[nt][r] = c0[r] + c1[r] + c2[r];
        }

        float mx0 = -1e30f, mx1 = -1e30f;
        #pragma unroll
        for (int nt = 0; nt < 4; nt++) {
            mx0 = fmaxf(mx0, fmaxf(sc[nt][0], sc[nt][1]));
            mx1 = fmaxf(mx1, fmaxf(sc[nt][2], sc[nt][3]));
        }
        mx0 = fmaxf(mx0, __shfl_xor_sync(0xFFFFFFFFu, mx0, 1));
        mx0 = fmaxf(mx0, __shfl_xor_sync(0xFFFFFFFFu, mx0, 2));
        mx1 = fmaxf(mx1, __shfl_xor_sync(0xFFFFFFFFu, mx1, 1));
        mx1 = fmaxf(mx1, __shfl_xor_sync(0xFFFFFFFFu, mx1, 2));
        float mn0 = fmaxf(mrun0, mx0), mn1 = fmaxf(mrun1, mx1);
        float esc0 = __expf(mrun0 - mn0), esc1 = __expf(mrun1 - mn1);
        float s0 = 0.0f, s1 = 0.0f;
        #pragma unroll
        for (int nt = 0; nt < 4; nt++) {
            sc[nt][0] = __expf(sc[nt][0] - mn0);
            sc[nt][1] = __expf(sc[nt][1] - mn0);
            sc[nt][2] = __expf(sc[nt][2] - mn1);
            sc[nt][3] = __expf(sc[nt][3] - mn1);
            s0 += sc[nt][0] + sc[nt][1];
            s1 += sc[nt][2] + sc[nt][3];
        }
        s0 += __shfl_xor_sync(0xFFFFFFFFu, s0, 1);
        s0 += __shfl_xor_sync(0xFFFFFFFFu, s0, 2);
        s1 += __shfl_xor_sync(0xFFFFFFFFu, s1, 1);
        s1 += __shfl_xor_sync(0xFFFFFFFFu, s1, 2);
        lrun0 = lrun0 * esc0 + s0;
        lrun1 = lrun1 * esc1 + s1;
        mrun0 = mn0; mrun1 = mn1;
        #pragma unroll
        for (int nt2 = 0; nt2 < 4; nt2++) {
            co[nt2][0] *= esc0; co[nt2][1] *= esc0;
            co[nt2][2] *= esc1; co[nt2][3] *= esc1;
        }

        #pragma unroll
        for (int kt2 = 0; kt2 < 2; kt2++) {
            uint32_t a[4];
            a[0] = pack_half2(sc[2 * kt2][0], sc[2 * kt2][1]);
            a[1] = pack_half2(sc[2 * kt2][2], sc[2 * kt2][3]);
            a[2] = pack_half2(sc[2 * kt2 + 1][0], sc[2 * kt2 + 1][1]);
            a[3] = pack_half2(sc[2 * kt2 + 1][2], sc[2 * kt2 + 1][3]);
            #pragma unroll
            for (int nt2 = 0; nt2 < 4; nt2++) {
                uint32_t b[2];
                ldsm_x2(b[0], b[1],
                        VtA + nt2 * 1152 + (j0 >> 1) * 4 + kt2 * 32 + frag36);
                mma_f16(co[nt2], a, b);
            }
        }
    }

    float inv0 = 1.0f / lrun0, inv1 = 1.0f / lrun1;
    int p0r = m_base + tq;
    size_t o0 = (size_t)tok_of<STAGE>(g, p0r) * 256 + h * 32;
    size_t o1 = (size_t)tok_of<STAGE>(g, p0r + 8) * 256 + h * 32;
    #pragma unroll
    for (int nt2 = 0; nt2 < 4; nt2++) {
        int cc = nt2 * 8 + 2 * tr;
        write_x_pair(o0 + cc, co[nt2][0] * inv0, co[nt2][1] * inv0);
        write_x_pair(o1 + cc, co[nt2][2] * inv1, co[nt2][3] * inv1);
    }
}

// ---------------------------------------------------------------------------
extern "C" void kernel_launch(void* const* d_in, const int* in_sizes, int n_in,
                              void* d_out, int out_size) {
    const float* x  = (const float*)d_in[0];
    const float* W1 = (const float*)d_in[1];
    const float* W2 = (const float*)d_in[2];
    const float* W3 = (const float*)d_in[3];
    const float* Wp = (const float*)d_in[4];
    float* out = (float*)d_out;

    __half* Xh; cudaGetSymbolAddress((void**)&Xh, g_Xh);
    __half* Wr; cudaGetSymbolAddress((void**)&Wr, g_W);
    float* QKp; cudaGetSymbolAddress((void**)&QKp, g_QK);
    __half* Vhp; cudaGetSymbolAddress((void**)&Vhp, g_Vh);

    const int SMEMG = 4 * 20480;               // 81920
    const int SMEMO = 81920;
    const int SMEM64 = 2 * 3712 * 4;           // 29696

    cudaFuncSetAttribute(fp16_gemm_qkv_kernel,
                         cudaFuncAttributeMaxDynamicSharedMemorySize, SMEMG);
    cudaFuncSetAttribute(fp16_gemm_out_kernel,
                         cudaFuncAttributeMaxDynamicSharedMemorySize, SMEMO);
    cudaFuncSetAttribute(attn64_kernel<2>,
                         cudaFuncAttributeMaxDynamicSharedMemorySize, SMEM64);
    cudaFuncSetAttribute(attn64_kernel<3>,
                         cudaFuncAttributeMaxDynamicSharedMemorySize, SMEM64);

    rope_table_kernel<<<16, 256>>>();
    round_w_kernel<<<2560, 256>>>(W1, W2, W3, Wp);
    permute_in_kernel<<<dim3(512, 8, 4), dim3(32, 8)>>>(x);

    // Stage 1: time-axis attention (S=256)
    fp16_gemm_qkv_kernel<<<dim3(6, 512), 256, SMEMG>>>(Xh, Wr, QKp, Vhp);
    attn1_kernel<<<dim3(256, 8, 2), 256>>>(QKp, Vhp);

    // Stage 2: freq-axis attention (S=64)
    fp16_gemm_qkv_kernel<<<dim3(6, 512), 256, SMEMG>>>(Xh, Wr + 196608, QKp, Vhp);
    attn64_kernel<2><<<dim3(1024, 4), 256, SMEM64>>>(QKp, Vhp);

    // Stage 3: windowed attention (S=64)
    fp16_gemm_qkv_kernel<<<dim3(6, 512), 256, SMEMG>>>(Xh, Wr + 393216, QKp, Vhp);
    attn64_kernel<3><<<dim3(1024, 4), 256, SMEM64>>>(QKp, Vhp);

    // Projection fused with output permute
    fp16_gemm_out_kernel<<<dim3(2, 512), 256, SMEMO>>>(Xh, Wr + 589824, out);
}

// round 17
// speedup vs baseline: 4.8310x; 1.0051x over previous
#include <cuda_runtime.h>
#include <cuda_bf16.h>
#include <cuda_fp16.h>
#include <math.h>
#include <stdint.h>

// Problem constants
#define BB 4
#define DD 256
#define TT 256
#define FF 64
#define HH 8
#define HD 32
#define NT (BB*TT*FF)          // 65536 tokens

// Scratch (no allocations allowed -> device globals)
__device__ __half g_Xh[(size_t)NT * DD];      // activations fp16 [tok][256]
__device__ float g_QK[(size_t)NT * 512];      // q|k (f32) [tok][512]
__device__ __half g_Vh[(size_t)NT * DD];      // v (fp16) [tok][256]
__device__ __half g_W[655360];                // weights fp16, B-layout [n][k]
__device__ float2 g_rope[256 * 16];           // cos/sin table [pos][j]

// ---------------------------------------------------------------------------
// Helpers
// ---------------------------------------------------------------------------
__device__ __forceinline__ void mma_f16(float* c, const uint32_t* a, const uint32_t* b) {
    asm volatile(
        "mma.sync.aligned.m16n8k16.row.col.f32.f16.f16.f32 "
        "{%0,%1,%2,%3}, {%4,%5,%6,%7}, {%8,%9}, {%0,%1,%2,%3};"
        : "+f"(c[0]), "+f"(c[1]), "+f"(c[2]), "+f"(c[3])
        : "r"(a[0]), "r"(a[1]), "r"(a[2]), "r"(a[3]), "r"(b[0]), "r"(b[1]));
}

__device__ __forceinline__ void mma_bf16(float* c, const uint32_t* a, const uint32_t* b) {
    asm volatile(
        "mma.sync.aligned.m16n8k16.row.col.f32.bf16.bf16.f32 "
        "{%0,%1,%2,%3}, {%4,%5,%6,%7}, {%8,%9}, {%0,%1,%2,%3};"
        : "+f"(c[0]), "+f"(c[1]), "+f"(c[2]), "+f"(c[3])
        : "r"(a[0]), "r"(a[1]), "r"(a[2]), "r"(a[3]), "r"(b[0]), "r"(b[1]));
}

__device__ __forceinline__ void ldsm_x4(uint32_t& r0, uint32_t& r1, uint32_t& r2,
                                        uint32_t& r3, uint32_t addr) {
    asm volatile("ldmatrix.sync.aligned.m8n8.x4.shared.b16 {%0,%1,%2,%3}, [%4];"
                 : "=r"(r0), "=r"(r1), "=r"(r2), "=r"(r3) : "r"(addr));
}
__device__ __forceinline__ void ldsm_x2(uint32_t& r0, uint32_t& r1, uint32_t addr) {
    asm volatile("ldmatrix.sync.aligned.m8n8.x2.shared.b16 {%0,%1}, [%2];"
                 : "=r"(r0), "=r"(r1) : "r"(addr));
}

__device__ __forceinline__ uint32_t pack_bf16_hi(float x0, float x1, float& r0, float& r1) {
    __nv_bfloat16 h0 = __float2bfloat16(x0);
    __nv_bfloat16 h1 = __float2bfloat16(x1);
    r0 = x0 - __bfloat162float(h0);
    r1 = x1 - __bfloat162float(h1);
    __nv_bfloat162 p = {h0, h1};
    return *(uint32_t*)&p;
}
__device__ __forceinline__ uint32_t pack_bf16(float x0, float x1) {
    __nv_bfloat162 p = {__float2bfloat16(x0), __float2bfloat16(x1)};
    return *(uint32_t*)&p;
}
__device__ __forceinline__ uint32_t pack_half2(float x0, float x1) {
    __half2 p = __floats2half2_rn(x0, x1);
    return *(uint32_t*)&p;
}

// cp.async helpers
__device__ __forceinline__ void cp_async16(uint32_t saddr, const void* g) {
    asm volatile("cp.async.cg.shared.global [%0], [%1], 16;" :: "r"(saddr), "l"(g));
}
__device__ __forceinline__ void cp_commit() {
    asm volatile("cp.async.commit_group;");
}
template <int N> __device__ __forceinline__ void cp_wait() {
    asm volatile("cp.async.wait_group %0;" :: "n"(N));
}
__device__ __forceinline__ uint32_t smem_u32(const void* p) {
    uint32_t a;
    asm("{ .reg .u64 t; cvta.to.shared.u64 t, %1; cvt.u32.u64 %0, t; }" : "=r"(a) : "l"(p));
    return a;
}

// ---------------------------------------------------------------------------
// RoPE table + weight prep (fp16, transposed to B-layout [n][k])
// ---------------------------------------------------------------------------
__global__ __launch_bounds__(256) void rope_table_kernel() {
    int i = blockIdx.x * 256 + threadIdx.x;   // 4096
    int p = i >> 4, j = i & 15;
    const float CEXP = 0.830482023721841f;
    float inv = exp2f(-(float)j * CEXP);
    float sn, cs;
    sincosf((float)p * inv, &sn, &cs);
    g_rope[i] = make_float2(cs, sn);
}

__global__ __launch_bounds__(256) void round_w_kernel(
    const float* __restrict__ W1, const float* __restrict__ W2,
    const float* __restrict__ W3, const float* __restrict__ Wp) {
    int i = blockIdx.x * 256 + threadIdx.x;   // 655360
    const float* src; int N; int base;
    if (i < 196608)      { src = W1; N = 768; base = 0; }
    else if (i < 393216) { src = W2; N = 768; base = 196608; }
    else if (i < 589824) { src = W3; N = 768; base = 393216; }
    else                 { src = Wp; N = 256; base = 589824; }
    int j = i - base;
    int n = j >> 8, k = j & 255;
    g_W[i] = __float2half(src[k * N + n]);
}

// ---------------------------------------------------------------------------
// Input permute
// ---------------------------------------------------------------------------
__global__ __launch_bounds__(256) void permute_in_kernel(const float* __restrict__ x) {
    __shared__ float tile[32][33];
    const int b = blockIdx.z;
    const int tf0 = blockIdx.x * 32;
    const int d0 = blockIdx.y * 32;
    const int tx = threadIdx.x, ty = threadIdx.y;
    #pragma unroll
    for (int i = 0; i < 4; i++)
        tile[ty + 8 * i][tx] = x[((size_t)(b * 256 + d0 + ty + 8 * i) * 16384) + tf0 + tx];
    __syncthreads();
    #pragma unroll
    for (int i = 0; i < 4; i++)
        g_Xh[((size_t)(b * 16384 + tf0 + ty + 8 * i)) * 256 + d0 + tx] =
            __float2half(tile[tx][ty + 8 * i]);
}

// ---------------------------------------------------------------------------
// FP16 GEMM for QKV (unchanged from round 16).
// ---------------------------------------------------------------------------
__global__ __launch_bounds__(256, 2) void fp16_gemm_qkv_kernel(
    const __half* __restrict__ A, const __half* __restrict__ B,
    float* __restrict__ Cqk, __half* __restrict__ Vh)
{
    extern __shared__ uint32_t smg[];
    const uint32_t smem_addr = smem_u32(smg);

    const int tid = threadIdx.x;
    const int wid = tid >> 5;
    const int lane = tid & 31;
    const int tq = lane >> 2;
    const int tr = lane & 3;
    const int warp_m = (wid & 1) * 64;
    const int warp_n = (wid >> 1) * 32;
    const int bx = blockIdx.x * 128;
    const int by = blockIdx.y * 128;

    float acc[4][4][4];
    #pragma unroll
    for (int i = 0; i < 4; i++)
        #pragma unroll
        for (int j = 0; j < 4; j++)
            #pragma unroll
            for (int r = 0; r < 4; r++) acc[i][j][r] = 0.0f;

    const char* Ag = (const char*)(A + (size_t)by * 256);
    const char* Bg = (const char*)(B + (size_t)bx * 256);

    auto issue = [&](int kt) {
        uint32_t stA = smem_addr + (kt & 3) * 20480;
        uint32_t stB = stA + 10240;
        #pragma unroll
        for (int r = 0; r < 2; r++) {
            int idx = tid + r * 256;
            int row = idx >> 2, cc = idx & 3;
            cp_async16(stA + row * 80 + cc * 16, Ag + (size_t)row * 512 + kt * 64 + cc * 16);
            cp_async16(stB + row * 80 + cc * 16, Bg + (size_t)row * 512 + kt * 64 + cc * 16);
        }
        cp_commit();
    };

    const int l7 = lane & 7;
    const uint32_t aOff = (uint32_t)((warp_m + l7 + ((lane >> 3) & 1) * 8) * 20 +
                                     (lane >> 4) * 4) * 4;
    const uint32_t bOff = (uint32_t)((warp_n + l7) * 20 + ((lane >> 3) & 1) * 4) * 4;

    const int nt = 8;
    issue(0);
    issue(1);
    issue(2);
    cp_wait<2>();
    __syncthreads();

    for (int kt = 0; kt < nt; kt++) {
        uint32_t stA = smem_addr + (kt & 3) * 20480;
        uint32_t stB = stA + 10240;

        #pragma unroll
        for (int s = 0; s < 2; s++) {
            uint32_t a[4][4], b[4][2];
            #pragma unroll
            for (int i = 0; i < 4; i++)
                ldsm_x4(a[i][0], a[i][1], a[i][2], a[i][3],
                        stA + aOff + i * 1280 + s * 32);
            #pragma unroll
            for (int j = 0; j < 4; j++)
                ldsm_x2(b[j][0], b[j][1], stB + bOff + j * 640 + s * 32);
            #pragma unroll
            for (int i = 0; i < 4; i++)
                #pragma unroll
                for (int j = 0; j < 4; j++)
                    mma_f16(acc[i][j], a[i], b[j]);
        }

        if (kt + 1 < nt) {
            if (kt + 3 < nt) {
                issue(kt + 3);
                cp_wait<2>();
            } else if (kt + 2 < nt) {
                cp_wait<1>();
            } else {
                cp_wait<0>();
            }
            __syncthreads();
        }
    }

    if (bx < 512) {
        #pragma unroll
        for (int i = 0; i < 4; i++) {
            int row0 = by + warp_m + i * 16 + tq;
            #pragma unroll
            for (int j = 0; j < 4; j++) {
                int col0 = bx + warp_n + j * 8 + 2 * tr;
                *(float2*)&Cqk[(size_t)row0 * 512 + col0] =
                    make_float2(acc[i][j][0], acc[i][j][1]);
                *(float2*)&Cqk[(size_t)(row0 + 8) * 512 + col0] =
                    make_float2(acc[i][j][2], acc[i][j][3]);
            }
        }
    } else {
        #pragma unroll
        for (int i = 0; i < 4; i++) {
            int row0 = by + warp_m + i * 16 + tq;
            #pragma unroll
            for (int j = 0; j < 4; j++) {
                int colv = (bx - 512) + warp_n + j * 8 + 2 * tr;
                *(uint32_t*)&Vh[(size_t)row0 * 256 + colv] =
                    pack_half2(acc[i][j][0], acc[i][j][1]);
                *(uint32_t*)&Vh[(size_t)(row0 + 8) * 256 + colv] =
                    pack_half2(acc[i][j][2], acc[i][j][3]);
            }
        }
    }
}

// ---------------------------------------------------------------------------
// Fused projection GEMM + output permute (unchanged).
// ---------------------------------------------------------------------------
__global__ __launch_bounds__(256, 2) void fp16_gemm_out_kernel(
    const __half* __restrict__ A, const __half* __restrict__ B,
    float* __restrict__ out)
{
    extern __shared__ uint32_t smg[];
    const uint32_t smem_addr = smem_u32(smg);

    const int tid = threadIdx.x;
    const int wid = tid >> 5;
    const int lane = tid & 31;
    const int tq = lane >> 2;
    const int tr = lane & 3;
    const int warp_m = (wid & 1) * 64;
    const int warp_n = (wid >> 1) * 32;
    const int bx = blockIdx.x * 128;
    const int by = blockIdx.y * 128;

    float acc[4][4][4];
    #pragma unroll
    for (int i = 0; i < 4; i++)
        #pragma unroll
        for (int j = 0; j < 4; j++)
            #pragma unroll
            for (int r = 0; r < 4; r++) acc[i][j][r] = 0.0f;

    const char* Ag = (const char*)(A + (size_t)by * 256);
    const char* Bg = (const char*)(B + (size_t)bx * 256);

    auto issue = [&](int kt) {
        uint32_t stA = smem_addr + (kt & 3) * 20480;
        uint32_t stB = stA + 10240;
        #pragma unroll
        for (int r = 0; r < 2; r++) {
            int idx = tid + r * 256;
            int row = idx >> 2, cc = idx & 3;
            cp_async16(stA + row * 80 + cc * 16, Ag + (size_t)row * 512 + kt * 64 + cc * 16);
            cp_async16(stB + row * 80 + cc * 16, Bg + (size_t)row * 512 + kt * 64 + cc * 16);
        }
        cp_commit();
    };

    const int l7 = lane & 7;
    const uint32_t aOff = (uint32_t)((warp_m + l7 + ((lane >> 3) & 1) * 8) * 20 +
                                     (lane >> 4) * 4) * 4;
    const uint32_t bOff = (uint32_t)((warp_n + l7) * 20 + ((lane >> 3) & 1) * 4) * 4;

    const int nt = 8;
    issue(0);
    issue(1);
    issue(2);
    cp_wait<2>();
    __syncthreads();

    for (int kt = 0; kt < nt; kt++) {
        uint32_t stA = smem_addr + (kt & 3) * 20480;
        uint32_t stB = stA + 10240;

        #pragma unroll
        for (int s = 0; s < 2; s++) {
            uint32_t a[4][4], b[4][2];
            #pragma unroll
            for (int i = 0; i < 4; i++)
                ldsm_x4(a[i][0], a[i][1], a[i][2], a[i][3],
                        stA + aOff + i * 1280 + s * 32);
            #pragma unroll
            for (int j = 0; j < 4; j++)
                ldsm_x2(b[j][0], b[j][1], stB + bOff + j * 640 + s * 32);
            #pragma unroll
            for (int i = 0; i < 4; i++)
                #pragma unroll
                for (int j = 0; j < 4; j++)
                    mma_f16(acc[i][j], a[i], b[j]);
        }

        if (kt + 1 < nt) {
            if (kt + 3 < nt) {
                issue(kt + 3);
                cp_wait<2>();
            } else if (kt + 2 < nt) {
                cp_wait<1>();
            } else {
                cp_wait<0>();
            }
            __syncthreads();
        }
    }

    __syncthreads();
    float* smT = (float*)smg;
    #pragma unroll
    for (int i = 0; i < 4; i++) {
        int row = warp_m + i * 16 + tq;
        #pragma unroll
        for (int j = 0; j < 4; j++) {
            int col = warp_n + j * 8 + 2 * tr;
            smT[col * 132 + row]           = acc[i][j][0];
            smT[(col + 1) * 132 + row]     = acc[i][j][1];
            smT[col * 132 + row + 8]       = acc[i][j][2];
            smT[(col + 1) * 132 + row + 8] = acc[i][j][3];
        }
    }
    __syncthreads();

    const int b = blockIdx.y >> 7;
    const int tf0 = (blockIdx.y << 7) & 16383;
    const int drow = tid >> 1, half = (tid & 1) * 64;
    const float* src = smT + drow * 132 + half;
    float* dst = out + ((size_t)(b * 256 + bx + drow) * 16384) + tf0 + half;
    #pragma unroll
    for (int q = 0; q < 16; q++)
        *(float4*)(dst + q * 4) = *(const float4*)(src + q * 4);
}

// ---------------------------------------------------------------------------
// Token index per stage.
// ---------------------------------------------------------------------------
template <int STAGE>
__device__ __forceinline__ int tok_of(int g, int p) {
    if (STAGE == 1) {
        int b = g >> 6, f = g & 63;
        return (b * 256 + p) * 64 + f;
    } else if (STAGE == 2) {
        return g * 64 + p;
    } else {
        int b = g >> 8, rem = g & 255;
        int i = rem >> 3, jf = rem & 7;
        int t = i * 8 + (p >> 3);
        int f = jf * 8 + (p & 7);
        return (b * 256 + t) * 64 + f;
    }
}

// ---------------------------------------------------------------------------
// Q fragments: bf16-split, built from g_QK (stride 512).
// ---------------------------------------------------------------------------
template <int STAGE>
__device__ __forceinline__ void load_q_frags(
    const float* __restrict__ qk, int g, int h, int p0,
    int tr, uint32_t qh[2][4], uint32_t ql[2][4])
{
    const float SCALE = 0.17677669529663687f;
    #pragma unroll
    for (int kt = 0; kt < 2; kt++)
        #pragma unroll
        for (int hv = 0; hv < 2; hv++) {
            int j = kt * 8 + tr + 4 * hv;
            #pragma unroll
            for (int rr = 0; rr < 2; rr++) {
                int p = p0 + rr * 8;
                int tok = tok_of<STAGE>(g, p);
                float2 q = *(const float2*)(qk + (size_t)tok * 512 + h * 32 + 2 * j);
                float2 cs = g_rope[p * 16 + j];
                float q0 = (q.x * cs.x - q.y * cs.y) * SCALE;
                float q1 = (q.y * cs.x + q.x * cs.y) * SCALE;
                float r0, r1;
                qh[kt][hv * 2 + rr] = pack_bf16_hi(q0, q1, r0, r1);
                ql[kt][hv * 2 + rr] = pack_bf16(r0, r1);
            }
        }
}

// X writer: fp16 pair
__device__ __forceinline__ void write_x_pair(size_t o, float v0, float v1) {
    *(uint32_t*)&g_Xh[o] = pack_half2(v0, v1);
}

// raw half pair fetch
template <int STAGE>
__device__ __forceinline__ uint32_t fetch_v_pair(const __half* __restrict__ vh,
                                                 int g, int h, int p_even, int vd) {
    uint16_t lo = *(const uint16_t*)(vh + (size_t)tok_of<STAGE>(g, p_even) * 256 + h * 32 + vd);
    uint16_t hi = *(const uint16_t*)(vh + (size_t)tok_of<STAGE>(g, p_even + 1) * 256 + h * 32 + vd);
    return (uint32_t)lo | ((uint32_t)hi << 16);
}

// ---------------------------------------------------------------------------
// Stage-1 attention: S=256, one block per (g,h); each warp handles TWO
// 16-row q-tiles (rows w*16.. and 128+w*16..) -> KV streamed ONCE.
// ---------------------------------------------------------------------------
__global__ __launch_bounds__(256, 2) void attn1_kernel(
    const float* __restrict__ qk, const __half* __restrict__ vh)
{
    constexpr int BUF = 1920;
    __shared__ uint32_t smu[2 * BUF];
    const uint32_t smemb = smem_u32(smu);

    const int g = blockIdx.x;
    const int h = blockIdx.y;
    const int tid = threadIdx.x;
    const int w = tid >> 5, lane = tid & 31, tq = lane >> 2, tr = lane & 3;
    const int m_base = w * 16;
    const uint32_t frag20 = (uint32_t)((lane & 7) * 20 + ((lane >> 3) & 1) * 4) * 4;

    uint32_t qhA[2][4], qlA[2][4], qhB[2][4], qlB[2][4];
    load_q_frags<1>(qk, g, h, m_base + tq, tr, qhA, qlA);
    load_q_frags<1>(qk, g, h, 128 + m_base + tq, tr, qhB, qlB);

    const int kj = tid & 15;
    const int kk0 = tid >> 4;
    const int vd = tid & 31;
    const int vp0 = tid >> 5;
    float2 kx[2];
    uint32_t vxu[2];

    auto load_chunk = [&](int c) {
        int kb = c * 32;
        #pragma unroll
        for (int r = 0; r < 2; r++) {
            int tok = tok_of<1>(g, kb + r * 16 + kk0);
            kx[r] = *(const float2*)(qk + (size_t)tok * 512 + 256 + h * 32 + 2 * kj);
        }
        #pragma unroll
        for (int r = 0; r < 2; r++) {
            int kp = r * 8 + vp0;
            vxu[r] = fetch_v_pair<1>(vh, g, h, kb + 2 * kp, vd);
        }
    };
    auto store_chunk = [&](int c, int base) {
        int kb = c * 32;
        #pragma unroll
        for (int r = 0; r < 2; r++) {
            int k = r * 16 + kk0;
            float2 cs = g_rope[(kb + k) * 16 + kj];
            float k0 = kx[r].x * cs.x - kx[r].y * cs.y;
            float k1 = kx[r].y * cs.x + kx[r].x * cs.y;
            float r0, r1;
            smu[base + k * 20 + kj] = pack_bf16_hi(k0, k1, r0, r1);
            smu[base + 640 + k * 20 + kj] = pack_bf16(r0, r1);
        }
        #pragma unroll
        for (int r = 0; r < 2; r++) {
            int kp = r * 8 + vp0;
            smu[base + 1280 + vd * 20 + kp] = vxu[r];
        }
    };

    load_chunk(0);
    store_chunk(0, 0);
    __syncthreads();

    float coA[4][4], coB[4][4];
    #pragma unroll
    for (int i = 0; i < 4; i++)
        #pragma unroll
        for (int j = 0; j < 4; j++) { coA[i][j] = 0.0f; coB[i][j] = 0.0f; }
    float mrA0 = -1e30f, mrA1 = -1e30f, lrA0 = 0.0f, lrA1 = 0.0f;
    float mrB0 = -1e30f, mrB1 = -1e30f, lrB0 = 0.0f, lrB1 = 0.0f;

    for (int c = 0; c < 8; c++) {
        const uint32_t KhiA = smemb + (c & 1) * BUF * 4;
        const uint32_t KloA = KhiA + 2560;
        const uint32_t VtA  = KhiA + 5120;

        if (c < 7) load_chunk(c + 1);

        // ---- process one q-tile against the resident chunk ----
        auto tile = [&](uint32_t qh[2][4], uint32_t ql[2][4], float co[4][4],
                        float& mrun0, float& mrun1, float& lrun0, float& lrun1) {
            float sc[4][4];
            #pragma unroll
            for (int nt = 0; nt < 4; nt++) {
                float c0[4] = {0, 0, 0, 0}, c1[4] = {0, 0, 0, 0}, c2[4] = {0, 0, 0, 0};
                #pragma unroll
                for (int kt = 0; kt < 2; kt++) {
                    uint32_t bh[2], bl[2];
                    ldsm_x2(bh[0], bh[1], KhiA + nt * 640 + kt * 32 + frag20);
                    ldsm_x2(bl[0], bl[1], KloA + nt * 640 + kt * 32 + frag20);
                    mma_bf16(c0, qh[kt], bh);
                    mma_bf16(c1, ql[kt], bh);
                    mma_bf16(c2, qh[kt], bl);
                }
                #pragma unroll
                for (int r = 0; r < 4; r++) sc[nt][r] = c0[r] + c1[r] + c2[r];
            }

            float mx0 = -1e30f, mx1 = -1e30f;
            #pragma unroll
            for (int nt = 0; nt < 4; nt++) {
                mx0 = fmaxf(mx0, fmaxf(sc[nt][0], sc[nt][1]));
                mx1 = fmaxf(mx1, fmaxf(sc[nt][2], sc[nt][3]));
            }
            mx0 = fmaxf(mx0, __shfl_xor_sync(0xFFFFFFFFu, mx0, 1));
            mx0 = fmaxf(mx0, __shfl_xor_sync(0xFFFFFFFFu, mx0, 2));
            mx1 = fmaxf(mx1, __shfl_xor_sync(0xFFFFFFFFu, mx1, 1));
            mx1 = fmaxf(mx1, __shfl_xor_sync(0xFFFFFFFFu, mx1, 2));
            float mn0 = fmaxf(mrun0, mx0), mn1 = fmaxf(mrun1, mx1);
            float esc0 = __expf(mrun0 - mn0), esc1 = __expf(mrun1 - mn1);
            float s0 = 0.0f, s1 = 0.0f;
            #pragma unroll
            for (int nt = 0; nt < 4; nt++) {
                sc[nt][0] = __expf(sc[nt][0] - mn0);
                sc[nt][1] = __expf(sc[nt][1] - mn0);
                sc[nt][2] = __expf(sc[nt][2] - mn1);
                sc[nt][3] = __expf(sc[nt][3] - mn1);
                s0 += sc[nt][0] + sc[nt][1];
                s1 += sc[nt][2] + sc[nt][3];
            }
            s0 += __shfl_xor_sync(0xFFFFFFFFu, s0, 1);
            s0 += __shfl_xor_sync(0xFFFFFFFFu, s0, 2);
            s1 += __shfl_xor_sync(0xFFFFFFFFu, s1, 1);
            s1 += __shfl_xor_sync(0xFFFFFFFFu, s1, 2);
            lrun0 = lrun0 * esc0 + s0;
            lrun1 = lrun1 * esc1 + s1;
            mrun0 = mn0; mrun1 = mn1;
            #pragma unroll
            for (int nt2 = 0; nt2 < 4; nt2++) {
                co[nt2][0] *= esc0; co[nt2][1] *= esc0;
                co[nt2][2] *= esc1; co[nt2][3] *= esc1;
            }

            #pragma unroll
            for (int kt2 = 0; kt2 < 2; kt2++) {
                uint32_t a[4];
                a[0] = pack_half2(sc[2 * kt2][0], sc[2 * kt2][1]);
                a[1] = pack_half2(sc[2 * kt2][2], sc[2 * kt2][3]);
                a[2] = pack_half2(sc[2 * kt2 + 1][0], sc[2 * kt2 + 1][1]);
                a[3] = pack_half2(sc[2 * kt2 + 1][2], sc[2 * kt2 + 1][3]);
                #pragma unroll
                for (int nt2 = 0; nt2 < 4; nt2++) {
                    uint32_t b[2];
                    ldsm_x2(b[0], b[1], VtA + nt2 * 640 + kt2 * 32 + frag20);
                    mma_f16(co[nt2], a, b);
                }
            }
        };

        tile(qhA, qlA, coA, mrA0, mrA1, lrA0, lrA1);
        tile(qhB, qlB, coB, mrB0, mrB1, lrB0, lrB1);

        if (c < 7) store_chunk(c + 1, ((c + 1) & 1) * BUF);
        __syncthreads();
    }

    // epilogue: both tiles
    {
        float inv0 = 1.0f / lrA0, inv1 = 1.0f / lrA1;
        int p0r = m_base + tq;
        size_t o0 = (size_t)tok_of<1>(g, p0r) * 256 + h * 32;
        size_t o1 = (size_t)tok_of<1>(g, p0r + 8) * 256 + h * 32;
        #pragma unroll
        for (int nt2 = 0; nt2 < 4; nt2++) {
            int cc = nt2 * 8 + 2 * tr;
            write_x_pair(o0 + cc, coA[nt2][0] * inv0, coA[nt2][1] * inv0);
            write_x_pair(o1 + cc, coA[nt2][2] * inv1, coA[nt2][3] * inv1);
        }
    }
    {
        float inv0 = 1.0f / lrB0, inv1 = 1.0f / lrB1;
        int p0r = 128 + m_base + tq;
        size_t o0 = (size_t)tok_of<1>(g, p0r) * 256 + h * 32;
        size_t o1 = (size_t)tok_of<1>(g, p0r + 8) * 256 + h * 32;
        #pragma unroll
        for (int nt2 = 0; nt2 < 4; nt2++) {
            int cc = nt2 * 8 + 2 * tr;
            write_x_pair(o0 + cc, coB[nt2][0] * inv0, coB[nt2][1] * inv0);
            write_x_pair(o1 + cc, coB[nt2][2] * inv1, coB[nt2][3] * inv1);
        }
    }
}

// ---------------------------------------------------------------------------
// Stage-2/3 attention: S=64, 2 heads per block (unchanged from round 16).
// ---------------------------------------------------------------------------
template <int STAGE>
__global__ __launch_bounds__(256, 3) void attn64_kernel(
    const float* __restrict__ qk, const __half* __restrict__ vh)
{
    constexpr int HS = 3712;
    extern __shared__ uint32_t smu2[];
    const uint32_t smemb = smem_u32(smu2);

    const int g = blockIdx.x;
    const int tid = threadIdx.x;
    const int w = tid >> 5, lane = tid & 31, tq = lane >> 2, tr = lane & 3;
    const int hh = w >> 2;
    const int h = blockIdx.y * 2 + hh;
    const int m_base = (w & 3) * 16;
    const uint32_t frag20 = (uint32_t)((lane & 7) * 20 + ((lane >> 3) & 1) * 4) * 4;
    const uint32_t frag36 = (uint32_t)((lane & 7) * 36 + ((lane >> 3) & 1) * 4) * 4;

    for (int idx = tid; idx < 2048; idx += 256) {
        int hl = idx >> 10, rem = idx & 1023;
        int k = rem >> 4, j = rem & 15;
        int tok = tok_of<STAGE>(g, k);
        const float* bp = qk + (size_t)tok * 512 + 256 + (blockIdx.y * 2 + hl) * 32;
        float x0 = bp[2 * j], x1 = bp[2 * j + 1];
        float2 cs = g_rope[k * 16 + j];
        float k0 = x0 * cs.x - x1 * cs.y;
        float k1 = x1 * cs.x + x0 * cs.y;
        float r0, r1;
        int base = hl * HS;
        smu2[base + k * 20 + j] = pack_bf16_hi(k0, k1, r0, r1);
        smu2[base + 1280 + k * 20 + j] = pack_bf16(r0, r1);
    }
    for (int idx = tid; idx < 2048; idx += 256) {
        int hl = idx >> 10, rem = idx & 1023;
        int kp = rem >> 5, d = rem & 31;
        smu2[hl * HS + 2560 + d * 36 + kp] =
            fetch_v_pair<STAGE>(vh, g, blockIdx.y * 2 + hl, 2 * kp, d);
    }

    uint32_t qh[2][4], ql[2][4];
    load_q_frags<STAGE>(qk, g, h, m_base + tq, tr, qh, ql);
    __syncthreads();

    const uint32_t KhiA = smemb + hh * HS * 4;
    const uint32_t KloA = KhiA + 5120;
    const uint32_t VtA  = KhiA + 10240;

    float co[4][4];
    #pragma unroll
    for (int i = 0; i < 4; i++)
        #pragma unroll
        for (int j = 0; j < 4; j++) co[i][j] = 0.0f;
    float mrun0 = -1e30f, mrun1 = -1e30f, lrun0 = 0.0f, lrun1 = 0.0f;

    #pragma unroll
    for (int j0 = 0; j0 < 64; j0 += 32) {
        float sc[4][4];
        #pragma unroll
        for (int nt = 0; nt < 4; nt++) {
            float c0[4] = {0, 0, 0, 0}, c1[4] = {0, 0, 0, 0}, c2[4] = {0, 0, 0, 0};
            #pragma unroll
            for (int kt = 0; kt < 2; kt++) {
                uint32_t bh[2], bl[2];
                ldsm_x2(bh[0], bh[1], KhiA + j0 * 80 + nt * 640 + kt * 32 + frag20);
                ldsm_x2(bl[0], bl[1], KloA + j0 * 80 + nt * 640 + kt * 32 + frag20);
                mma_bf16(c0, qh[kt], bh);
                mma_bf16(c1, ql[kt], bh);
                mma_bf16(c2, qh[kt], bl);
            }
            #pragma unroll
            for (int r = 0; r < 4; r++) sc[nt][r] = c0[r] + c1[r] + c2[r];
        }

        float mx0 = -1e30f, mx1 = -1e30f;
        #pragma unroll
        for (int nt = 0; nt < 4; nt++) {
            mx0 = fmaxf(mx0, fmaxf(sc[nt][0], sc[nt][1]));
            mx1 = fmaxf(mx1, fmaxf(sc[nt][2], sc[nt][3]));
        }
        mx0 = fmaxf(mx0, __shfl_xor_sync(0xFFFFFFFFu, mx0, 1));
        mx0 = fmaxf(mx0, __shfl_xor_sync(0xFFFFFFFFu, mx0, 2));
        mx1 = fmaxf(mx1, __shfl_xor_sync(0xFFFFFFFFu, mx1, 1));
        mx1 = fmaxf(mx1, __shfl_xor_sync(0xFFFFFFFFu, mx1, 2));
        float mn0 = fmaxf(mrun0, mx0), mn1 = fmaxf(mrun1, mx1);
        float esc0 = __expf(mrun0 - mn0), esc1 = __expf(mrun1 - mn1);
        float s0 = 0.0f, s1 = 0.0f;
        #pragma unroll
        for (int nt = 0; nt < 4; nt++) {
            sc[nt][0] = __expf(sc[nt][0] - mn0);
            sc[nt][1] = __expf(sc[nt][1] - mn0);
            sc[nt][2] = __expf(sc[nt][2] - mn1);
            sc[nt][3] = __expf(sc[nt][3] - mn1);
            s0 += sc[nt][0] + sc[nt][1];
            s1 += sc[nt][2] + sc[nt][3];
        }
        s0 += __shfl_xor_sync(0xFFFFFFFFu, s0, 1);
        s0 += __shfl_xor_sync(0xFFFFFFFFu, s0, 2);
        s1 += __shfl_xor_sync(0xFFFFFFFFu, s1, 1);
        s1 += __shfl_xor_sync(0xFFFFFFFFu, s1, 2);
        lrun0 = lrun0 * esc0 + s0;
        lrun1 = lrun1 * esc1 + s1;
        mrun0 = mn0; mrun1 = mn1;
        #pragma unroll
        for (int nt2 = 0; nt2 < 4; nt2++) {
            co[nt2][0] *= esc0; co[nt2][1] *= esc0;
            co[nt2][2] *= esc1; co[nt2][3] *= esc1;
        }

        #pragma unroll
        for (int kt2 = 0; kt2 < 2; kt2++) {
            uint32_t a[4];
            a[0] = pack_half2(sc[2 * kt2][0], sc[2 * kt2][1]);
            a[1] = pack_half2(sc[2 * kt2][2], sc[2 * kt2][3]);
            a[2] = pack_half2(sc[2 * kt2 + 1][0], sc[2 * kt2 + 1][1]);
            a[3] = pack_half2(sc[2 * kt2 + 1][2], sc[2 * kt2 + 1][3]);
            #pragma unroll
            for (int nt2 = 0; nt2 < 4; nt2++) {
                uint32_t b[2];
                ldsm_x2(b[0], b[1],
                        VtA + nt2 * 1152 + (j0 >> 1) * 4 + kt2 * 32 + frag36);
                mma_f16(co[nt2], a, b);
            }
        }
    }

    float inv0 = 1.0f / lrun0, inv1 = 1.0f / lrun1;
    int p0r = m_base + tq;
    size_t o0 = (size_t)tok_of<STAGE>(g, p0r) * 256 + h * 32;
    size_t o1 = (size_t)tok_of<STAGE>(g, p0r + 8) * 256 + h * 32;
    #pragma unroll
    for (int nt2 = 0; nt2 < 4; nt2++) {
        int cc = nt2 * 8 + 2 * tr;
        write_x_pair(o0 + cc, co[nt2][0] * inv0, co[nt2][1] * inv0);
        write_x_pair(o1 + cc, co[nt2][2] * inv1, co[nt2][3] * inv1);
    }
}

// ---------------------------------------------------------------------------
extern "C" void kernel_launch(void* const* d_in, const int* in_sizes, int n_in,
                              void* d_out, int out_size) {
    const float* x  = (const float*)d_in[0];
    const float* W1 = (const float*)d_in[1];
    const float* W2 = (const float*)d_in[2];
    const float* W3 = (const float*)d_in[3];
    const float* Wp = (const float*)d_in[4];
    float* out = (float*)d_out;

    __half* Xh; cudaGetSymbolAddress((void**)&Xh, g_Xh);
    __half* Wr; cudaGetSymbolAddress((void**)&Wr, g_W);
    float* QKp; cudaGetSymbolAddress((void**)&QKp, g_QK);
    __half* Vhp; cudaGetSymbolAddress((void**)&Vhp, g_Vh);

    const int SMEMG = 4 * 20480;               // 81920
    const int SMEMO = 81920;
    const int SMEM64 = 2 * 3712 * 4;           // 29696

    cudaFuncSetAttribute(fp16_gemm_qkv_kernel,
                         cudaFuncAttributeMaxDynamicSharedMemorySize, SMEMG);
    cudaFuncSetAttribute(fp16_gemm_out_kernel,
                         cudaFuncAttributeMaxDynamicSharedMemorySize, SMEMO);
    cudaFuncSetAttribute(attn64_kernel<2>,
                         cudaFuncAttributeMaxDynamicSharedMemorySize, SMEM64);
    cudaFuncSetAttribute(attn64_kernel<3>,
                         cudaFuncAttributeMaxDynamicSharedMemorySize, SMEM64);

    rope_table_kernel<<<16, 256>>>();
    round_w_kernel<<<2560, 256>>>(W1, W2, W3, Wp);
    permute_in_kernel<<<dim3(512, 8, 4), dim3(32, 8)>>>(x);

    // Stage 1: time-axis attention (S=256), one block per (g,h)
    fp16_gemm_qkv_kernel<<<dim3(6, 512), 256, SMEMG>>>(Xh, Wr, QKp, Vhp);
    attn1_kernel<<<dim3(256, 8), 256>>>(QKp, Vhp);

    // Stage 2: freq-axis attention (S=64)
    fp16_gemm_qkv_kernel<<<dim3(6, 512), 256, SMEMG>>>(Xh, Wr + 196608, QKp, Vhp);
    attn64_kernel<2><<<dim3(1024, 4), 256, SMEM64>>>(QKp, Vhp);

    // Stage 3: windowed attention (S=64)
    fp16_gemm_qkv_kernel<<<dim3(6, 512), 256, SMEMG>>>(Xh, Wr + 393216, QKp, Vhp);
    attn64_kernel<3><<<dim3(1024, 4), 256, SMEM64>>>(QKp, Vhp);

    // Projection fused with output permute
    fp16_gemm_out_kernel<<<dim3(2, 512), 256, SMEMO>>>(Xh, Wr + 589824, out);
}